// round 8
// baseline (speedup 1.0000x reference)
#include <cuda_runtime.h>
#include <cuda_bf16.h>
#include <math.h>
#include <stdint.h>

// ---------------------------------------------------------------------------
// Problem dims (fixed)
// ---------------------------------------------------------------------------
#define BATCH   32
#define SEQ     512
#define DMODEL  512
#define NHEADS  8
#define HDIM    64
#define DFF     2048
#define MTOK    (BATCH * SEQ)
#define LN_EPS  1e-12f
#define QS      1536                      // qkv combined row stride

// ---------------------------------------------------------------------------
// Scratch (device globals)
// ---------------------------------------------------------------------------
__device__ float g_t0[MTOK * DMODEL];
__device__ float g_attnln[MTOK * DMODEL];
__device__ float g_bqkv[QS];

__device__ __nv_bfloat16 g_xhi[MTOK * DMODEL];
__device__ __nv_bfloat16 g_xlo[MTOK * DMODEL];
__device__ __nv_bfloat16 g_qkvhi[MTOK * QS];
__device__ __nv_bfloat16 g_qkvlo[MTOK * QS];
__device__ __nv_bfloat16 g_chi[MTOK * DMODEL];
__device__ __nv_bfloat16 g_clo[MTOK * DMODEL];
__device__ __nv_bfloat16 g_ahi[MTOK * DMODEL];
__device__ __nv_bfloat16 g_alo[MTOK * DMODEL];
__device__ __nv_bfloat16 g_fhi[MTOK * DFF];
__device__ __nv_bfloat16 g_flo[MTOK * DFF];

__device__ __nv_bfloat16 g_wqkvhi[QS * DMODEL];
__device__ __nv_bfloat16 g_wqkvlo[QS * DMODEL];
__device__ __nv_bfloat16 g_wohi[DMODEL * DMODEL];
__device__ __nv_bfloat16 g_wolo[DMODEL * DMODEL];
__device__ __nv_bfloat16 g_w1hi[DFF * DMODEL];
__device__ __nv_bfloat16 g_w1lo[DFF * DMODEL];
__device__ __nv_bfloat16 g_w2hi[DMODEL * DFF];
__device__ __nv_bfloat16 g_w2lo[DMODEL * DFF];

// ---------------------------------------------------------------------------
// helpers
// ---------------------------------------------------------------------------
__device__ __forceinline__ void mma16816(float* c, const uint32_t* a, const uint32_t* b)
{
    asm volatile(
        "mma.sync.aligned.m16n8k16.row.col.f32.bf16.bf16.f32 "
        "{%0,%1,%2,%3}, {%4,%5,%6,%7}, {%8,%9}, {%0,%1,%2,%3};"
        : "+f"(c[0]), "+f"(c[1]), "+f"(c[2]), "+f"(c[3])
        : "r"(a[0]), "r"(a[1]), "r"(a[2]), "r"(a[3]), "r"(b[0]), "r"(b[1]));
}

__device__ __forceinline__ uint32_t smem_u32(const void* p) {
    uint32_t a;
    asm("{ .reg .u64 t; cvta.to.shared.u64 t, %1; cvt.u32.u64 %0, t; }"
        : "=r"(a) : "l"(p));
    return a;
}

__device__ __forceinline__ void cp16(uint32_t dst, const void* src) {
    asm volatile("cp.async.cg.shared.global [%0], [%1], 16;"
                 :: "r"(dst), "l"(src));
}
__device__ __forceinline__ void cp_commit() {
    asm volatile("cp.async.commit_group;" ::: "memory");
}
template <int N>
__device__ __forceinline__ void cp_wait() {
    asm volatile("cp.async.wait_group %0;" :: "n"(N) : "memory");
}

__device__ __forceinline__ float fast_exp(float x) {
    float y = fmaxf(x * 1.4426950408889634f, -120.0f);
    float n = rintf(y);
    float f = y - n;
    float p = 1.3333558e-3f;
    p = fmaf(p, f, 9.6181291e-3f);
    p = fmaf(p, f, 5.5504109e-2f);
    p = fmaf(p, f, 2.4022651e-1f);
    p = fmaf(p, f, 6.9314718e-1f);
    p = fmaf(p, f, 1.0f);
    return p * __int_as_float(((int)n + 127) << 23);
}

__device__ __forceinline__ void split1(float v, unsigned short& h, unsigned short& l) {
    __nv_bfloat16 hb = __float2bfloat16_rn(v);
    float r = v - __bfloat162float(hb);
    __nv_bfloat16 lb = __float2bfloat16_rn(r);
    h = __bfloat16_as_ushort(hb);
    l = __bfloat16_as_ushort(lb);
}
__device__ __forceinline__ uint32_t pack2(unsigned short a, unsigned short b) {
    return (uint32_t)a | ((uint32_t)b << 16);
}

// ---------------------------------------------------------------------------
// prep kernels
// ---------------------------------------------------------------------------
__global__ void split_kernel(const float* __restrict__ X,
                             __nv_bfloat16* __restrict__ hi,
                             __nv_bfloat16* __restrict__ lo, int n4)
{
    int i = blockIdx.x * blockDim.x + threadIdx.x;
    if (i >= n4) return;
    float4 x = ((const float4*)X)[i];
    unsigned short h0, h1, h2, h3, l0, l1, l2, l3;
    split1(x.x, h0, l0); split1(x.y, h1, l1);
    split1(x.z, h2, l2); split1(x.w, h3, l3);
    uint2 hv, lv;
    hv.x = pack2(h0, h1); hv.y = pack2(h2, h3);
    lv.x = pack2(l0, l1); lv.y = pack2(l2, l3);
    ((uint2*)hi)[i] = hv;
    ((uint2*)lo)[i] = lv;
}

// Transpose + split: W[K][N] fp32 -> hi/lo [noff+N][K] bf16
__global__ void tsplit_kernel(const float* __restrict__ W,
                              __nv_bfloat16* __restrict__ hi,
                              __nv_bfloat16* __restrict__ lo,
                              int K, int N, int noff)
{
    __shared__ float tile[32][33];
    const int n0 = blockIdx.x * 32, k0 = blockIdx.y * 32;
    const int tx = threadIdx.x, ty = threadIdx.y;
#pragma unroll
    for (int i = 0; i < 32; i += 8)
        tile[ty + i][tx] = W[(size_t)(k0 + ty + i) * N + n0 + tx];
    __syncthreads();
#pragma unroll
    for (int i = 0; i < 32; i += 8) {
        float v = tile[tx][ty + i];
        unsigned short h, l;
        split1(v, h, l);
        size_t o = (size_t)(noff + n0 + ty + i) * K + k0 + tx;
        hi[o] = __ushort_as_bfloat16(h);
        lo[o] = __ushort_as_bfloat16(l);
    }
}

__global__ void concat_bias_kernel(const float* __restrict__ a,
                                   const float* __restrict__ b,
                                   const float* __restrict__ c,
                                   float* __restrict__ o)
{
    int i = blockIdx.x * blockDim.x + threadIdx.x;
    if (i >= QS) return;
    o[i] = (i < 512) ? a[i] : (i < 1024) ? b[i - 512] : c[i - 1024];
}

// ---------------------------------------------------------------------------
// Pipelined tensor-core split-GEMM.
// CTA tile 128x128, k-tile 32, 2-stage cp.async (80 KB smem, 2 CTA/SM).
// 8 warps: 4 m-warps x 2 n-warps; warp tile 32x64; acc 2x8x4.
// Multi-output epilogue: Cf fp32 and/or Chi/Clo bf16 split, optional GELU.
// ---------------------------------------------------------------------------
#define SA2 40
#define ST2 (128 * SA2)                   // 5120 elems per array
#define STAGE2 (4 * ST2)                  // Ahi Alo Bhi Blo = 20480 elems
#define GM_SMEM_BYTES (2 * STAGE2 * 2)    // 81920 bytes

__global__ __launch_bounds__(256)
void gemm_mma(const __nv_bfloat16* __restrict__ Ahi,
              const __nv_bfloat16* __restrict__ Alo,
              const __nv_bfloat16* __restrict__ Bhi,
              const __nv_bfloat16* __restrict__ Blo,
              const float* __restrict__ bias,
              float* __restrict__ Cf,
              __nv_bfloat16* __restrict__ Chi,
              __nv_bfloat16* __restrict__ Clo,
              int M, int N, int K, int do_gelu)
{
    extern __shared__ __nv_bfloat16 smb[];
    const uint32_t sm_base = smem_u32(smb);

    const int tid = threadIdx.x;
    const int wid = tid >> 5;
    const int lid = tid & 31;
    const int gID = lid >> 2;
    const int t4  = lid & 3;

    const int row0 = blockIdx.y * 128;
    const int col0 = blockIdx.x * 128;
    const int m_off = (wid & 3) * 32;
    const int n_off = (wid >> 2) * 64;

    // loader: A and B both 128 rows x 32 k; 512 chunks of 8 bf16 each; 2/thread
    const int lr = tid >> 1;              // row for this thread's 2 chunks? no:
    // use e-based mapping (same as prior proven loader)
    auto load_stage = [&](int buf, int t) {
        const int kb = t << 5;
        uint32_t base = sm_base + (uint32_t)buf * (STAGE2 * 2);
#pragma unroll
        for (int i = 0; i < 2; i++) {
            int e = tid + i * 256;
            int r = e >> 2, g = e & 3;
            uint32_t ds = (uint32_t)(r * SA2 + g * 8) * 2;
            size_t srcA = (size_t)(row0 + r) * K + kb + g * 8;
            size_t srcB = (size_t)(col0 + r) * K + kb + g * 8;
            cp16(base + ds, Ahi + srcA);
            cp16(base + ST2 * 2 + ds, Alo + srcA);
            cp16(base + 2 * ST2 * 2 + ds, Bhi + srcB);
            cp16(base + 3 * ST2 * 2 + ds, Blo + srcB);
        }
        cp_commit();
    };
    (void)lr;

    float acc[2][8][4];
#pragma unroll
    for (int mi = 0; mi < 2; mi++)
#pragma unroll
        for (int ni = 0; ni < 8; ni++)
#pragma unroll
            for (int j = 0; j < 4; j++) acc[mi][ni][j] = 0.f;

    const int nT = K >> 5;
    load_stage(0, 0);

    for (int t = 0; t < nT; t++) {
        const int buf = t & 1;
        if (t + 1 < nT) {
            load_stage(1 - buf, t + 1);
            cp_wait<1>();
        } else {
            cp_wait<0>();
        }
        __syncthreads();

        const __nv_bfloat16* As_hi = smb + buf * STAGE2;
        const __nv_bfloat16* As_lo = As_hi + ST2;
        const __nv_bfloat16* Bs_hi = As_hi + 2 * ST2;
        const __nv_bfloat16* Bs_lo = As_hi + 3 * ST2;

#pragma unroll
        for (int kk = 0; kk < 32; kk += 16) {
            uint32_t ahi[2][4], alo[2][4];
#pragma unroll
            for (int mi = 0; mi < 2; mi++) {
                int r = m_off + mi * 16 + gID;
                int base0 = r * SA2 + kk + t4 * 2;
                int base1 = (r + 8) * SA2 + kk + t4 * 2;
                ahi[mi][0] = *(const uint32_t*)&As_hi[base0];
                ahi[mi][1] = *(const uint32_t*)&As_hi[base1];
                ahi[mi][2] = *(const uint32_t*)&As_hi[base0 + 8];
                ahi[mi][3] = *(const uint32_t*)&As_hi[base1 + 8];
                alo[mi][0] = *(const uint32_t*)&As_lo[base0];
                alo[mi][1] = *(const uint32_t*)&As_lo[base1];
                alo[mi][2] = *(const uint32_t*)&As_lo[base0 + 8];
                alo[mi][3] = *(const uint32_t*)&As_lo[base1 + 8];
            }
#pragma unroll
            for (int ni = 0; ni < 8; ni++) {
                int n = n_off + ni * 8 + gID;
                int base = n * SA2 + kk + t4 * 2;
                uint32_t bh[2], bl[2];
                bh[0] = *(const uint32_t*)&Bs_hi[base];
                bh[1] = *(const uint32_t*)&Bs_hi[base + 8];
                bl[0] = *(const uint32_t*)&Bs_lo[base];
                bl[1] = *(const uint32_t*)&Bs_lo[base + 8];
#pragma unroll
                for (int mi = 0; mi < 2; mi++) {
                    mma16816(acc[mi][ni], ahi[mi], bh);
                    mma16816(acc[mi][ni], alo[mi], bh);
                    mma16816(acc[mi][ni], ahi[mi], bl);
                }
            }
        }
        __syncthreads();
    }

    // ---- epilogue ----
#pragma unroll
    for (int mi = 0; mi < 2; mi++) {
#pragma unroll
        for (int ni = 0; ni < 8; ni++) {
            int col = col0 + n_off + ni * 8 + t4 * 2;
            float b0 = bias[col], b1 = bias[col + 1];
#pragma unroll
            for (int half = 0; half < 2; half++) {
                int row = row0 + m_off + mi * 16 + gID + half * 8;
                float v0 = acc[mi][ni][half * 2 + 0] + b0;
                float v1 = acc[mi][ni][half * 2 + 1] + b1;
                if (do_gelu) {
                    v0 = 0.5f * v0 * (1.0f + erff(v0 * 0.70710678118654752f));
                    v1 = 0.5f * v1 * (1.0f + erff(v1 * 0.70710678118654752f));
                }
                size_t o = (size_t)row * N + col;
                if (Cf) {
                    float2 fo; fo.x = v0; fo.y = v1;
                    *(float2*)(Cf + o) = fo;
                }
                if (Chi) {
                    unsigned short h0, h1, l0, l1;
                    split1(v0, h0, l0);
                    split1(v1, h1, l1);
                    *(uint32_t*)(Chi + o) = pack2(h0, h1);
                    *(uint32_t*)(Clo + o) = pack2(l0, l1);
                }
            }
        }
    }
}

// ---------------------------------------------------------------------------
// Tensor-core attention. q/k/v pre-split bf16 at row stride QS (combined buf);
// ctx written pre-split at stride DMODEL. Phase-1 K double-buffered cp.async.
// ---------------------------------------------------------------------------
#define AT_SA   72
#define AT_QHI  0
#define AT_QLO  9216
#define AT_K0   18432
#define AT_PHI  55296
#define AT_PLO  64512
#define AT_SS   73728
#define AT_INV  (AT_SS + 64 * 512 * 4)
#define AT_SMEM (AT_INV + 256)

__global__ __launch_bounds__(256)
void attn_mma(const __nv_bfloat16* __restrict__ Qhi_g,
              const __nv_bfloat16* __restrict__ Qlo_g,
              const __nv_bfloat16* __restrict__ Khi_g,
              const __nv_bfloat16* __restrict__ Klo_g,
              const __nv_bfloat16* __restrict__ Vhi_g,
              const __nv_bfloat16* __restrict__ Vlo_g,
              const float* __restrict__ mask,
              __nv_bfloat16* __restrict__ Chi_g,
              __nv_bfloat16* __restrict__ Clo_g)
{
    extern __shared__ char smc[];
    const uint32_t sm_base = smem_u32(smc);
    __nv_bfloat16* Qhi = (__nv_bfloat16*)(smc + AT_QHI);
    __nv_bfloat16* Qlo = (__nv_bfloat16*)(smc + AT_QLO);
    __nv_bfloat16* Phi = (__nv_bfloat16*)(smc + AT_PHI);
    __nv_bfloat16* Plo = (__nv_bfloat16*)(smc + AT_PLO);
    float* Ss   = (float*)(smc + AT_SS);
    float* invs = (float*)(smc + AT_INV);

    const int tid = threadIdx.x;
    const int wid = tid >> 5, lid = tid & 31;
    const int gID = lid >> 2, t4 = lid & 3;
    const int wm = wid & 3, wn = wid >> 2;
    const int q0 = blockIdx.x * 64;
    const int h = blockIdx.y, b = blockIdx.z;
    const size_t hbq = ((size_t)b * SEQ) * QS + (size_t)h * HDIM;      // qkv base
    const size_t hbo = ((size_t)b * SEQ) * DMODEL + (size_t)h * HDIM;  // ctx base
    const float* mbase = mask + (size_t)b * SEQ * SEQ;

    auto load_k = [&](int bb, int kc) {
        const int k0 = kc * 64;
        uint32_t kh = sm_base + AT_K0 + (uint32_t)bb * 18432;
        uint32_t kl = kh + 9216;
#pragma unroll
        for (int i = 0; i < 2; i++) {
            int e = tid + i * 256;
            int r = e >> 3, g = e & 7;
            size_t src = hbq + (size_t)(k0 + r) * QS + g * 8;
            uint32_t ds = (uint32_t)(r * AT_SA + g * 8) * 2;
            cp16(kh + ds, Khi_g + src);
            cp16(kl + ds, Klo_g + src);
        }
        cp_commit();
    };

    load_k(0, 0);

    // load Q tile
#pragma unroll
    for (int i = 0; i < 2; i++) {
        int e = tid + i * 256;
        int r = e >> 3, g = e & 7;
        size_t src = hbq + (size_t)(q0 + r) * QS + g * 8;
        int ds = r * AT_SA + g * 8;
        *(uint4*)(Qhi + ds) = *(const uint4*)(Qhi_g + src);
        *(uint4*)(Qlo + ds) = *(const uint4*)(Qlo_g + src);
    }

    float pv[4][4];
#pragma unroll
    for (int ni = 0; ni < 4; ni++)
#pragma unroll
        for (int j = 0; j < 4; j++) pv[ni][j] = 0.f;

    // ---- phase 1: scores ----
    for (int kc = 0; kc < 8; kc++) {
        const int k0 = kc * 64;
        if (kc + 1 < 8) {
            load_k((kc + 1) & 1, kc + 1);
            cp_wait<1>();
        } else {
            cp_wait<0>();
        }
        __syncthreads();

        const __nv_bfloat16* Khi = (const __nv_bfloat16*)(smc + AT_K0 + (kc & 1) * 18432);
        const __nv_bfloat16* Klo = Khi + 4608;

        float s[4][4];
#pragma unroll
        for (int ni = 0; ni < 4; ni++)
#pragma unroll
            for (int j = 0; j < 4; j++) s[ni][j] = 0.f;

#pragma unroll
        for (int kk = 0; kk < 64; kk += 16) {
            uint32_t ah[4], al[4];
            int rb0 = (wm * 16 + gID) * AT_SA + kk + t4 * 2;
            int rb1 = rb0 + 8 * AT_SA;
            ah[0] = *(const uint32_t*)&Qhi[rb0];
            ah[1] = *(const uint32_t*)&Qhi[rb1];
            ah[2] = *(const uint32_t*)&Qhi[rb0 + 8];
            ah[3] = *(const uint32_t*)&Qhi[rb1 + 8];
            al[0] = *(const uint32_t*)&Qlo[rb0];
            al[1] = *(const uint32_t*)&Qlo[rb1];
            al[2] = *(const uint32_t*)&Qlo[rb0 + 8];
            al[3] = *(const uint32_t*)&Qlo[rb1 + 8];
#pragma unroll
            for (int ni = 0; ni < 4; ni++) {
                int nb = (wn * 32 + ni * 8 + gID) * AT_SA + kk + t4 * 2;
                uint32_t bh[2], bl[2];
                bh[0] = *(const uint32_t*)&Khi[nb];
                bh[1] = *(const uint32_t*)&Khi[nb + 8];
                bl[0] = *(const uint32_t*)&Klo[nb];
                bl[1] = *(const uint32_t*)&Klo[nb + 8];
                mma16816(s[ni], ah, bh);
                mma16816(s[ni], al, bh);
                mma16816(s[ni], ah, bl);
            }
        }
#pragma unroll
        for (int ni = 0; ni < 4; ni++) {
            int col = k0 + wn * 32 + ni * 8 + t4 * 2;
#pragma unroll
            for (int hf = 0; hf < 2; hf++) {
                int row = wm * 16 + gID + hf * 8;
                float2 m2 = *(const float2*)(mbase + (size_t)(q0 + row) * SEQ + col);
                float2 o;
                o.x = s[ni][hf * 2 + 0] * 0.125f + m2.x;
                o.y = s[ni][hf * 2 + 1] * 0.125f + m2.y;
                *(float2*)(Ss + row * 512 + col) = o;
            }
        }
        __syncthreads();
    }

    // ---- phase 2: softmax ----
    {
#pragma unroll
        for (int rr = 0; rr < 8; rr++) {
            int r = wid * 8 + rr;
            float* row = Ss + r * 512;
            float4 v[4];
#pragma unroll
            for (int it = 0; it < 4; it++)
                v[it] = *(float4*)(row + it * 128 + lid * 4);
            float m = -1e30f;
#pragma unroll
            for (int it = 0; it < 4; it++)
                m = fmaxf(m, fmaxf(fmaxf(v[it].x, v[it].y), fmaxf(v[it].z, v[it].w)));
#pragma unroll
            for (int off = 16; off; off >>= 1)
                m = fmaxf(m, __shfl_xor_sync(0xffffffffu, m, off));
            float sum = 0.f;
#pragma unroll
            for (int it = 0; it < 4; it++) {
                v[it].x = fast_exp(v[it].x - m);
                v[it].y = fast_exp(v[it].y - m);
                v[it].z = fast_exp(v[it].z - m);
                v[it].w = fast_exp(v[it].w - m);
                sum += v[it].x + v[it].y + v[it].z + v[it].w;
                *(float4*)(row + it * 128 + lid * 4) = v[it];
            }
#pragma unroll
            for (int off = 16; off; off >>= 1)
                sum += __shfl_xor_sync(0xffffffffu, sum, off);
            if (lid == 0) invs[r] = 1.0f / sum;
        }
    }

    // ---- phase 3: P @ V ----
    __nv_bfloat16* Vth = (__nv_bfloat16*)(smc + AT_K0);
    __nv_bfloat16* Vtl = Vth + 4608;
    for (int kc = 0; kc < 8; kc++) {
        const int k0 = kc * 64;
        __syncthreads();

        // P chunk: normalize + split
        {
            int r = tid >> 2, c0 = (tid & 3) * 16;
            float is = invs[r];
#pragma unroll
            for (int j2 = 0; j2 < 2; j2++) {
                const float* src = Ss + r * 512 + k0 + c0 + j2 * 8;
                float4 a = *(const float4*)(src);
                float4 bq = *(const float4*)(src + 4);
                float vals[8] = {a.x * is, a.y * is, a.z * is, a.w * is,
                                 bq.x * is, bq.y * is, bq.z * is, bq.w * is};
                unsigned short hh[8], ll[8];
#pragma unroll
                for (int j = 0; j < 8; j++) split1(vals[j], hh[j], ll[j]);
                uint4 hv, lv;
                hv.x = pack2(hh[0], hh[1]); hv.y = pack2(hh[2], hh[3]);
                hv.z = pack2(hh[4], hh[5]); hv.w = pack2(hh[6], hh[7]);
                lv.x = pack2(ll[0], ll[1]); lv.y = pack2(ll[2], ll[3]);
                lv.z = pack2(ll[4], ll[5]); lv.w = pack2(ll[6], ll[7]);
                *(uint4*)(Phi + r * AT_SA + c0 + j2 * 8) = hv;
                *(uint4*)(Plo + r * AT_SA + c0 + j2 * 8) = lv;
            }
        }

        // V chunk: transpose
#pragma unroll
        for (int i = 0; i < 4; i++) {
            int e = tid + i * 256;
            int r = e >> 4, c4 = e & 15;
            size_t src = hbq + (size_t)(k0 + r) * QS + c4 * 4;
            uint2 hv = *(const uint2*)(Vhi_g + src);
            uint2 lv = *(const uint2*)(Vlo_g + src);
            int d = c4 * 4;
            Vth[(d + 0) * AT_SA + r] = __ushort_as_bfloat16((unsigned short)(hv.x & 0xffff));
            Vth[(d + 1) * AT_SA + r] = __ushort_as_bfloat16((unsigned short)(hv.x >> 16));
            Vth[(d + 2) * AT_SA + r] = __ushort_as_bfloat16((unsigned short)(hv.y & 0xffff));
            Vth[(d + 3) * AT_SA + r] = __ushort_as_bfloat16((unsigned short)(hv.y >> 16));
            Vtl[(d + 0) * AT_SA + r] = __ushort_as_bfloat16((unsigned short)(lv.x & 0xffff));
            Vtl[(d + 1) * AT_SA + r] = __ushort_as_bfloat16((unsigned short)(lv.x >> 16));
            Vtl[(d + 2) * AT_SA + r] = __ushort_as_bfloat16((unsigned short)(lv.y & 0xffff));
            Vtl[(d + 3) * AT_SA + r] = __ushort_as_bfloat16((unsigned short)(lv.y >> 16));
        }
        __syncthreads();

#pragma unroll
        for (int kk = 0; kk < 64; kk += 16) {
            uint32_t ah[4], al[4];
            int rb0 = (wm * 16 + gID) * AT_SA + kk + t4 * 2;
            int rb1 = rb0 + 8 * AT_SA;
            ah[0] = *(const uint32_t*)&Phi[rb0];
            ah[1] = *(const uint32_t*)&Phi[rb1];
            ah[2] = *(const uint32_t*)&Phi[rb0 + 8];
            ah[3] = *(const uint32_t*)&Phi[rb1 + 8];
            al[0] = *(const uint32_t*)&Plo[rb0];
            al[1] = *(const uint32_t*)&Plo[rb1];
            al[2] = *(const uint32_t*)&Plo[rb0 + 8];
            al[3] = *(const uint32_t*)&Plo[rb1 + 8];
#pragma unroll
            for (int ni = 0; ni < 4; ni++) {
                int nb = (wn * 32 + ni * 8 + gID) * AT_SA + kk + t4 * 2;
                uint32_t bh[2], bl[2];
                bh[0] = *(const uint32_t*)&Vth[nb];
                bh[1] = *(const uint32_t*)&Vth[nb + 8];
                bl[0] = *(const uint32_t*)&Vtl[nb];
                bl[1] = *(const uint32_t*)&Vtl[nb + 8];
                mma16816(pv[ni], ah, bh);
                mma16816(pv[ni], al, bh);
                mma16816(pv[ni], ah, bl);
            }
        }
    }

    // ---- write ctx as bf16 hi/lo ----
#pragma unroll
    for (int ni = 0; ni < 4; ni++) {
        int d = wn * 32 + ni * 8 + t4 * 2;
#pragma unroll
        for (int hf = 0; hf < 2; hf++) {
            int row = wm * 16 + gID + hf * 8;
            unsigned short h0, h1, l0, l1;
            split1(pv[ni][hf * 2 + 0], h0, l0);
            split1(pv[ni][hf * 2 + 1], h1, l1);
            size_t o = hbo + (size_t)(q0 + row) * DMODEL + d;
            *(uint32_t*)(Chi_g + o) = pack2(h0, h1);
            *(uint32_t*)(Clo_g + o) = pack2(l0, l1);
        }
    }
}

// ---------------------------------------------------------------------------
// LayerNorm + residual; optional bf16 hi/lo side outputs
// ---------------------------------------------------------------------------
__global__ void ln_residual_kernel(const float* __restrict__ y,
                                   const float* __restrict__ res,
                                   const float* __restrict__ g,
                                   const float* __restrict__ bta,
                                   float* __restrict__ out,
                                   __nv_bfloat16* __restrict__ ohi,
                                   __nv_bfloat16* __restrict__ olo)
{
    __shared__ float red[256];
    const int r = blockIdx.x;
    const int tid = threadIdx.x;
    const size_t off = (size_t)r * DMODEL;

    float v0 = y[off + tid]        + res[off + tid];
    float v1 = y[off + tid + 256]  + res[off + tid + 256];

    red[tid] = v0 + v1;
    __syncthreads();
#pragma unroll
    for (int s = 128; s; s >>= 1) {
        if (tid < s) red[tid] += red[tid + s];
        __syncthreads();
    }
    float mean = red[0] * (1.0f / 512.0f);
    __syncthreads();

    float d0 = v0 - mean, d1 = v1 - mean;
    red[tid] = d0 * d0 + d1 * d1;
    __syncthreads();
#pragma unroll
    for (int s = 128; s; s >>= 1) {
        if (tid < s) red[tid] += red[tid + s];
        __syncthreads();
    }
    float inv = rsqrtf(red[0] * (1.0f / 512.0f) + LN_EPS);

    float o0 = d0 * inv * g[tid]       + bta[tid];
    float o1 = d1 * inv * g[tid + 256] + bta[tid + 256];
    out[off + tid]       = o0;
    out[off + tid + 256] = o1;
    if (ohi) {
        unsigned short h, l;
        split1(o0, h, l);
        ohi[off + tid] = __ushort_as_bfloat16(h);
        olo[off + tid] = __ushort_as_bfloat16(l);
        split1(o1, h, l);
        ohi[off + tid + 256] = __ushort_as_bfloat16(h);
        olo[off + tid + 256] = __ushort_as_bfloat16(l);
    }
}

// ---------------------------------------------------------------------------
// launch
// ---------------------------------------------------------------------------
extern "C" void kernel_launch(void* const* d_in, const int* in_sizes, int n_in,
                              void* d_out, int out_size)
{
    const float* x     = (const float*)d_in[0];
    const float* mask  = (const float*)d_in[1];
    const float* Wq    = (const float*)d_in[2];
    const float* bq    = (const float*)d_in[3];
    const float* Wk    = (const float*)d_in[4];
    const float* bk    = (const float*)d_in[5];
    const float* Wv    = (const float*)d_in[6];
    const float* bv    = (const float*)d_in[7];
    const float* Wo    = (const float*)d_in[8];
    const float* bo    = (const float*)d_in[9];
    const float* ln1g  = (const float*)d_in[10];
    const float* ln1b  = (const float*)d_in[11];
    const float* W1    = (const float*)d_in[12];
    const float* b1    = (const float*)d_in[13];
    const float* W2    = (const float*)d_in[14];
    const float* b2    = (const float*)d_in[15];
    const float* ln2g  = (const float*)d_in[16];
    const float* ln2b  = (const float*)d_in[17];
    float* out = (float*)d_out;

    float *t0, *aln, *bqkv;
    cudaGetSymbolAddress((void**)&t0,   g_t0);
    cudaGetSymbolAddress((void**)&aln,  g_attnln);
    cudaGetSymbolAddress((void**)&bqkv, g_bqkv);

    __nv_bfloat16 *xhi, *xlo, *qkvhi, *qkvlo, *chi, *clo, *ahi, *alo, *fhi, *flo;
    cudaGetSymbolAddress((void**)&xhi,   g_xhi);
    cudaGetSymbolAddress((void**)&xlo,   g_xlo);
    cudaGetSymbolAddress((void**)&qkvhi, g_qkvhi);
    cudaGetSymbolAddress((void**)&qkvlo, g_qkvlo);
    cudaGetSymbolAddress((void**)&chi,   g_chi);
    cudaGetSymbolAddress((void**)&clo,   g_clo);
    cudaGetSymbolAddress((void**)&ahi,   g_ahi);
    cudaGetSymbolAddress((void**)&alo,   g_alo);
    cudaGetSymbolAddress((void**)&fhi,   g_fhi);
    cudaGetSymbolAddress((void**)&flo,   g_flo);

    __nv_bfloat16 *wqkvh, *wqkvl, *woh, *wol, *w1h, *w1l, *w2h, *w2l;
    cudaGetSymbolAddress((void**)&wqkvh, g_wqkvhi);
    cudaGetSymbolAddress((void**)&wqkvl, g_wqkvlo);
    cudaGetSymbolAddress((void**)&woh,   g_wohi);
    cudaGetSymbolAddress((void**)&wol,   g_wolo);
    cudaGetSymbolAddress((void**)&w1h,   g_w1hi);
    cudaGetSymbolAddress((void**)&w1l,   g_w1lo);
    cudaGetSymbolAddress((void**)&w2h,   g_w2hi);
    cudaGetSymbolAddress((void**)&w2l,   g_w2lo);

    cudaFuncSetAttribute(attn_mma,
                         cudaFuncAttributeMaxDynamicSharedMemorySize, AT_SMEM);
    cudaFuncSetAttribute(gemm_mma,
                         cudaFuncAttributeMaxDynamicSharedMemorySize, GM_SMEM_BYTES);

    dim3 tb(32, 8);

    // weight transpose + split (QKV concatenated)
    tsplit_kernel<<<dim3(DMODEL / 32, DMODEL / 32), tb>>>(Wq, wqkvh, wqkvl, DMODEL, DMODEL, 0);
    tsplit_kernel<<<dim3(DMODEL / 32, DMODEL / 32), tb>>>(Wk, wqkvh, wqkvl, DMODEL, DMODEL, 512);
    tsplit_kernel<<<dim3(DMODEL / 32, DMODEL / 32), tb>>>(Wv, wqkvh, wqkvl, DMODEL, DMODEL, 1024);
    tsplit_kernel<<<dim3(DMODEL / 32, DMODEL / 32), tb>>>(Wo, woh, wol, DMODEL, DMODEL, 0);
    tsplit_kernel<<<dim3(DFF / 32, DMODEL / 32), tb>>>(W1, w1h, w1l, DMODEL, DFF, 0);
    tsplit_kernel<<<dim3(DMODEL / 32, DFF / 32), tb>>>(W2, w2h, w2l, DFF, DMODEL, 0);
    concat_bias_kernel<<<6, 256>>>(bq, bk, bv, bqkv);

    // split input x
    {
        int n4 = MTOK * DMODEL / 4;
        split_kernel<<<(n4 + 255) / 256, 256>>>(x, xhi, xlo, n4);
    }

    // fused QKV projection -> combined bf16 hi/lo, stride 1536
    {
        dim3 grid(QS / 128, MTOK / 128);
        gemm_mma<<<grid, 256, GM_SMEM_BYTES>>>(xhi, xlo, wqkvh, wqkvl, bqkv,
                                               nullptr, qkvhi, qkvlo,
                                               MTOK, QS, DMODEL, 0);
    }

    // attention -> ctx bf16 hi/lo
    {
        dim3 grid(SEQ / 64, NHEADS, BATCH);
        attn_mma<<<grid, 256, AT_SMEM>>>(qkvhi, qkvlo,
                                         qkvhi + 512, qkvlo + 512,
                                         qkvhi + 1024, qkvlo + 1024,
                                         mask, chi, clo);
    }

    // output projection + residual LN
    {
        dim3 grid(DMODEL / 128, MTOK / 128);
        gemm_mma<<<grid, 256, GM_SMEM_BYTES>>>(chi, clo, woh, wol, bo,
                                               t0, nullptr, nullptr,
                                               MTOK, DMODEL, DMODEL, 0);
        ln_residual_kernel<<<MTOK, 256>>>(t0, x, ln1g, ln1b, aln, ahi, alo);
    }

    // FFN
    {
        dim3 grid1(DFF / 128, MTOK / 128);
        gemm_mma<<<grid1, 256, GM_SMEM_BYTES>>>(ahi, alo, w1h, w1l, b1,
                                                nullptr, fhi, flo,
                                                MTOK, DFF, DMODEL, 1);
        dim3 grid2(DMODEL / 128, MTOK / 128);
        gemm_mma<<<grid2, 256, GM_SMEM_BYTES>>>(fhi, flo, w2h, w2l, b2,
                                                t0, nullptr, nullptr,
                                                MTOK, DMODEL, DFF, 0);
        ln_residual_kernel<<<MTOK, 256>>>(t0, aln, ln2g, ln2b, out,
                                          nullptr, nullptr);
    }
}

// round 9
// speedup vs baseline: 1.0233x; 1.0233x over previous
#include <cuda_runtime.h>
#include <cuda_bf16.h>
#include <math.h>
#include <stdint.h>

// ---------------------------------------------------------------------------
// Problem dims (fixed)
// ---------------------------------------------------------------------------
#define BATCH   32
#define SEQ     512
#define DMODEL  512
#define NHEADS  8
#define HDIM    64
#define DFF     2048
#define MTOK    (BATCH * SEQ)
#define LN_EPS  1e-12f
#define QS      1536                      // qkv combined row stride

// ---------------------------------------------------------------------------
// Scratch (device globals)
// ---------------------------------------------------------------------------
__device__ float g_t0[MTOK * DMODEL];
__device__ float g_attnln[MTOK * DMODEL];
__device__ float g_bqkv[QS];

__device__ __nv_bfloat16 g_xhi[MTOK * DMODEL];
__device__ __nv_bfloat16 g_xlo[MTOK * DMODEL];
__device__ __nv_bfloat16 g_qkvhi[MTOK * QS];
__device__ __nv_bfloat16 g_qkvlo[MTOK * QS];
__device__ __nv_bfloat16 g_chi[MTOK * DMODEL];
__device__ __nv_bfloat16 g_clo[MTOK * DMODEL];
__device__ __nv_bfloat16 g_ahi[MTOK * DMODEL];
__device__ __nv_bfloat16 g_alo[MTOK * DMODEL];
__device__ __nv_bfloat16 g_fhi[MTOK * DFF];
__device__ __nv_bfloat16 g_flo[MTOK * DFF];

__device__ __nv_bfloat16 g_wqkvhi[QS * DMODEL];
__device__ __nv_bfloat16 g_wqkvlo[QS * DMODEL];
__device__ __nv_bfloat16 g_wohi[DMODEL * DMODEL];
__device__ __nv_bfloat16 g_wolo[DMODEL * DMODEL];
__device__ __nv_bfloat16 g_w1hi[DFF * DMODEL];
__device__ __nv_bfloat16 g_w1lo[DFF * DMODEL];
__device__ __nv_bfloat16 g_w2hi[DMODEL * DFF];
__device__ __nv_bfloat16 g_w2lo[DMODEL * DFF];

// ---------------------------------------------------------------------------
// helpers
// ---------------------------------------------------------------------------
__device__ __forceinline__ void mma16816(float* c, const uint32_t* a, const uint32_t* b)
{
    asm volatile(
        "mma.sync.aligned.m16n8k16.row.col.f32.bf16.bf16.f32 "
        "{%0,%1,%2,%3}, {%4,%5,%6,%7}, {%8,%9}, {%0,%1,%2,%3};"
        : "+f"(c[0]), "+f"(c[1]), "+f"(c[2]), "+f"(c[3])
        : "r"(a[0]), "r"(a[1]), "r"(a[2]), "r"(a[3]), "r"(b[0]), "r"(b[1]));
}

__device__ __forceinline__ uint32_t smem_u32(const void* p) {
    uint32_t a;
    asm("{ .reg .u64 t; cvta.to.shared.u64 t, %1; cvt.u32.u64 %0, t; }"
        : "=r"(a) : "l"(p));
    return a;
}

__device__ __forceinline__ void cp16(uint32_t dst, const void* src) {
    asm volatile("cp.async.cg.shared.global [%0], [%1], 16;"
                 :: "r"(dst), "l"(src));
}
__device__ __forceinline__ void cp_commit() {
    asm volatile("cp.async.commit_group;" ::: "memory");
}
template <int N>
__device__ __forceinline__ void cp_wait() {
    asm volatile("cp.async.wait_group %0;" :: "n"(N) : "memory");
}

__device__ __forceinline__ float fast_exp(float x) {
    float y = fmaxf(x * 1.4426950408889634f, -120.0f);
    float n = rintf(y);
    float f = y - n;
    float p = 1.3333558e-3f;
    p = fmaf(p, f, 9.6181291e-3f);
    p = fmaf(p, f, 5.5504109e-2f);
    p = fmaf(p, f, 2.4022651e-1f);
    p = fmaf(p, f, 6.9314718e-1f);
    p = fmaf(p, f, 1.0f);
    return p * __int_as_float(((int)n + 127) << 23);
}

__device__ __forceinline__ void split1(float v, unsigned short& h, unsigned short& l) {
    __nv_bfloat16 hb = __float2bfloat16_rn(v);
    float r = v - __bfloat162float(hb);
    __nv_bfloat16 lb = __float2bfloat16_rn(r);
    h = __bfloat16_as_ushort(hb);
    l = __bfloat16_as_ushort(lb);
}
__device__ __forceinline__ uint32_t pack2(unsigned short a, unsigned short b) {
    return (uint32_t)a | ((uint32_t)b << 16);
}

// ---------------------------------------------------------------------------
// prep kernels
// ---------------------------------------------------------------------------
__global__ void split_kernel(const float* __restrict__ X,
                             __nv_bfloat16* __restrict__ hi,
                             __nv_bfloat16* __restrict__ lo, int n4)
{
    int i = blockIdx.x * blockDim.x + threadIdx.x;
    if (i >= n4) return;
    float4 x = ((const float4*)X)[i];
    unsigned short h0, h1, h2, h3, l0, l1, l2, l3;
    split1(x.x, h0, l0); split1(x.y, h1, l1);
    split1(x.z, h2, l2); split1(x.w, h3, l3);
    uint2 hv, lv;
    hv.x = pack2(h0, h1); hv.y = pack2(h2, h3);
    lv.x = pack2(l0, l1); lv.y = pack2(l2, l3);
    ((uint2*)hi)[i] = hv;
    ((uint2*)lo)[i] = lv;
}

// Transpose + split: W[K][N] fp32 -> hi/lo [noff+N][K] bf16
__global__ void tsplit_kernel(const float* __restrict__ W,
                              __nv_bfloat16* __restrict__ hi,
                              __nv_bfloat16* __restrict__ lo,
                              int K, int N, int noff)
{
    __shared__ float tile[32][33];
    const int n0 = blockIdx.x * 32, k0 = blockIdx.y * 32;
    const int tx = threadIdx.x, ty = threadIdx.y;
#pragma unroll
    for (int i = 0; i < 32; i += 8)
        tile[ty + i][tx] = W[(size_t)(k0 + ty + i) * N + n0 + tx];
    __syncthreads();
#pragma unroll
    for (int i = 0; i < 32; i += 8) {
        float v = tile[tx][ty + i];
        unsigned short h, l;
        split1(v, h, l);
        size_t o = (size_t)(noff + n0 + ty + i) * K + k0 + tx;
        hi[o] = __ushort_as_bfloat16(h);
        lo[o] = __ushort_as_bfloat16(l);
    }
}

__global__ void concat_bias_kernel(const float* __restrict__ a,
                                   const float* __restrict__ b,
                                   const float* __restrict__ c,
                                   float* __restrict__ o)
{
    int i = blockIdx.x * blockDim.x + threadIdx.x;
    if (i >= QS) return;
    o[i] = (i < 512) ? a[i] : (i < 1024) ? b[i - 512] : c[i - 1024];
}

// ---------------------------------------------------------------------------
// Pipelined tensor-core split-GEMM (round-7 proven config).
// CTA 128x64, k-tile 32, 2-stage cp.async, 60 KB smem -> 3 CTA/SM.
// ---------------------------------------------------------------------------
#define SA2 40
#define ST2_A (128 * SA2)                 // 5120 elems
#define ST2_B (64 * SA2)                  // 2560 elems
#define STAGE2 (2 * ST2_A + 2 * ST2_B)    // 15360 elems
#define GM_SMEM_BYTES (2 * STAGE2 * 2)    // 61440 bytes

__global__ __launch_bounds__(256)
void gemm_mma(const __nv_bfloat16* __restrict__ Ahi,
              const __nv_bfloat16* __restrict__ Alo,
              const __nv_bfloat16* __restrict__ Bhi,
              const __nv_bfloat16* __restrict__ Blo,
              const float* __restrict__ bias,
              float* __restrict__ Cf,
              __nv_bfloat16* __restrict__ Chi,
              __nv_bfloat16* __restrict__ Clo,
              int M, int N, int K, int do_gelu)
{
    extern __shared__ __nv_bfloat16 smb[];
    const uint32_t sm_base = smem_u32(smb);

    const int tid = threadIdx.x;
    const int wid = tid >> 5;
    const int lid = tid & 31;
    const int gID = lid >> 2;
    const int t4  = lid & 3;

    const int row0 = blockIdx.y * 128;
    const int col0 = blockIdx.x * 64;
    const int m_off = (wid & 3) * 32;
    const int n_off = (wid >> 2) * 32;

    auto load_stage = [&](int buf, int t) {
        const int kb = t << 5;
        uint32_t base = sm_base + (uint32_t)buf * (STAGE2 * 2);
#pragma unroll
        for (int i = 0; i < 2; i++) {
            int e = tid + i * 256;
            int r = e >> 2, g = e & 3;
            uint32_t ds = (uint32_t)(r * SA2 + g * 8) * 2;
            size_t src = (size_t)(row0 + r) * K + kb + g * 8;
            cp16(base + ds, Ahi + src);
            cp16(base + ST2_A * 2 + ds, Alo + src);
        }
        {
            int r = tid >> 2, g = tid & 3;
            uint32_t ds = (uint32_t)(r * SA2 + g * 8) * 2;
            size_t src = (size_t)(col0 + r) * K + kb + g * 8;
            cp16(base + 2 * ST2_A * 2 + ds, Bhi + src);
            cp16(base + 2 * ST2_A * 2 + ST2_B * 2 + ds, Blo + src);
        }
        cp_commit();
    };

    float acc[2][4][4];
#pragma unroll
    for (int mi = 0; mi < 2; mi++)
#pragma unroll
        for (int ni = 0; ni < 4; ni++)
#pragma unroll
            for (int j = 0; j < 4; j++) acc[mi][ni][j] = 0.f;

    const int nT = K >> 5;
    load_stage(0, 0);

    for (int t = 0; t < nT; t++) {
        const int buf = t & 1;
        if (t + 1 < nT) {
            load_stage(1 - buf, t + 1);
            cp_wait<1>();
        } else {
            cp_wait<0>();
        }
        __syncthreads();

        const __nv_bfloat16* As_hi = smb + buf * STAGE2;
        const __nv_bfloat16* As_lo = As_hi + ST2_A;
        const __nv_bfloat16* Bs_hi = As_hi + 2 * ST2_A;
        const __nv_bfloat16* Bs_lo = Bs_hi + ST2_B;

#pragma unroll
        for (int kk = 0; kk < 32; kk += 16) {
            uint32_t ahi[2][4], alo[2][4], bhi[4][2], blo[4][2];
#pragma unroll
            for (int mi = 0; mi < 2; mi++) {
                int r = m_off + mi * 16 + gID;
                int base0 = r * SA2 + kk + t4 * 2;
                int base1 = (r + 8) * SA2 + kk + t4 * 2;
                ahi[mi][0] = *(const uint32_t*)&As_hi[base0];
                ahi[mi][1] = *(const uint32_t*)&As_hi[base1];
                ahi[mi][2] = *(const uint32_t*)&As_hi[base0 + 8];
                ahi[mi][3] = *(const uint32_t*)&As_hi[base1 + 8];
                alo[mi][0] = *(const uint32_t*)&As_lo[base0];
                alo[mi][1] = *(const uint32_t*)&As_lo[base1];
                alo[mi][2] = *(const uint32_t*)&As_lo[base0 + 8];
                alo[mi][3] = *(const uint32_t*)&As_lo[base1 + 8];
            }
#pragma unroll
            for (int ni = 0; ni < 4; ni++) {
                int n = n_off + ni * 8 + gID;
                int base = n * SA2 + kk + t4 * 2;
                bhi[ni][0] = *(const uint32_t*)&Bs_hi[base];
                bhi[ni][1] = *(const uint32_t*)&Bs_hi[base + 8];
                blo[ni][0] = *(const uint32_t*)&Bs_lo[base];
                blo[ni][1] = *(const uint32_t*)&Bs_lo[base + 8];
            }
#pragma unroll
            for (int mi = 0; mi < 2; mi++)
#pragma unroll
                for (int ni = 0; ni < 4; ni++) {
                    mma16816(acc[mi][ni], ahi[mi], bhi[ni]);
                    mma16816(acc[mi][ni], alo[mi], bhi[ni]);
                    mma16816(acc[mi][ni], ahi[mi], blo[ni]);
                }
        }
        __syncthreads();
    }

    // ---- epilogue ----
#pragma unroll
    for (int mi = 0; mi < 2; mi++) {
#pragma unroll
        for (int ni = 0; ni < 4; ni++) {
            int col = col0 + n_off + ni * 8 + t4 * 2;
            float b0 = bias[col], b1 = bias[col + 1];
#pragma unroll
            for (int half = 0; half < 2; half++) {
                int row = row0 + m_off + mi * 16 + gID + half * 8;
                float v0 = acc[mi][ni][half * 2 + 0] + b0;
                float v1 = acc[mi][ni][half * 2 + 1] + b1;
                if (do_gelu) {
                    v0 = 0.5f * v0 * (1.0f + erff(v0 * 0.70710678118654752f));
                    v1 = 0.5f * v1 * (1.0f + erff(v1 * 0.70710678118654752f));
                }
                size_t o = (size_t)row * N + col;
                if (Cf) {
                    float2 fo; fo.x = v0; fo.y = v1;
                    *(float2*)(Cf + o) = fo;
                }
                if (Chi) {
                    unsigned short h0, h1, l0, l1;
                    split1(v0, h0, l0);
                    split1(v1, h1, l1);
                    *(uint32_t*)(Chi + o) = pack2(h0, h1);
                    *(uint32_t*)(Clo + o) = pack2(l0, l1);
                }
            }
        }
    }
}

// ---------------------------------------------------------------------------
// Tensor-core attention (round-8 proven; qkv stride QS).
// ---------------------------------------------------------------------------
#define AT_SA   72
#define AT_QHI  0
#define AT_QLO  9216
#define AT_K0   18432
#define AT_PHI  55296
#define AT_PLO  64512
#define AT_SS   73728
#define AT_INV  (AT_SS + 64 * 512 * 4)
#define AT_SMEM (AT_INV + 256)

__global__ __launch_bounds__(256)
void attn_mma(const __nv_bfloat16* __restrict__ Qhi_g,
              const __nv_bfloat16* __restrict__ Qlo_g,
              const __nv_bfloat16* __restrict__ Khi_g,
              const __nv_bfloat16* __restrict__ Klo_g,
              const __nv_bfloat16* __restrict__ Vhi_g,
              const __nv_bfloat16* __restrict__ Vlo_g,
              const float* __restrict__ mask,
              __nv_bfloat16* __restrict__ Chi_g,
              __nv_bfloat16* __restrict__ Clo_g)
{
    extern __shared__ char smc[];
    const uint32_t sm_base = smem_u32(smc);
    __nv_bfloat16* Qhi = (__nv_bfloat16*)(smc + AT_QHI);
    __nv_bfloat16* Qlo = (__nv_bfloat16*)(smc + AT_QLO);
    __nv_bfloat16* Phi = (__nv_bfloat16*)(smc + AT_PHI);
    __nv_bfloat16* Plo = (__nv_bfloat16*)(smc + AT_PLO);
    float* Ss   = (float*)(smc + AT_SS);
    float* invs = (float*)(smc + AT_INV);

    const int tid = threadIdx.x;
    const int wid = tid >> 5, lid = tid & 31;
    const int gID = lid >> 2, t4 = lid & 3;
    const int wm = wid & 3, wn = wid >> 2;
    const int q0 = blockIdx.x * 64;
    const int h = blockIdx.y, b = blockIdx.z;
    const size_t hbq = ((size_t)b * SEQ) * QS + (size_t)h * HDIM;
    const size_t hbo = ((size_t)b * SEQ) * DMODEL + (size_t)h * HDIM;
    const float* mbase = mask + (size_t)b * SEQ * SEQ;

    auto load_k = [&](int bb, int kc) {
        const int k0 = kc * 64;
        uint32_t kh = sm_base + AT_K0 + (uint32_t)bb * 18432;
        uint32_t kl = kh + 9216;
#pragma unroll
        for (int i = 0; i < 2; i++) {
            int e = tid + i * 256;
            int r = e >> 3, g = e & 7;
            size_t src = hbq + (size_t)(k0 + r) * QS + g * 8;
            uint32_t ds = (uint32_t)(r * AT_SA + g * 8) * 2;
            cp16(kh + ds, Khi_g + src);
            cp16(kl + ds, Klo_g + src);
        }
        cp_commit();
    };

    load_k(0, 0);

    // load Q tile
#pragma unroll
    for (int i = 0; i < 2; i++) {
        int e = tid + i * 256;
        int r = e >> 3, g = e & 7;
        size_t src = hbq + (size_t)(q0 + r) * QS + g * 8;
        int ds = r * AT_SA + g * 8;
        *(uint4*)(Qhi + ds) = *(const uint4*)(Qhi_g + src);
        *(uint4*)(Qlo + ds) = *(const uint4*)(Qlo_g + src);
    }

    float pv[4][4];
#pragma unroll
    for (int ni = 0; ni < 4; ni++)
#pragma unroll
        for (int j = 0; j < 4; j++) pv[ni][j] = 0.f;

    // ---- phase 1: scores ----
    for (int kc = 0; kc < 8; kc++) {
        const int k0 = kc * 64;
        if (kc + 1 < 8) {
            load_k((kc + 1) & 1, kc + 1);
            cp_wait<1>();
        } else {
            cp_wait<0>();
        }
        __syncthreads();

        const __nv_bfloat16* Khi = (const __nv_bfloat16*)(smc + AT_K0 + (kc & 1) * 18432);
        const __nv_bfloat16* Klo = Khi + 4608;

        float s[4][4];
#pragma unroll
        for (int ni = 0; ni < 4; ni++)
#pragma unroll
            for (int j = 0; j < 4; j++) s[ni][j] = 0.f;

#pragma unroll
        for (int kk = 0; kk < 64; kk += 16) {
            uint32_t ah[4], al[4];
            int rb0 = (wm * 16 + gID) * AT_SA + kk + t4 * 2;
            int rb1 = rb0 + 8 * AT_SA;
            ah[0] = *(const uint32_t*)&Qhi[rb0];
            ah[1] = *(const uint32_t*)&Qhi[rb1];
            ah[2] = *(const uint32_t*)&Qhi[rb0 + 8];
            ah[3] = *(const uint32_t*)&Qhi[rb1 + 8];
            al[0] = *(const uint32_t*)&Qlo[rb0];
            al[1] = *(const uint32_t*)&Qlo[rb1];
            al[2] = *(const uint32_t*)&Qlo[rb0 + 8];
            al[3] = *(const uint32_t*)&Qlo[rb1 + 8];
#pragma unroll
            for (int ni = 0; ni < 4; ni++) {
                int nb = (wn * 32 + ni * 8 + gID) * AT_SA + kk + t4 * 2;
                uint32_t bh[2], bl[2];
                bh[0] = *(const uint32_t*)&Khi[nb];
                bh[1] = *(const uint32_t*)&Khi[nb + 8];
                bl[0] = *(const uint32_t*)&Klo[nb];
                bl[1] = *(const uint32_t*)&Klo[nb + 8];
                mma16816(s[ni], ah, bh);
                mma16816(s[ni], al, bh);
                mma16816(s[ni], ah, bl);
            }
        }
#pragma unroll
        for (int ni = 0; ni < 4; ni++) {
            int col = k0 + wn * 32 + ni * 8 + t4 * 2;
#pragma unroll
            for (int hf = 0; hf < 2; hf++) {
                int row = wm * 16 + gID + hf * 8;
                float2 m2 = *(const float2*)(mbase + (size_t)(q0 + row) * SEQ + col);
                float2 o;
                o.x = s[ni][hf * 2 + 0] * 0.125f + m2.x;
                o.y = s[ni][hf * 2 + 1] * 0.125f + m2.y;
                *(float2*)(Ss + row * 512 + col) = o;
            }
        }
        __syncthreads();
    }

    // ---- phase 2: softmax ----
    {
#pragma unroll
        for (int rr = 0; rr < 8; rr++) {
            int r = wid * 8 + rr;
            float* row = Ss + r * 512;
            float4 v[4];
#pragma unroll
            for (int it = 0; it < 4; it++)
                v[it] = *(float4*)(row + it * 128 + lid * 4);
            float m = -1e30f;
#pragma unroll
            for (int it = 0; it < 4; it++)
                m = fmaxf(m, fmaxf(fmaxf(v[it].x, v[it].y), fmaxf(v[it].z, v[it].w)));
#pragma unroll
            for (int off = 16; off; off >>= 1)
                m = fmaxf(m, __shfl_xor_sync(0xffffffffu, m, off));
            float sum = 0.f;
#pragma unroll
            for (int it = 0; it < 4; it++) {
                v[it].x = fast_exp(v[it].x - m);
                v[it].y = fast_exp(v[it].y - m);
                v[it].z = fast_exp(v[it].z - m);
                v[it].w = fast_exp(v[it].w - m);
                sum += v[it].x + v[it].y + v[it].z + v[it].w;
                *(float4*)(row + it * 128 + lid * 4) = v[it];
            }
#pragma unroll
            for (int off = 16; off; off >>= 1)
                sum += __shfl_xor_sync(0xffffffffu, sum, off);
            if (lid == 0) invs[r] = 1.0f / sum;
        }
    }

    // ---- phase 3: P @ V ----
    __nv_bfloat16* Vth = (__nv_bfloat16*)(smc + AT_K0);
    __nv_bfloat16* Vtl = Vth + 4608;
    for (int kc = 0; kc < 8; kc++) {
        const int k0 = kc * 64;
        __syncthreads();

        // P chunk: normalize + split
        {
            int r = tid >> 2, c0 = (tid & 3) * 16;
            float is = invs[r];
#pragma unroll
            for (int j2 = 0; j2 < 2; j2++) {
                const float* src = Ss + r * 512 + k0 + c0 + j2 * 8;
                float4 a = *(const float4*)(src);
                float4 bq = *(const float4*)(src + 4);
                float vals[8] = {a.x * is, a.y * is, a.z * is, a.w * is,
                                 bq.x * is, bq.y * is, bq.z * is, bq.w * is};
                unsigned short hh[8], ll[8];
#pragma unroll
                for (int j = 0; j < 8; j++) split1(vals[j], hh[j], ll[j]);
                uint4 hv, lv;
                hv.x = pack2(hh[0], hh[1]); hv.y = pack2(hh[2], hh[3]);
                hv.z = pack2(hh[4], hh[5]); hv.w = pack2(hh[6], hh[7]);
                lv.x = pack2(ll[0], ll[1]); lv.y = pack2(ll[2], ll[3]);
                lv.z = pack2(ll[4], ll[5]); lv.w = pack2(ll[6], ll[7]);
                *(uint4*)(Phi + r * AT_SA + c0 + j2 * 8) = hv;
                *(uint4*)(Plo + r * AT_SA + c0 + j2 * 8) = lv;
            }
        }

        // V chunk: transpose
#pragma unroll
        for (int i = 0; i < 4; i++) {
            int e = tid + i * 256;
            int r = e >> 4, c4 = e & 15;
            size_t src = hbq + (size_t)(k0 + r) * QS + c4 * 4;
            uint2 hv = *(const uint2*)(Vhi_g + src);
            uint2 lv = *(const uint2*)(Vlo_g + src);
            int d = c4 * 4;
            Vth[(d + 0) * AT_SA + r] = __ushort_as_bfloat16((unsigned short)(hv.x & 0xffff));
            Vth[(d + 1) * AT_SA + r] = __ushort_as_bfloat16((unsigned short)(hv.x >> 16));
            Vth[(d + 2) * AT_SA + r] = __ushort_as_bfloat16((unsigned short)(hv.y & 0xffff));
            Vth[(d + 3) * AT_SA + r] = __ushort_as_bfloat16((unsigned short)(hv.y >> 16));
            Vtl[(d + 0) * AT_SA + r] = __ushort_as_bfloat16((unsigned short)(lv.x & 0xffff));
            Vtl[(d + 1) * AT_SA + r] = __ushort_as_bfloat16((unsigned short)(lv.x >> 16));
            Vtl[(d + 2) * AT_SA + r] = __ushort_as_bfloat16((unsigned short)(lv.y & 0xffff));
            Vtl[(d + 3) * AT_SA + r] = __ushort_as_bfloat16((unsigned short)(lv.y >> 16));
        }
        __syncthreads();

#pragma unroll
        for (int kk = 0; kk < 64; kk += 16) {
            uint32_t ah[4], al[4];
            int rb0 = (wm * 16 + gID) * AT_SA + kk + t4 * 2;
            int rb1 = rb0 + 8 * AT_SA;
            ah[0] = *(const uint32_t*)&Phi[rb0];
            ah[1] = *(const uint32_t*)&Phi[rb1];
            ah[2] = *(const uint32_t*)&Phi[rb0 + 8];
            ah[3] = *(const uint32_t*)&Phi[rb1 + 8];
            al[0] = *(const uint32_t*)&Plo[rb0];
            al[1] = *(const uint32_t*)&Plo[rb1];
            al[2] = *(const uint32_t*)&Plo[rb0 + 8];
            al[3] = *(const uint32_t*)&Plo[rb1 + 8];
#pragma unroll
            for (int ni = 0; ni < 4; ni++) {
                int nb = (wn * 32 + ni * 8 + gID) * AT_SA + kk + t4 * 2;
                uint32_t bh[2], bl[2];
                bh[0] = *(const uint32_t*)&Vth[nb];
                bh[1] = *(const uint32_t*)&Vth[nb + 8];
                bl[0] = *(const uint32_t*)&Vtl[nb];
                bl[1] = *(const uint32_t*)&Vtl[nb + 8];
                mma16816(pv[ni], ah, bh);
                mma16816(pv[ni], al, bh);
                mma16816(pv[ni], ah, bl);
            }
        }
    }

    // ---- write ctx as bf16 hi/lo ----
#pragma unroll
    for (int ni = 0; ni < 4; ni++) {
        int d = wn * 32 + ni * 8 + t4 * 2;
#pragma unroll
        for (int hf = 0; hf < 2; hf++) {
            int row = wm * 16 + gID + hf * 8;
            unsigned short h0, h1, l0, l1;
            split1(pv[ni][hf * 2 + 0], h0, l0);
            split1(pv[ni][hf * 2 + 1], h1, l1);
            size_t o = hbo + (size_t)(q0 + row) * DMODEL + d;
            *(uint32_t*)(Chi_g + o) = pack2(h0, h1);
            *(uint32_t*)(Clo_g + o) = pack2(l0, l1);
        }
    }
}

// ---------------------------------------------------------------------------
// LayerNorm + residual; optional bf16 hi/lo side outputs
// ---------------------------------------------------------------------------
__global__ void ln_residual_kernel(const float* __restrict__ y,
                                   const float* __restrict__ res,
                                   const float* __restrict__ g,
                                   const float* __restrict__ bta,
                                   float* __restrict__ out,
                                   __nv_bfloat16* __restrict__ ohi,
                                   __nv_bfloat16* __restrict__ olo)
{
    __shared__ float red[256];
    const int r = blockIdx.x;
    const int tid = threadIdx.x;
    const size_t off = (size_t)r * DMODEL;

    float v0 = y[off + tid]        + res[off + tid];
    float v1 = y[off + tid + 256]  + res[off + tid + 256];

    red[tid] = v0 + v1;
    __syncthreads();
#pragma unroll
    for (int s = 128; s; s >>= 1) {
        if (tid < s) red[tid] += red[tid + s];
        __syncthreads();
    }
    float mean = red[0] * (1.0f / 512.0f);
    __syncthreads();

    float d0 = v0 - mean, d1 = v1 - mean;
    red[tid] = d0 * d0 + d1 * d1;
    __syncthreads();
#pragma unroll
    for (int s = 128; s; s >>= 1) {
        if (tid < s) red[tid] += red[tid + s];
        __syncthreads();
    }
    float inv = rsqrtf(red[0] * (1.0f / 512.0f) + LN_EPS);

    float o0 = d0 * inv * g[tid]       + bta[tid];
    float o1 = d1 * inv * g[tid + 256] + bta[tid + 256];
    out[off + tid]       = o0;
    out[off + tid + 256] = o1;
    if (ohi) {
        unsigned short h, l;
        split1(o0, h, l);
        ohi[off + tid] = __ushort_as_bfloat16(h);
        olo[off + tid] = __ushort_as_bfloat16(l);
        split1(o1, h, l);
        ohi[off + tid + 256] = __ushort_as_bfloat16(h);
        olo[off + tid + 256] = __ushort_as_bfloat16(l);
    }
}

// ---------------------------------------------------------------------------
// launch
// ---------------------------------------------------------------------------
extern "C" void kernel_launch(void* const* d_in, const int* in_sizes, int n_in,
                              void* d_out, int out_size)
{
    const float* x     = (const float*)d_in[0];
    const float* mask  = (const float*)d_in[1];
    const float* Wq    = (const float*)d_in[2];
    const float* bq    = (const float*)d_in[3];
    const float* Wk    = (const float*)d_in[4];
    const float* bk    = (const float*)d_in[5];
    const float* Wv    = (const float*)d_in[6];
    const float* bv    = (const float*)d_in[7];
    const float* Wo    = (const float*)d_in[8];
    const float* bo    = (const float*)d_in[9];
    const float* ln1g  = (const float*)d_in[10];
    const float* ln1b  = (const float*)d_in[11];
    const float* W1    = (const float*)d_in[12];
    const float* b1    = (const float*)d_in[13];
    const float* W2    = (const float*)d_in[14];
    const float* b2    = (const float*)d_in[15];
    const float* ln2g  = (const float*)d_in[16];
    const float* ln2b  = (const float*)d_in[17];
    float* out = (float*)d_out;

    float *t0, *aln, *bqkv;
    cudaGetSymbolAddress((void**)&t0,   g_t0);
    cudaGetSymbolAddress((void**)&aln,  g_attnln);
    cudaGetSymbolAddress((void**)&bqkv, g_bqkv);

    __nv_bfloat16 *xhi, *xlo, *qkvhi, *qkvlo, *chi, *clo, *ahi, *alo, *fhi, *flo;
    cudaGetSymbolAddress((void**)&xhi,   g_xhi);
    cudaGetSymbolAddress((void**)&xlo,   g_xlo);
    cudaGetSymbolAddress((void**)&qkvhi, g_qkvhi);
    cudaGetSymbolAddress((void**)&qkvlo, g_qkvlo);
    cudaGetSymbolAddress((void**)&chi,   g_chi);
    cudaGetSymbolAddress((void**)&clo,   g_clo);
    cudaGetSymbolAddress((void**)&ahi,   g_ahi);
    cudaGetSymbolAddress((void**)&alo,   g_alo);
    cudaGetSymbolAddress((void**)&fhi,   g_fhi);
    cudaGetSymbolAddress((void**)&flo,   g_flo);

    __nv_bfloat16 *wqkvh, *wqkvl, *woh, *wol, *w1h, *w1l, *w2h, *w2l;
    cudaGetSymbolAddress((void**)&wqkvh, g_wqkvhi);
    cudaGetSymbolAddress((void**)&wqkvl, g_wqkvlo);
    cudaGetSymbolAddress((void**)&woh,   g_wohi);
    cudaGetSymbolAddress((void**)&wol,   g_wolo);
    cudaGetSymbolAddress((void**)&w1h,   g_w1hi);
    cudaGetSymbolAddress((void**)&w1l,   g_w1lo);
    cudaGetSymbolAddress((void**)&w2h,   g_w2hi);
    cudaGetSymbolAddress((void**)&w2l,   g_w2lo);

    cudaFuncSetAttribute(attn_mma,
                         cudaFuncAttributeMaxDynamicSharedMemorySize, AT_SMEM);
    cudaFuncSetAttribute(gemm_mma,
                         cudaFuncAttributeMaxDynamicSharedMemorySize, GM_SMEM_BYTES);

    dim3 tb(32, 8);

    // weight transpose + split (QKV concatenated)
    tsplit_kernel<<<dim3(DMODEL / 32, DMODEL / 32), tb>>>(Wq, wqkvh, wqkvl, DMODEL, DMODEL, 0);
    tsplit_kernel<<<dim3(DMODEL / 32, DMODEL / 32), tb>>>(Wk, wqkvh, wqkvl, DMODEL, DMODEL, 512);
    tsplit_kernel<<<dim3(DMODEL / 32, DMODEL / 32), tb>>>(Wv, wqkvh, wqkvl, DMODEL, DMODEL, 1024);
    tsplit_kernel<<<dim3(DMODEL / 32, DMODEL / 32), tb>>>(Wo, woh, wol, DMODEL, DMODEL, 0);
    tsplit_kernel<<<dim3(DFF / 32, DMODEL / 32), tb>>>(W1, w1h, w1l, DMODEL, DFF, 0);
    tsplit_kernel<<<dim3(DMODEL / 32, DFF / 32), tb>>>(W2, w2h, w2l, DFF, DMODEL, 0);
    concat_bias_kernel<<<6, 256>>>(bq, bk, bv, bqkv);

    // split input x
    {
        int n4 = MTOK * DMODEL / 4;
        split_kernel<<<(n4 + 255) / 256, 256>>>(x, xhi, xlo, n4);
    }

    // fused QKV projection -> combined bf16 hi/lo, stride 1536
    {
        dim3 grid(QS / 64, MTOK / 128);
        gemm_mma<<<grid, 256, GM_SMEM_BYTES>>>(xhi, xlo, wqkvh, wqkvl, bqkv,
                                               nullptr, qkvhi, qkvlo,
                                               MTOK, QS, DMODEL, 0);
    }

    // attention -> ctx bf16 hi/lo
    {
        dim3 grid(SEQ / 64, NHEADS, BATCH);
        attn_mma<<<grid, 256, AT_SMEM>>>(qkvhi, qkvlo,
                                         qkvhi + 512, qkvlo + 512,
                                         qkvhi + 1024, qkvlo + 1024,
                                         mask, chi, clo);
    }

    // output projection + residual LN
    {
        dim3 grid(DMODEL / 64, MTOK / 128);
        gemm_mma<<<grid, 256, GM_SMEM_BYTES>>>(chi, clo, woh, wol, bo,
                                               t0, nullptr, nullptr,
                                               MTOK, DMODEL, DMODEL, 0);
        ln_residual_kernel<<<MTOK, 256>>>(t0, x, ln1g, ln1b, aln, ahi, alo);
    }

    // FFN
    {
        dim3 grid1(DFF / 64, MTOK / 128);
        gemm_mma<<<grid1, 256, GM_SMEM_BYTES>>>(ahi, alo, w1h, w1l, b1,
                                                nullptr, fhi, flo,
                                                MTOK, DFF, DMODEL, 1);
        dim3 grid2(DMODEL / 64, MTOK / 128);
        gemm_mma<<<grid2, 256, GM_SMEM_BYTES>>>(fhi, flo, w2h, w2l, b2,
                                                t0, nullptr, nullptr,
                                                MTOK, DMODEL, DFF, 0);
        ln_residual_kernel<<<MTOK, 256>>>(t0, aln, ln2g, ln2b, out,
                                          nullptr, nullptr);
    }
}

// round 10
// speedup vs baseline: 1.0523x; 1.0283x over previous
#include <cuda_runtime.h>
#include <cuda_bf16.h>
#include <math.h>
#include <stdint.h>

// ---------------------------------------------------------------------------
// Problem dims (fixed)
// ---------------------------------------------------------------------------
#define BATCH   32
#define SEQ     512
#define DMODEL  512
#define NHEADS  8
#define HDIM    64
#define DFF     2048
#define MTOK    (BATCH * SEQ)
#define LN_EPS  1e-12f

// ---------------------------------------------------------------------------
// Scratch (device globals)
// ---------------------------------------------------------------------------
__device__ float g_t0[MTOK * DMODEL];
__device__ float g_attnln[MTOK * DMODEL];

__device__ __nv_bfloat16 g_xhi[MTOK * DMODEL];
__device__ __nv_bfloat16 g_xlo[MTOK * DMODEL];
__device__ __nv_bfloat16 g_qhi[MTOK * DMODEL];
__device__ __nv_bfloat16 g_qlo[MTOK * DMODEL];
__device__ __nv_bfloat16 g_khi[MTOK * DMODEL];
__device__ __nv_bfloat16 g_klo[MTOK * DMODEL];
__device__ __nv_bfloat16 g_vhi[MTOK * DMODEL];
__device__ __nv_bfloat16 g_vlo[MTOK * DMODEL];
__device__ __nv_bfloat16 g_chi[MTOK * DMODEL];
__device__ __nv_bfloat16 g_clo[MTOK * DMODEL];
__device__ __nv_bfloat16 g_ahi[MTOK * DMODEL];
__device__ __nv_bfloat16 g_alo[MTOK * DMODEL];
__device__ __nv_bfloat16 g_fhi[MTOK * DFF];
__device__ __nv_bfloat16 g_flo[MTOK * DFF];

__device__ __nv_bfloat16 g_wqhi[DMODEL * DMODEL];
__device__ __nv_bfloat16 g_wqlo[DMODEL * DMODEL];
__device__ __nv_bfloat16 g_wkhi[DMODEL * DMODEL];
__device__ __nv_bfloat16 g_wklo[DMODEL * DMODEL];
__device__ __nv_bfloat16 g_wvhi[DMODEL * DMODEL];
__device__ __nv_bfloat16 g_wvlo[DMODEL * DMODEL];
__device__ __nv_bfloat16 g_wohi[DMODEL * DMODEL];
__device__ __nv_bfloat16 g_wolo[DMODEL * DMODEL];
__device__ __nv_bfloat16 g_w1hi[DFF * DMODEL];
__device__ __nv_bfloat16 g_w1lo[DFF * DMODEL];
__device__ __nv_bfloat16 g_w2hi[DMODEL * DFF];
__device__ __nv_bfloat16 g_w2lo[DMODEL * DFF];

// ---------------------------------------------------------------------------
// helpers
// ---------------------------------------------------------------------------
__device__ __forceinline__ void mma16816(float* c, const uint32_t* a, const uint32_t* b)
{
    asm volatile(
        "mma.sync.aligned.m16n8k16.row.col.f32.bf16.bf16.f32 "
        "{%0,%1,%2,%3}, {%4,%5,%6,%7}, {%8,%9}, {%0,%1,%2,%3};"
        : "+f"(c[0]), "+f"(c[1]), "+f"(c[2]), "+f"(c[3])
        : "r"(a[0]), "r"(a[1]), "r"(a[2]), "r"(a[3]), "r"(b[0]), "r"(b[1]));
}

__device__ __forceinline__ uint32_t smem_u32(const void* p) {
    uint32_t a;
    asm("{ .reg .u64 t; cvta.to.shared.u64 t, %1; cvt.u32.u64 %0, t; }"
        : "=r"(a) : "l"(p));
    return a;
}

__device__ __forceinline__ void cp16(uint32_t dst, const void* src) {
    asm volatile("cp.async.cg.shared.global [%0], [%1], 16;"
                 :: "r"(dst), "l"(src));
}
__device__ __forceinline__ void cp_commit() {
    asm volatile("cp.async.commit_group;" ::: "memory");
}
template <int N>
__device__ __forceinline__ void cp_wait() {
    asm volatile("cp.async.wait_group %0;" :: "n"(N) : "memory");
}

__device__ __forceinline__ float fast_exp(float x) {
    float y = fmaxf(x * 1.4426950408889634f, -120.0f);
    float n = rintf(y);
    float f = y - n;
    float p = 1.3333558e-3f;
    p = fmaf(p, f, 9.6181291e-3f);
    p = fmaf(p, f, 5.5504109e-2f);
    p = fmaf(p, f, 2.4022651e-1f);
    p = fmaf(p, f, 6.9314718e-1f);
    p = fmaf(p, f, 1.0f);
    return p * __int_as_float(((int)n + 127) << 23);
}

__device__ __forceinline__ void split1(float v, unsigned short& h, unsigned short& l) {
    __nv_bfloat16 hb = __float2bfloat16_rn(v);
    float r = v - __bfloat162float(hb);
    __nv_bfloat16 lb = __float2bfloat16_rn(r);
    h = __bfloat16_as_ushort(hb);
    l = __bfloat16_as_ushort(lb);
}
__device__ __forceinline__ uint32_t pack2(unsigned short a, unsigned short b) {
    return (uint32_t)a | ((uint32_t)b << 16);
}

// ---------------------------------------------------------------------------
// prep kernels
// ---------------------------------------------------------------------------
__global__ void split_kernel(const float* __restrict__ X,
                             __nv_bfloat16* __restrict__ hi,
                             __nv_bfloat16* __restrict__ lo, int n4)
{
    int i = blockIdx.x * blockDim.x + threadIdx.x;
    if (i >= n4) return;
    float4 x = ((const float4*)X)[i];
    unsigned short h0, h1, h2, h3, l0, l1, l2, l3;
    split1(x.x, h0, l0); split1(x.y, h1, l1);
    split1(x.z, h2, l2); split1(x.w, h3, l3);
    uint2 hv, lv;
    hv.x = pack2(h0, h1); hv.y = pack2(h2, h3);
    lv.x = pack2(l0, l1); lv.y = pack2(l2, l3);
    ((uint2*)hi)[i] = hv;
    ((uint2*)lo)[i] = lv;
}

// Transpose + split: W[K][N] fp32 -> hi/lo [N][K] bf16
__global__ void tsplit_kernel(const float* __restrict__ W,
                              __nv_bfloat16* __restrict__ hi,
                              __nv_bfloat16* __restrict__ lo,
                              int K, int N)
{
    __shared__ float tile[32][33];
    const int n0 = blockIdx.x * 32, k0 = blockIdx.y * 32;
    const int tx = threadIdx.x, ty = threadIdx.y;
#pragma unroll
    for (int i = 0; i < 32; i += 8)
        tile[ty + i][tx] = W[(size_t)(k0 + ty + i) * N + n0 + tx];
    __syncthreads();
#pragma unroll
    for (int i = 0; i < 32; i += 8) {
        float v = tile[tx][ty + i];
        unsigned short h, l;
        split1(v, h, l);
        size_t o = (size_t)(n0 + ty + i) * K + k0 + tx;
        hi[o] = __ushort_as_bfloat16(h);
        lo[o] = __ushort_as_bfloat16(l);
    }
}

// ---------------------------------------------------------------------------
// Pipelined tensor-core split-GEMM (round-7 proven config).
// CTA 128x64, k-tile 32, 2-stage cp.async, 60 KB smem -> 3 CTA/SM.
// ---------------------------------------------------------------------------
#define SA2 40
#define ST2_A (128 * SA2)
#define ST2_B (64 * SA2)
#define STAGE2 (2 * ST2_A + 2 * ST2_B)
#define GM_SMEM_BYTES (2 * STAGE2 * 2)

__global__ __launch_bounds__(256)
void gemm_mma(const __nv_bfloat16* __restrict__ Ahi,
              const __nv_bfloat16* __restrict__ Alo,
              const __nv_bfloat16* __restrict__ Bhi,
              const __nv_bfloat16* __restrict__ Blo,
              const float* __restrict__ bias,
              float* __restrict__ Cf,
              __nv_bfloat16* __restrict__ Chi,
              __nv_bfloat16* __restrict__ Clo,
              int M, int N, int K, int do_gelu)
{
    extern __shared__ __nv_bfloat16 smb[];
    const uint32_t sm_base = smem_u32(smb);

    const int tid = threadIdx.x;
    const int wid = tid >> 5;
    const int lid = tid & 31;
    const int gID = lid >> 2;
    const int t4  = lid & 3;

    const int row0 = blockIdx.y * 128;
    const int col0 = blockIdx.x * 64;
    const int m_off = (wid & 3) * 32;
    const int n_off = (wid >> 2) * 32;

    auto load_stage = [&](int buf, int t) {
        const int kb = t << 5;
        uint32_t base = sm_base + (uint32_t)buf * (STAGE2 * 2);
#pragma unroll
        for (int i = 0; i < 2; i++) {
            int e = tid + i * 256;
            int r = e >> 2, g = e & 3;
            uint32_t ds = (uint32_t)(r * SA2 + g * 8) * 2;
            size_t src = (size_t)(row0 + r) * K + kb + g * 8;
            cp16(base + ds, Ahi + src);
            cp16(base + ST2_A * 2 + ds, Alo + src);
        }
        {
            int r = tid >> 2, g = tid & 3;
            uint32_t ds = (uint32_t)(r * SA2 + g * 8) * 2;
            size_t src = (size_t)(col0 + r) * K + kb + g * 8;
            cp16(base + 2 * ST2_A * 2 + ds, Bhi + src);
            cp16(base + 2 * ST2_A * 2 + ST2_B * 2 + ds, Blo + src);
        }
        cp_commit();
    };

    float acc[2][4][4];
#pragma unroll
    for (int mi = 0; mi < 2; mi++)
#pragma unroll
        for (int ni = 0; ni < 4; ni++)
#pragma unroll
            for (int j = 0; j < 4; j++) acc[mi][ni][j] = 0.f;

    const int nT = K >> 5;
    load_stage(0, 0);

    for (int t = 0; t < nT; t++) {
        const int buf = t & 1;
        if (t + 1 < nT) {
            load_stage(1 - buf, t + 1);
            cp_wait<1>();
        } else {
            cp_wait<0>();
        }
        __syncthreads();

        const __nv_bfloat16* As_hi = smb + buf * STAGE2;
        const __nv_bfloat16* As_lo = As_hi + ST2_A;
        const __nv_bfloat16* Bs_hi = As_hi + 2 * ST2_A;
        const __nv_bfloat16* Bs_lo = Bs_hi + ST2_B;

#pragma unroll
        for (int kk = 0; kk < 32; kk += 16) {
            uint32_t ahi[2][4], alo[2][4], bhi[4][2], blo[4][2];
#pragma unroll
            for (int mi = 0; mi < 2; mi++) {
                int r = m_off + mi * 16 + gID;
                int base0 = r * SA2 + kk + t4 * 2;
                int base1 = (r + 8) * SA2 + kk + t4 * 2;
                ahi[mi][0] = *(const uint32_t*)&As_hi[base0];
                ahi[mi][1] = *(const uint32_t*)&As_hi[base1];
                ahi[mi][2] = *(const uint32_t*)&As_hi[base0 + 8];
                ahi[mi][3] = *(const uint32_t*)&As_hi[base1 + 8];
                alo[mi][0] = *(const uint32_t*)&As_lo[base0];
                alo[mi][1] = *(const uint32_t*)&As_lo[base1];
                alo[mi][2] = *(const uint32_t*)&As_lo[base0 + 8];
                alo[mi][3] = *(const uint32_t*)&As_lo[base1 + 8];
            }
#pragma unroll
            for (int ni = 0; ni < 4; ni++) {
                int n = n_off + ni * 8 + gID;
                int base = n * SA2 + kk + t4 * 2;
                bhi[ni][0] = *(const uint32_t*)&Bs_hi[base];
                bhi[ni][1] = *(const uint32_t*)&Bs_hi[base + 8];
                blo[ni][0] = *(const uint32_t*)&Bs_lo[base];
                blo[ni][1] = *(const uint32_t*)&Bs_lo[base + 8];
            }
#pragma unroll
            for (int mi = 0; mi < 2; mi++)
#pragma unroll
                for (int ni = 0; ni < 4; ni++) {
                    mma16816(acc[mi][ni], ahi[mi], bhi[ni]);
                    mma16816(acc[mi][ni], alo[mi], bhi[ni]);
                    mma16816(acc[mi][ni], ahi[mi], blo[ni]);
                }
        }
        __syncthreads();
    }

    // ---- epilogue ----
#pragma unroll
    for (int mi = 0; mi < 2; mi++) {
#pragma unroll
        for (int ni = 0; ni < 4; ni++) {
            int col = col0 + n_off + ni * 8 + t4 * 2;
            float b0 = bias[col], b1 = bias[col + 1];
#pragma unroll
            for (int half = 0; half < 2; half++) {
                int row = row0 + m_off + mi * 16 + gID + half * 8;
                float v0 = acc[mi][ni][half * 2 + 0] + b0;
                float v1 = acc[mi][ni][half * 2 + 1] + b1;
                if (do_gelu) {
                    v0 = 0.5f * v0 * (1.0f + erff(v0 * 0.70710678118654752f));
                    v1 = 0.5f * v1 * (1.0f + erff(v1 * 0.70710678118654752f));
                }
                size_t o = (size_t)row * N + col;
                if (Cf) {
                    float2 fo; fo.x = v0; fo.y = v1;
                    *(float2*)(Cf + o) = fo;
                }
                if (Chi) {
                    unsigned short h0, h1, l0, l1;
                    split1(v0, h0, l0);
                    split1(v1, h1, l1);
                    *(uint32_t*)(Chi + o) = pack2(h0, h1);
                    *(uint32_t*)(Clo + o) = pack2(l0, l1);
                }
            }
        }
    }
}

// ---------------------------------------------------------------------------
// Tensor-core attention (round-7 base) + phase-3 V cp.async staging.
// ---------------------------------------------------------------------------
#define AT_SA   72
#define AT_QHI  0
#define AT_QLO  9216
#define AT_K0   18432
#define AT_SV   36864                 // V staging (reuses phase-1 K buf1)
#define AT_PHI  55296
#define AT_PLO  64512
#define AT_SS   73728
#define AT_INV  (AT_SS + 64 * 512 * 4)
#define AT_SMEM (AT_INV + 256)

__global__ __launch_bounds__(256)
void attn_mma(const __nv_bfloat16* __restrict__ Qhi_g,
              const __nv_bfloat16* __restrict__ Qlo_g,
              const __nv_bfloat16* __restrict__ Khi_g,
              const __nv_bfloat16* __restrict__ Klo_g,
              const __nv_bfloat16* __restrict__ Vhi_g,
              const __nv_bfloat16* __restrict__ Vlo_g,
              const float* __restrict__ mask,
              __nv_bfloat16* __restrict__ Chi_g,
              __nv_bfloat16* __restrict__ Clo_g)
{
    extern __shared__ char smc[];
    const uint32_t sm_base = smem_u32(smc);
    __nv_bfloat16* Qhi = (__nv_bfloat16*)(smc + AT_QHI);
    __nv_bfloat16* Qlo = (__nv_bfloat16*)(smc + AT_QLO);
    __nv_bfloat16* Phi = (__nv_bfloat16*)(smc + AT_PHI);
    __nv_bfloat16* Plo = (__nv_bfloat16*)(smc + AT_PLO);
    float* Ss   = (float*)(smc + AT_SS);
    float* invs = (float*)(smc + AT_INV);

    const int tid = threadIdx.x;
    const int wid = tid >> 5, lid = tid & 31;
    const int gID = lid >> 2, t4 = lid & 3;
    const int wm = wid & 3, wn = wid >> 2;
    const int q0 = blockIdx.x * 64;
    const int h = blockIdx.y, b = blockIdx.z;
    const size_t hb = ((size_t)b * SEQ) * DMODEL + (size_t)h * HDIM;
    const float* mbase = mask + (size_t)b * SEQ * SEQ;

    auto load_k = [&](int bb, int kc) {
        const int k0 = kc * 64;
        uint32_t kh = sm_base + AT_K0 + (uint32_t)bb * 18432;
        uint32_t kl = kh + 9216;
#pragma unroll
        for (int i = 0; i < 2; i++) {
            int e = tid + i * 256;
            int r = e >> 3, g = e & 7;
            size_t src = hb + (size_t)(k0 + r) * DMODEL + g * 8;
            uint32_t ds = (uint32_t)(r * AT_SA + g * 8) * 2;
            cp16(kh + ds, Khi_g + src);
            cp16(kl + ds, Klo_g + src);
        }
        cp_commit();
    };

    // stage V chunk row-major (64 rows x 64 bf16, hi + lo) into AT_SV
    auto stage_v = [&](int kc) {
        const int k0 = kc * 64;
        uint32_t sv = sm_base + AT_SV;
#pragma unroll
        for (int i = 0; i < 2; i++) {
            int e = tid + i * 256;
            int r = e >> 3, g = e & 7;
            size_t src = hb + (size_t)(k0 + r) * DMODEL + g * 8;
            uint32_t ds = (uint32_t)(r * 64 + g * 8) * 2;
            cp16(sv + ds, Vhi_g + src);
            cp16(sv + 8192 + ds, Vlo_g + src);
        }
        cp_commit();
    };

    load_k(0, 0);

    // load Q tile
#pragma unroll
    for (int i = 0; i < 2; i++) {
        int e = tid + i * 256;
        int r = e >> 3, g = e & 7;
        size_t src = hb + (size_t)(q0 + r) * DMODEL + g * 8;
        int ds = r * AT_SA + g * 8;
        *(uint4*)(Qhi + ds) = *(const uint4*)(Qhi_g + src);
        *(uint4*)(Qlo + ds) = *(const uint4*)(Qlo_g + src);
    }

    float pv[4][4];
#pragma unroll
    for (int ni = 0; ni < 4; ni++)
#pragma unroll
        for (int j = 0; j < 4; j++) pv[ni][j] = 0.f;

    // ---- phase 1: scores (pipelined K) ----
    for (int kc = 0; kc < 8; kc++) {
        const int k0 = kc * 64;
        if (kc + 1 < 8) {
            load_k((kc + 1) & 1, kc + 1);
            cp_wait<1>();
        } else {
            cp_wait<0>();
        }
        __syncthreads();

        const __nv_bfloat16* Khi = (const __nv_bfloat16*)(smc + AT_K0 + (kc & 1) * 18432);
        const __nv_bfloat16* Klo = Khi + 4608;

        float s[4][4];
#pragma unroll
        for (int ni = 0; ni < 4; ni++)
#pragma unroll
            for (int j = 0; j < 4; j++) s[ni][j] = 0.f;

#pragma unroll
        for (int kk = 0; kk < 64; kk += 16) {
            uint32_t ah[4], al[4];
            int rb0 = (wm * 16 + gID) * AT_SA + kk + t4 * 2;
            int rb1 = rb0 + 8 * AT_SA;
            ah[0] = *(const uint32_t*)&Qhi[rb0];
            ah[1] = *(const uint32_t*)&Qhi[rb1];
            ah[2] = *(const uint32_t*)&Qhi[rb0 + 8];
            ah[3] = *(const uint32_t*)&Qhi[rb1 + 8];
            al[0] = *(const uint32_t*)&Qlo[rb0];
            al[1] = *(const uint32_t*)&Qlo[rb1];
            al[2] = *(const uint32_t*)&Qlo[rb0 + 8];
            al[3] = *(const uint32_t*)&Qlo[rb1 + 8];
#pragma unroll
            for (int ni = 0; ni < 4; ni++) {
                int nb = (wn * 32 + ni * 8 + gID) * AT_SA + kk + t4 * 2;
                uint32_t bh[2], bl[2];
                bh[0] = *(const uint32_t*)&Khi[nb];
                bh[1] = *(const uint32_t*)&Khi[nb + 8];
                bl[0] = *(const uint32_t*)&Klo[nb];
                bl[1] = *(const uint32_t*)&Klo[nb + 8];
                mma16816(s[ni], ah, bh);
                mma16816(s[ni], al, bh);
                mma16816(s[ni], ah, bl);
            }
        }
#pragma unroll
        for (int ni = 0; ni < 4; ni++) {
            int col = k0 + wn * 32 + ni * 8 + t4 * 2;
#pragma unroll
            for (int hf = 0; hf < 2; hf++) {
                int row = wm * 16 + gID + hf * 8;
                float2 m2 = *(const float2*)(mbase + (size_t)(q0 + row) * SEQ + col);
                float2 o;
                o.x = s[ni][hf * 2 + 0] * 0.125f + m2.x;
                o.y = s[ni][hf * 2 + 1] * 0.125f + m2.y;
                *(float2*)(Ss + row * 512 + col) = o;
            }
        }
        __syncthreads();
    }

    // prefetch V chunk 0 while softmax runs (buf1 region is now free)
    stage_v(0);

    // ---- phase 2: softmax ----
    {
#pragma unroll
        for (int rr = 0; rr < 8; rr++) {
            int r = wid * 8 + rr;
            float* row = Ss + r * 512;
            float4 v[4];
#pragma unroll
            for (int it = 0; it < 4; it++)
                v[it] = *(float4*)(row + it * 128 + lid * 4);
            float m = -1e30f;
#pragma unroll
            for (int it = 0; it < 4; it++)
                m = fmaxf(m, fmaxf(fmaxf(v[it].x, v[it].y), fmaxf(v[it].z, v[it].w)));
#pragma unroll
            for (int off = 16; off; off >>= 1)
                m = fmaxf(m, __shfl_xor_sync(0xffffffffu, m, off));
            float sum = 0.f;
#pragma unroll
            for (int it = 0; it < 4; it++) {
                v[it].x = fast_exp(v[it].x - m);
                v[it].y = fast_exp(v[it].y - m);
                v[it].z = fast_exp(v[it].z - m);
                v[it].w = fast_exp(v[it].w - m);
                sum += v[it].x + v[it].y + v[it].z + v[it].w;
                *(float4*)(row + it * 128 + lid * 4) = v[it];
            }
#pragma unroll
            for (int off = 16; off; off >>= 1)
                sum += __shfl_xor_sync(0xffffffffu, sum, off);
            if (lid == 0) invs[r] = 1.0f / sum;
        }
    }

    // ---- phase 3: P @ V, V staged via cp.async ----
    __nv_bfloat16* Vth = (__nv_bfloat16*)(smc + AT_K0);
    __nv_bfloat16* Vtl = Vth + 4608;
    const __nv_bfloat16* Svh = (const __nv_bfloat16*)(smc + AT_SV);
    const __nv_bfloat16* Svl = Svh + 4096;
    for (int kc = 0; kc < 8; kc++) {
        const int k0 = kc * 64;
        cp_wait<0>();
        __syncthreads();

        // P chunk: normalize + split
        {
            int r = tid >> 2, c0 = (tid & 3) * 16;
            float is = invs[r];
#pragma unroll
            for (int j2 = 0; j2 < 2; j2++) {
                const float* src = Ss + r * 512 + k0 + c0 + j2 * 8;
                float4 a = *(const float4*)(src);
                float4 bq = *(const float4*)(src + 4);
                float vals[8] = {a.x * is, a.y * is, a.z * is, a.w * is,
                                 bq.x * is, bq.y * is, bq.z * is, bq.w * is};
                unsigned short hh[8], ll[8];
#pragma unroll
                for (int j = 0; j < 8; j++) split1(vals[j], hh[j], ll[j]);
                uint4 hv, lv;
                hv.x = pack2(hh[0], hh[1]); hv.y = pack2(hh[2], hh[3]);
                hv.z = pack2(hh[4], hh[5]); hv.w = pack2(hh[6], hh[7]);
                lv.x = pack2(ll[0], ll[1]); lv.y = pack2(ll[2], ll[3]);
                lv.z = pack2(ll[4], ll[5]); lv.w = pack2(ll[6], ll[7]);
                *(uint4*)(Phi + r * AT_SA + c0 + j2 * 8) = hv;
                *(uint4*)(Plo + r * AT_SA + c0 + j2 * 8) = lv;
            }
        }

        // V chunk: transpose from staging smem
#pragma unroll
        for (int i = 0; i < 4; i++) {
            int e = tid + i * 256;
            int r = e >> 4, c4 = e & 15;
            uint2 hv = *(const uint2*)(Svh + r * 64 + c4 * 4);
            uint2 lv = *(const uint2*)(Svl + r * 64 + c4 * 4);
            int d = c4 * 4;
            Vth[(d + 0) * AT_SA + r] = __ushort_as_bfloat16((unsigned short)(hv.x & 0xffff));
            Vth[(d + 1) * AT_SA + r] = __ushort_as_bfloat16((unsigned short)(hv.x >> 16));
            Vth[(d + 2) * AT_SA + r] = __ushort_as_bfloat16((unsigned short)(hv.y & 0xffff));
            Vth[(d + 3) * AT_SA + r] = __ushort_as_bfloat16((unsigned short)(hv.y >> 16));
            Vtl[(d + 0) * AT_SA + r] = __ushort_as_bfloat16((unsigned short)(lv.x & 0xffff));
            Vtl[(d + 1) * AT_SA + r] = __ushort_as_bfloat16((unsigned short)(lv.x >> 16));
            Vtl[(d + 2) * AT_SA + r] = __ushort_as_bfloat16((unsigned short)(lv.y & 0xffff));
            Vtl[(d + 3) * AT_SA + r] = __ushort_as_bfloat16((unsigned short)(lv.y >> 16));
        }
        __syncthreads();

        // prefetch next V chunk while MMAs run
        if (kc + 1 < 8) stage_v(kc + 1);

#pragma unroll
        for (int kk = 0; kk < 64; kk += 16) {
            uint32_t ah[4], al[4];
            int rb0 = (wm * 16 + gID) * AT_SA + kk + t4 * 2;
            int rb1 = rb0 + 8 * AT_SA;
            ah[0] = *(const uint32_t*)&Phi[rb0];
            ah[1] = *(const uint32_t*)&Phi[rb1];
            ah[2] = *(const uint32_t*)&Phi[rb0 + 8];
            ah[3] = *(const uint32_t*)&Phi[rb1 + 8];
            al[0] = *(const uint32_t*)&Plo[rb0];
            al[1] = *(const uint32_t*)&Plo[rb1];
            al[2] = *(const uint32_t*)&Plo[rb0 + 8];
            al[3] = *(const uint32_t*)&Plo[rb1 + 8];
#pragma unroll
            for (int ni = 0; ni < 4; ni++) {
                int nb = (wn * 32 + ni * 8 + gID) * AT_SA + kk + t4 * 2;
                uint32_t bh[2], bl[2];
                bh[0] = *(const uint32_t*)&Vth[nb];
                bh[1] = *(const uint32_t*)&Vth[nb + 8];
                bl[0] = *(const uint32_t*)&Vtl[nb];
                bl[1] = *(const uint32_t*)&Vtl[nb + 8];
                mma16816(pv[ni], ah, bh);
                mma16816(pv[ni], al, bh);
                mma16816(pv[ni], ah, bl);
            }
        }
    }

    // ---- write ctx as bf16 hi/lo ----
#pragma unroll
    for (int ni = 0; ni < 4; ni++) {
        int d = wn * 32 + ni * 8 + t4 * 2;
#pragma unroll
        for (int hf = 0; hf < 2; hf++) {
            int row = wm * 16 + gID + hf * 8;
            unsigned short h0, h1, l0, l1;
            split1(pv[ni][hf * 2 + 0], h0, l0);
            split1(pv[ni][hf * 2 + 1], h1, l1);
            size_t o = hb + (size_t)(q0 + row) * DMODEL + d;
            *(uint32_t*)(Chi_g + o) = pack2(h0, h1);
            *(uint32_t*)(Clo_g + o) = pack2(l0, l1);
        }
    }
}

// ---------------------------------------------------------------------------
// LayerNorm + residual: warp per row, shuffle-only reductions.
// Optional bf16 hi/lo side outputs. grid = MTOK/8, block = 256 (8 warps).
// ---------------------------------------------------------------------------
__global__ __launch_bounds__(256)
void ln_residual_kernel(const float* __restrict__ y,
                        const float* __restrict__ res,
                        const float* __restrict__ g,
                        const float* __restrict__ bta,
                        float* __restrict__ out,
                        __nv_bfloat16* __restrict__ ohi,
                        __nv_bfloat16* __restrict__ olo)
{
    const int warp = threadIdx.x >> 5;
    const int lane = threadIdx.x & 31;
    const int row  = blockIdx.x * 8 + warp;
    const size_t base = (size_t)row * DMODEL;

    float4 v[4];
    float sum = 0.f;
#pragma unroll
    for (int it = 0; it < 4; it++) {
        int c = lane * 4 + it * 128;
        float4 a = *(const float4*)(y + base + c);
        float4 bb = *(const float4*)(res + base + c);
        v[it].x = a.x + bb.x; v[it].y = a.y + bb.y;
        v[it].z = a.z + bb.z; v[it].w = a.w + bb.w;
        sum += v[it].x + v[it].y + v[it].z + v[it].w;
    }
#pragma unroll
    for (int off = 16; off; off >>= 1)
        sum += __shfl_xor_sync(0xffffffffu, sum, off);
    float mean = sum * (1.0f / 512.0f);

    float var = 0.f;
#pragma unroll
    for (int it = 0; it < 4; it++) {
        v[it].x -= mean; v[it].y -= mean; v[it].z -= mean; v[it].w -= mean;
        var += v[it].x * v[it].x + v[it].y * v[it].y
             + v[it].z * v[it].z + v[it].w * v[it].w;
    }
#pragma unroll
    for (int off = 16; off; off >>= 1)
        var += __shfl_xor_sync(0xffffffffu, var, off);
    float inv = rsqrtf(var * (1.0f / 512.0f) + LN_EPS);

#pragma unroll
    for (int it = 0; it < 4; it++) {
        int c = lane * 4 + it * 128;
        float4 gg = *(const float4*)(g + c);
        float4 bb = *(const float4*)(bta + c);
        float4 o;
        o.x = v[it].x * inv * gg.x + bb.x;
        o.y = v[it].y * inv * gg.y + bb.y;
        o.z = v[it].z * inv * gg.z + bb.z;
        o.w = v[it].w * inv * gg.w + bb.w;
        *(float4*)(out + base + c) = o;
        if (ohi) {
            unsigned short h0, h1, h2, h3, l0, l1, l2, l3;
            split1(o.x, h0, l0); split1(o.y, h1, l1);
            split1(o.z, h2, l2); split1(o.w, h3, l3);
            uint2 hv, lv;
            hv.x = pack2(h0, h1); hv.y = pack2(h2, h3);
            lv.x = pack2(l0, l1); lv.y = pack2(l2, l3);
            *(uint2*)(ohi + base + c) = hv;
            *(uint2*)(olo + base + c) = lv;
        }
    }
}

// ---------------------------------------------------------------------------
// launch
// ---------------------------------------------------------------------------
extern "C" void kernel_launch(void* const* d_in, const int* in_sizes, int n_in,
                              void* d_out, int out_size)
{
    const float* x     = (const float*)d_in[0];
    const float* mask  = (const float*)d_in[1];
    const float* Wq    = (const float*)d_in[2];
    const float* bq    = (const float*)d_in[3];
    const float* Wk    = (const float*)d_in[4];
    const float* bk    = (const float*)d_in[5];
    const float* Wv    = (const float*)d_in[6];
    const float* bv    = (const float*)d_in[7];
    const float* Wo    = (const float*)d_in[8];
    const float* bo    = (const float*)d_in[9];
    const float* ln1g  = (const float*)d_in[10];
    const float* ln1b  = (const float*)d_in[11];
    const float* W1    = (const float*)d_in[12];
    const float* b1    = (const float*)d_in[13];
    const float* W2    = (const float*)d_in[14];
    const float* b2    = (const float*)d_in[15];
    const float* ln2g  = (const float*)d_in[16];
    const float* ln2b  = (const float*)d_in[17];
    float* out = (float*)d_out;

    float *t0, *aln;
    cudaGetSymbolAddress((void**)&t0,  g_t0);
    cudaGetSymbolAddress((void**)&aln, g_attnln);

    __nv_bfloat16 *xhi, *xlo, *qhi, *qlo, *khi, *klo, *vhi, *vlo;
    __nv_bfloat16 *chi, *clo, *ahi, *alo, *fhi, *flo;
    cudaGetSymbolAddress((void**)&xhi, g_xhi);
    cudaGetSymbolAddress((void**)&xlo, g_xlo);
    cudaGetSymbolAddress((void**)&qhi, g_qhi);
    cudaGetSymbolAddress((void**)&qlo, g_qlo);
    cudaGetSymbolAddress((void**)&khi, g_khi);
    cudaGetSymbolAddress((void**)&klo, g_klo);
    cudaGetSymbolAddress((void**)&vhi, g_vhi);
    cudaGetSymbolAddress((void**)&vlo, g_vlo);
    cudaGetSymbolAddress((void**)&chi, g_chi);
    cudaGetSymbolAddress((void**)&clo, g_clo);
    cudaGetSymbolAddress((void**)&ahi, g_ahi);
    cudaGetSymbolAddress((void**)&alo, g_alo);
    cudaGetSymbolAddress((void**)&fhi, g_fhi);
    cudaGetSymbolAddress((void**)&flo, g_flo);

    __nv_bfloat16 *wqh, *wql, *wkh, *wkl, *wvh, *wvl, *woh, *wol, *w1h, *w1l, *w2h, *w2l;
    cudaGetSymbolAddress((void**)&wqh, g_wqhi);
    cudaGetSymbolAddress((void**)&wql, g_wqlo);
    cudaGetSymbolAddress((void**)&wkh, g_wkhi);
    cudaGetSymbolAddress((void**)&wkl, g_wklo);
    cudaGetSymbolAddress((void**)&wvh, g_wvhi);
    cudaGetSymbolAddress((void**)&wvl, g_wvlo);
    cudaGetSymbolAddress((void**)&woh, g_wohi);
    cudaGetSymbolAddress((void**)&wol, g_wolo);
    cudaGetSymbolAddress((void**)&w1h, g_w1hi);
    cudaGetSymbolAddress((void**)&w1l, g_w1lo);
    cudaGetSymbolAddress((void**)&w2h, g_w2hi);
    cudaGetSymbolAddress((void**)&w2l, g_w2lo);

    cudaFuncSetAttribute(attn_mma,
                         cudaFuncAttributeMaxDynamicSharedMemorySize, AT_SMEM);
    cudaFuncSetAttribute(gemm_mma,
                         cudaFuncAttributeMaxDynamicSharedMemorySize, GM_SMEM_BYTES);

    dim3 tb(32, 8);

    // weight transpose + split
    tsplit_kernel<<<dim3(DMODEL / 32, DMODEL / 32), tb>>>(Wq, wqh, wql, DMODEL, DMODEL);
    tsplit_kernel<<<dim3(DMODEL / 32, DMODEL / 32), tb>>>(Wk, wkh, wkl, DMODEL, DMODEL);
    tsplit_kernel<<<dim3(DMODEL / 32, DMODEL / 32), tb>>>(Wv, wvh, wvl, DMODEL, DMODEL);
    tsplit_kernel<<<dim3(DMODEL / 32, DMODEL / 32), tb>>>(Wo, woh, wol, DMODEL, DMODEL);
    tsplit_kernel<<<dim3(DFF / 32, DMODEL / 32), tb>>>(W1, w1h, w1l, DMODEL, DFF);
    tsplit_kernel<<<dim3(DMODEL / 32, DFF / 32), tb>>>(W2, w2h, w2l, DFF, DMODEL);

    // split input x
    {
        int n4 = MTOK * DMODEL / 4;
        split_kernel<<<(n4 + 255) / 256, 256>>>(x, xhi, xlo, n4);
    }

    // QKV projections -> bf16 hi/lo directly
    {
        dim3 grid(DMODEL / 64, MTOK / 128);
        gemm_mma<<<grid, 256, GM_SMEM_BYTES>>>(xhi, xlo, wqh, wql, bq,
                                               nullptr, qhi, qlo,
                                               MTOK, DMODEL, DMODEL, 0);
        gemm_mma<<<grid, 256, GM_SMEM_BYTES>>>(xhi, xlo, wkh, wkl, bk,
                                               nullptr, khi, klo,
                                               MTOK, DMODEL, DMODEL, 0);
        gemm_mma<<<grid, 256, GM_SMEM_BYTES>>>(xhi, xlo, wvh, wvl, bv,
                                               nullptr, vhi, vlo,
                                               MTOK, DMODEL, DMODEL, 0);
    }

    // attention -> ctx bf16 hi/lo
    {
        dim3 grid(SEQ / 64, NHEADS, BATCH);
        attn_mma<<<grid, 256, AT_SMEM>>>(qhi, qlo, khi, klo, vhi, vlo,
                                         mask, chi, clo);
    }

    // output projection + residual LN
    {
        dim3 grid(DMODEL / 64, MTOK / 128);
        gemm_mma<<<grid, 256, GM_SMEM_BYTES>>>(chi, clo, woh, wol, bo,
                                               t0, nullptr, nullptr,
                                               MTOK, DMODEL, DMODEL, 0);
        ln_residual_kernel<<<MTOK / 8, 256>>>(t0, x, ln1g, ln1b, aln, ahi, alo);
    }

    // FFN
    {
        dim3 grid1(DFF / 64, MTOK / 128);
        gemm_mma<<<grid1, 256, GM_SMEM_BYTES>>>(ahi, alo, w1h, w1l, b1,
                                                nullptr, fhi, flo,
                                                MTOK, DFF, DMODEL, 1);
        dim3 grid2(DMODEL / 64, MTOK / 128);
        gemm_mma<<<grid2, 256, GM_SMEM_BYTES>>>(fhi, flo, w2h, w2l, b2,
                                                t0, nullptr, nullptr,
                                                MTOK, DMODEL, DFF, 0);
        ln_residual_kernel<<<MTOK / 8, 256>>>(t0, aln, ln2g, ln2b, out,
                                              nullptr, nullptr);
    }
}

// round 11
// speedup vs baseline: 1.0917x; 1.0374x over previous
#include <cuda_runtime.h>
#include <cuda_bf16.h>
#include <math.h>
#include <stdint.h>

// ---------------------------------------------------------------------------
// Problem dims (fixed)
// ---------------------------------------------------------------------------
#define BATCH   32
#define SEQ     512
#define DMODEL  512
#define NHEADS  8
#define HDIM    64
#define DFF     2048
#define MTOK    (BATCH * SEQ)
#define LN_EPS  1e-12f

// ---------------------------------------------------------------------------
// Scratch (device globals)
// ---------------------------------------------------------------------------
__device__ float g_t0[MTOK * DMODEL];
__device__ float g_attnln[MTOK * DMODEL];

__device__ __nv_bfloat16 g_xhi[MTOK * DMODEL];
__device__ __nv_bfloat16 g_xlo[MTOK * DMODEL];
__device__ __nv_bfloat16 g_qhi[MTOK * DMODEL];
__device__ __nv_bfloat16 g_qlo[MTOK * DMODEL];
__device__ __nv_bfloat16 g_khi[MTOK * DMODEL];
__device__ __nv_bfloat16 g_klo[MTOK * DMODEL];
__device__ __nv_bfloat16 g_vhi[MTOK * DMODEL];
__device__ __nv_bfloat16 g_vlo[MTOK * DMODEL];
__device__ __nv_bfloat16 g_chi[MTOK * DMODEL];
__device__ __nv_bfloat16 g_clo[MTOK * DMODEL];
__device__ __nv_bfloat16 g_ahi[MTOK * DMODEL];
__device__ __nv_bfloat16 g_alo[MTOK * DMODEL];
__device__ __nv_bfloat16 g_fhi[MTOK * DFF];
__device__ __nv_bfloat16 g_flo[MTOK * DFF];

__device__ __nv_bfloat16 g_wqhi[DMODEL * DMODEL];
__device__ __nv_bfloat16 g_wqlo[DMODEL * DMODEL];
__device__ __nv_bfloat16 g_wkhi[DMODEL * DMODEL];
__device__ __nv_bfloat16 g_wklo[DMODEL * DMODEL];
__device__ __nv_bfloat16 g_wvhi[DMODEL * DMODEL];
__device__ __nv_bfloat16 g_wvlo[DMODEL * DMODEL];
__device__ __nv_bfloat16 g_wohi[DMODEL * DMODEL];
__device__ __nv_bfloat16 g_wolo[DMODEL * DMODEL];
__device__ __nv_bfloat16 g_w1hi[DFF * DMODEL];
__device__ __nv_bfloat16 g_w1lo[DFF * DMODEL];
__device__ __nv_bfloat16 g_w2hi[DMODEL * DFF];
__device__ __nv_bfloat16 g_w2lo[DMODEL * DFF];

// ---------------------------------------------------------------------------
// helpers
// ---------------------------------------------------------------------------
__device__ __forceinline__ void mma16816(float* c, const uint32_t* a, const uint32_t* b)
{
    asm volatile(
        "mma.sync.aligned.m16n8k16.row.col.f32.bf16.bf16.f32 "
        "{%0,%1,%2,%3}, {%4,%5,%6,%7}, {%8,%9}, {%0,%1,%2,%3};"
        : "+f"(c[0]), "+f"(c[1]), "+f"(c[2]), "+f"(c[3])
        : "r"(a[0]), "r"(a[1]), "r"(a[2]), "r"(a[3]), "r"(b[0]), "r"(b[1]));
}

__device__ __forceinline__ void ldsm_x4(uint32_t* r, uint32_t addr)
{
    asm volatile(
        "ldmatrix.sync.aligned.m8n8.x4.shared.b16 {%0,%1,%2,%3}, [%4];"
        : "=r"(r[0]), "=r"(r[1]), "=r"(r[2]), "=r"(r[3]) : "r"(addr));
}

__device__ __forceinline__ uint32_t smem_u32(const void* p) {
    uint32_t a;
    asm("{ .reg .u64 t; cvta.to.shared.u64 t, %1; cvt.u32.u64 %0, t; }"
        : "=r"(a) : "l"(p));
    return a;
}

__device__ __forceinline__ void cp16(uint32_t dst, const void* src) {
    asm volatile("cp.async.cg.shared.global [%0], [%1], 16;"
                 :: "r"(dst), "l"(src));
}
__device__ __forceinline__ void cp_commit() {
    asm volatile("cp.async.commit_group;" ::: "memory");
}
template <int N>
__device__ __forceinline__ void cp_wait() {
    asm volatile("cp.async.wait_group %0;" :: "n"(N) : "memory");
}

__device__ __forceinline__ float fast_exp(float x) {
    float y = fmaxf(x * 1.4426950408889634f, -120.0f);
    float n = rintf(y);
    float f = y - n;
    float p = 1.3333558e-3f;
    p = fmaf(p, f, 9.6181291e-3f);
    p = fmaf(p, f, 5.5504109e-2f);
    p = fmaf(p, f, 2.4022651e-1f);
    p = fmaf(p, f, 6.9314718e-1f);
    p = fmaf(p, f, 1.0f);
    return p * __int_as_float(((int)n + 127) << 23);
}

__device__ __forceinline__ void split1(float v, unsigned short& h, unsigned short& l) {
    __nv_bfloat16 hb = __float2bfloat16_rn(v);
    float r = v - __bfloat162float(hb);
    __nv_bfloat16 lb = __float2bfloat16_rn(r);
    h = __bfloat16_as_ushort(hb);
    l = __bfloat16_as_ushort(lb);
}
__device__ __forceinline__ uint32_t pack2(unsigned short a, unsigned short b) {
    return (uint32_t)a | ((uint32_t)b << 16);
}

// ---------------------------------------------------------------------------
// prep kernels
// ---------------------------------------------------------------------------
__global__ void split_kernel(const float* __restrict__ X,
                             __nv_bfloat16* __restrict__ hi,
                             __nv_bfloat16* __restrict__ lo, int n4)
{
    int i = blockIdx.x * blockDim.x + threadIdx.x;
    if (i >= n4) return;
    float4 x = ((const float4*)X)[i];
    unsigned short h0, h1, h2, h3, l0, l1, l2, l3;
    split1(x.x, h0, l0); split1(x.y, h1, l1);
    split1(x.z, h2, l2); split1(x.w, h3, l3);
    uint2 hv, lv;
    hv.x = pack2(h0, h1); hv.y = pack2(h2, h3);
    lv.x = pack2(l0, l1); lv.y = pack2(l2, l3);
    ((uint2*)hi)[i] = hv;
    ((uint2*)lo)[i] = lv;
}

// Transpose + split: W[K][N] fp32 -> hi/lo [N][K] bf16
__global__ void tsplit_kernel(const float* __restrict__ W,
                              __nv_bfloat16* __restrict__ hi,
                              __nv_bfloat16* __restrict__ lo,
                              int K, int N)
{
    __shared__ float tile[32][33];
    const int n0 = blockIdx.x * 32, k0 = blockIdx.y * 32;
    const int tx = threadIdx.x, ty = threadIdx.y;
#pragma unroll
    for (int i = 0; i < 32; i += 8)
        tile[ty + i][tx] = W[(size_t)(k0 + ty + i) * N + n0 + tx];
    __syncthreads();
#pragma unroll
    for (int i = 0; i < 32; i += 8) {
        float v = tile[tx][ty + i];
        unsigned short h, l;
        split1(v, h, l);
        size_t o = (size_t)(n0 + ty + i) * K + k0 + tx;
        hi[o] = __ushort_as_bfloat16(h);
        lo[o] = __ushort_as_bfloat16(l);
    }
}

// ---------------------------------------------------------------------------
// Pipelined tensor-core split-GEMM, fragment loads via ldmatrix.
// CTA 128x64, k-tile 32, 2-stage cp.async, 60 KB smem -> 3 CTA/SM.
// ---------------------------------------------------------------------------
#define SA2 40
#define ST2_A (128 * SA2)
#define ST2_B (64 * SA2)
#define STAGE2 (2 * ST2_A + 2 * ST2_B)
#define GM_SMEM_BYTES (2 * STAGE2 * 2)

__global__ __launch_bounds__(256)
void gemm_mma(const __nv_bfloat16* __restrict__ Ahi,
              const __nv_bfloat16* __restrict__ Alo,
              const __nv_bfloat16* __restrict__ Bhi,
              const __nv_bfloat16* __restrict__ Blo,
              const float* __restrict__ bias,
              float* __restrict__ Cf,
              __nv_bfloat16* __restrict__ Chi,
              __nv_bfloat16* __restrict__ Clo,
              int M, int N, int K, int do_gelu)
{
    extern __shared__ __nv_bfloat16 smb[];
    const uint32_t sm_base = smem_u32(smb);

    const int tid = threadIdx.x;
    const int wid = tid >> 5;
    const int lid = tid & 31;
    const int gID = lid >> 2;
    const int t4  = lid & 3;

    const int row0 = blockIdx.y * 128;
    const int col0 = blockIdx.x * 64;
    const int m_off = (wid & 3) * 32;
    const int n_off = (wid >> 2) * 32;

    // ldmatrix lane-constant address components
    const int a_ro = ((lid >> 3) & 1) * 8 + (lid & 7);  // row offset within 16
    const int a_ko = (lid >> 4) * 8;                     // k offset (0 or 8)
    const int b_rr = lid & 7;                            // row within n-tile
    const int b_ni = (lid >> 4) & 1;                     // which n-tile of pair
    const int b_ko = ((lid >> 3) & 1) * 8;               // k offset (0 or 8)

    auto load_stage = [&](int buf, int t) {
        const int kb = t << 5;
        uint32_t base = sm_base + (uint32_t)buf * (STAGE2 * 2);
#pragma unroll
        for (int i = 0; i < 2; i++) {
            int e = tid + i * 256;
            int r = e >> 2, g = e & 3;
            uint32_t ds = (uint32_t)(r * SA2 + g * 8) * 2;
            size_t src = (size_t)(row0 + r) * K + kb + g * 8;
            cp16(base + ds, Ahi + src);
            cp16(base + ST2_A * 2 + ds, Alo + src);
        }
        {
            int r = tid >> 2, g = tid & 3;
            uint32_t ds = (uint32_t)(r * SA2 + g * 8) * 2;
            size_t src = (size_t)(col0 + r) * K + kb + g * 8;
            cp16(base + 2 * ST2_A * 2 + ds, Bhi + src);
            cp16(base + 2 * ST2_A * 2 + ST2_B * 2 + ds, Blo + src);
        }
        cp_commit();
    };

    float acc[2][4][4];
#pragma unroll
    for (int mi = 0; mi < 2; mi++)
#pragma unroll
        for (int ni = 0; ni < 4; ni++)
#pragma unroll
            for (int j = 0; j < 4; j++) acc[mi][ni][j] = 0.f;

    const int nT = K >> 5;
    load_stage(0, 0);

    for (int t = 0; t < nT; t++) {
        const int buf = t & 1;
        if (t + 1 < nT) {
            load_stage(1 - buf, t + 1);
            cp_wait<1>();
        } else {
            cp_wait<0>();
        }
        __syncthreads();

        const uint32_t sA = sm_base + (uint32_t)buf * (STAGE2 * 2);
        const uint32_t sB = sA + 2 * ST2_A * 2;

#pragma unroll
        for (int kk = 0; kk < 32; kk += 16) {
            uint32_t ahi[2][4], alo[2][4], bhi[4][2], blo[4][2];
#pragma unroll
            for (int mi = 0; mi < 2; mi++) {
                uint32_t aaddr = sA +
                    (uint32_t)((m_off + mi * 16 + a_ro) * SA2 + kk + a_ko) * 2;
                ldsm_x4(ahi[mi], aaddr);
                ldsm_x4(alo[mi], aaddr + ST2_A * 2);
            }
#pragma unroll
            for (int p = 0; p < 2; p++) {
                int n = n_off + (p * 2 + b_ni) * 8 + b_rr;
                uint32_t baddr = sB + (uint32_t)(n * SA2 + kk + b_ko) * 2;
                uint32_t r[4];
                ldsm_x4(r, baddr);
                bhi[p * 2][0] = r[0]; bhi[p * 2][1] = r[1];
                bhi[p * 2 + 1][0] = r[2]; bhi[p * 2 + 1][1] = r[3];
                ldsm_x4(r, baddr + ST2_B * 2);
                blo[p * 2][0] = r[0]; blo[p * 2][1] = r[1];
                blo[p * 2 + 1][0] = r[2]; blo[p * 2 + 1][1] = r[3];
            }
#pragma unroll
            for (int mi = 0; mi < 2; mi++)
#pragma unroll
                for (int ni = 0; ni < 4; ni++) {
                    mma16816(acc[mi][ni], ahi[mi], bhi[ni]);
                    mma16816(acc[mi][ni], alo[mi], bhi[ni]);
                    mma16816(acc[mi][ni], ahi[mi], blo[ni]);
                }
        }
        __syncthreads();
    }

    // ---- epilogue ----
#pragma unroll
    for (int mi = 0; mi < 2; mi++) {
#pragma unroll
        for (int ni = 0; ni < 4; ni++) {
            int col = col0 + n_off + ni * 8 + t4 * 2;
            float b0 = bias[col], b1 = bias[col + 1];
#pragma unroll
            for (int half = 0; half < 2; half++) {
                int row = row0 + m_off + mi * 16 + gID + half * 8;
                float v0 = acc[mi][ni][half * 2 + 0] + b0;
                float v1 = acc[mi][ni][half * 2 + 1] + b1;
                if (do_gelu) {
                    v0 = 0.5f * v0 * (1.0f + erff(v0 * 0.70710678118654752f));
                    v1 = 0.5f * v1 * (1.0f + erff(v1 * 0.70710678118654752f));
                }
                size_t o = (size_t)row * N + col;
                if (Cf) {
                    float2 fo; fo.x = v0; fo.y = v1;
                    *(float2*)(Cf + o) = fo;
                }
                if (Chi) {
                    unsigned short h0, h1, l0, l1;
                    split1(v0, h0, l0);
                    split1(v1, h1, l1);
                    *(uint32_t*)(Chi + o) = pack2(h0, h1);
                    *(uint32_t*)(Clo + o) = pack2(l0, l1);
                }
            }
        }
    }
}

// ---------------------------------------------------------------------------
// Tensor-core attention (round-10 proven: K pipelined, V staged).
// ---------------------------------------------------------------------------
#define AT_SA   72
#define AT_QHI  0
#define AT_QLO  9216
#define AT_K0   18432
#define AT_SV   36864
#define AT_PHI  55296
#define AT_PLO  64512
#define AT_SS   73728
#define AT_INV  (AT_SS + 64 * 512 * 4)
#define AT_SMEM (AT_INV + 256)

__global__ __launch_bounds__(256)
void attn_mma(const __nv_bfloat16* __restrict__ Qhi_g,
              const __nv_bfloat16* __restrict__ Qlo_g,
              const __nv_bfloat16* __restrict__ Khi_g,
              const __nv_bfloat16* __restrict__ Klo_g,
              const __nv_bfloat16* __restrict__ Vhi_g,
              const __nv_bfloat16* __restrict__ Vlo_g,
              const float* __restrict__ mask,
              __nv_bfloat16* __restrict__ Chi_g,
              __nv_bfloat16* __restrict__ Clo_g)
{
    extern __shared__ char smc[];
    const uint32_t sm_base = smem_u32(smc);
    __nv_bfloat16* Qhi = (__nv_bfloat16*)(smc + AT_QHI);
    __nv_bfloat16* Qlo = (__nv_bfloat16*)(smc + AT_QLO);
    __nv_bfloat16* Phi = (__nv_bfloat16*)(smc + AT_PHI);
    __nv_bfloat16* Plo = (__nv_bfloat16*)(smc + AT_PLO);
    float* Ss   = (float*)(smc + AT_SS);
    float* invs = (float*)(smc + AT_INV);

    const int tid = threadIdx.x;
    const int wid = tid >> 5, lid = tid & 31;
    const int gID = lid >> 2, t4 = lid & 3;
    const int wm = wid & 3, wn = wid >> 2;
    const int q0 = blockIdx.x * 64;
    const int h = blockIdx.y, b = blockIdx.z;
    const size_t hb = ((size_t)b * SEQ) * DMODEL + (size_t)h * HDIM;
    const float* mbase = mask + (size_t)b * SEQ * SEQ;

    auto load_k = [&](int bb, int kc) {
        const int k0 = kc * 64;
        uint32_t kh = sm_base + AT_K0 + (uint32_t)bb * 18432;
        uint32_t kl = kh + 9216;
#pragma unroll
        for (int i = 0; i < 2; i++) {
            int e = tid + i * 256;
            int r = e >> 3, g = e & 7;
            size_t src = hb + (size_t)(k0 + r) * DMODEL + g * 8;
            uint32_t ds = (uint32_t)(r * AT_SA + g * 8) * 2;
            cp16(kh + ds, Khi_g + src);
            cp16(kl + ds, Klo_g + src);
        }
        cp_commit();
    };

    auto stage_v = [&](int kc) {
        const int k0 = kc * 64;
        uint32_t sv = sm_base + AT_SV;
#pragma unroll
        for (int i = 0; i < 2; i++) {
            int e = tid + i * 256;
            int r = e >> 3, g = e & 7;
            size_t src = hb + (size_t)(k0 + r) * DMODEL + g * 8;
            uint32_t ds = (uint32_t)(r * 64 + g * 8) * 2;
            cp16(sv + ds, Vhi_g + src);
            cp16(sv + 8192 + ds, Vlo_g + src);
        }
        cp_commit();
    };

    load_k(0, 0);

#pragma unroll
    for (int i = 0; i < 2; i++) {
        int e = tid + i * 256;
        int r = e >> 3, g = e & 7;
        size_t src = hb + (size_t)(q0 + r) * DMODEL + g * 8;
        int ds = r * AT_SA + g * 8;
        *(uint4*)(Qhi + ds) = *(const uint4*)(Qhi_g + src);
        *(uint4*)(Qlo + ds) = *(const uint4*)(Qlo_g + src);
    }

    float pv[4][4];
#pragma unroll
    for (int ni = 0; ni < 4; ni++)
#pragma unroll
        for (int j = 0; j < 4; j++) pv[ni][j] = 0.f;

    // ---- phase 1: scores ----
    for (int kc = 0; kc < 8; kc++) {
        const int k0 = kc * 64;
        if (kc + 1 < 8) {
            load_k((kc + 1) & 1, kc + 1);
            cp_wait<1>();
        } else {
            cp_wait<0>();
        }
        __syncthreads();

        const __nv_bfloat16* Khi = (const __nv_bfloat16*)(smc + AT_K0 + (kc & 1) * 18432);
        const __nv_bfloat16* Klo = Khi + 4608;

        float s[4][4];
#pragma unroll
        for (int ni = 0; ni < 4; ni++)
#pragma unroll
            for (int j = 0; j < 4; j++) s[ni][j] = 0.f;

#pragma unroll
        for (int kk = 0; kk < 64; kk += 16) {
            uint32_t ah[4], al[4];
            int rb0 = (wm * 16 + gID) * AT_SA + kk + t4 * 2;
            int rb1 = rb0 + 8 * AT_SA;
            ah[0] = *(const uint32_t*)&Qhi[rb0];
            ah[1] = *(const uint32_t*)&Qhi[rb1];
            ah[2] = *(const uint32_t*)&Qhi[rb0 + 8];
            ah[3] = *(const uint32_t*)&Qhi[rb1 + 8];
            al[0] = *(const uint32_t*)&Qlo[rb0];
            al[1] = *(const uint32_t*)&Qlo[rb1];
            al[2] = *(const uint32_t*)&Qlo[rb0 + 8];
            al[3] = *(const uint32_t*)&Qlo[rb1 + 8];
#pragma unroll
            for (int ni = 0; ni < 4; ni++) {
                int nb = (wn * 32 + ni * 8 + gID) * AT_SA + kk + t4 * 2;
                uint32_t bh[2], bl[2];
                bh[0] = *(const uint32_t*)&Khi[nb];
                bh[1] = *(const uint32_t*)&Khi[nb + 8];
                bl[0] = *(const uint32_t*)&Klo[nb];
                bl[1] = *(const uint32_t*)&Klo[nb + 8];
                mma16816(s[ni], ah, bh);
                mma16816(s[ni], al, bh);
                mma16816(s[ni], ah, bl);
            }
        }
#pragma unroll
        for (int ni = 0; ni < 4; ni++) {
            int col = k0 + wn * 32 + ni * 8 + t4 * 2;
#pragma unroll
            for (int hf = 0; hf < 2; hf++) {
                int row = wm * 16 + gID + hf * 8;
                float2 m2 = *(const float2*)(mbase + (size_t)(q0 + row) * SEQ + col);
                float2 o;
                o.x = s[ni][hf * 2 + 0] * 0.125f + m2.x;
                o.y = s[ni][hf * 2 + 1] * 0.125f + m2.y;
                *(float2*)(Ss + row * 512 + col) = o;
            }
        }
        __syncthreads();
    }

    stage_v(0);

    // ---- phase 2: softmax ----
    {
#pragma unroll
        for (int rr = 0; rr < 8; rr++) {
            int r = wid * 8 + rr;
            float* row = Ss + r * 512;
            float4 v[4];
#pragma unroll
            for (int it = 0; it < 4; it++)
                v[it] = *(float4*)(row + it * 128 + lid * 4);
            float m = -1e30f;
#pragma unroll
            for (int it = 0; it < 4; it++)
                m = fmaxf(m, fmaxf(fmaxf(v[it].x, v[it].y), fmaxf(v[it].z, v[it].w)));
#pragma unroll
            for (int off = 16; off; off >>= 1)
                m = fmaxf(m, __shfl_xor_sync(0xffffffffu, m, off));
            float sum = 0.f;
#pragma unroll
            for (int it = 0; it < 4; it++) {
                v[it].x = fast_exp(v[it].x - m);
                v[it].y = fast_exp(v[it].y - m);
                v[it].z = fast_exp(v[it].z - m);
                v[it].w = fast_exp(v[it].w - m);
                sum += v[it].x + v[it].y + v[it].z + v[it].w;
                *(float4*)(row + it * 128 + lid * 4) = v[it];
            }
#pragma unroll
            for (int off = 16; off; off >>= 1)
                sum += __shfl_xor_sync(0xffffffffu, sum, off);
            if (lid == 0) invs[r] = 1.0f / sum;
        }
    }

    // ---- phase 3: P @ V ----
    __nv_bfloat16* Vth = (__nv_bfloat16*)(smc + AT_K0);
    __nv_bfloat16* Vtl = Vth + 4608;
    const __nv_bfloat16* Svh = (const __nv_bfloat16*)(smc + AT_SV);
    const __nv_bfloat16* Svl = Svh + 4096;
    for (int kc = 0; kc < 8; kc++) {
        const int k0 = kc * 64;
        cp_wait<0>();
        __syncthreads();

        // P chunk: normalize + split
        {
            int r = tid >> 2, c0 = (tid & 3) * 16;
            float is = invs[r];
#pragma unroll
            for (int j2 = 0; j2 < 2; j2++) {
                const float* src = Ss + r * 512 + k0 + c0 + j2 * 8;
                float4 a = *(const float4*)(src);
                float4 bq = *(const float4*)(src + 4);
                float vals[8] = {a.x * is, a.y * is, a.z * is, a.w * is,
                                 bq.x * is, bq.y * is, bq.z * is, bq.w * is};
                unsigned short hh[8], ll[8];
#pragma unroll
                for (int j = 0; j < 8; j++) split1(vals[j], hh[j], ll[j]);
                uint4 hv, lv;
                hv.x = pack2(hh[0], hh[1]); hv.y = pack2(hh[2], hh[3]);
                hv.z = pack2(hh[4], hh[5]); hv.w = pack2(hh[6], hh[7]);
                lv.x = pack2(ll[0], ll[1]); lv.y = pack2(ll[2], ll[3]);
                lv.z = pack2(ll[4], ll[5]); lv.w = pack2(ll[6], ll[7]);
                *(uint4*)(Phi + r * AT_SA + c0 + j2 * 8) = hv;
                *(uint4*)(Plo + r * AT_SA + c0 + j2 * 8) = lv;
            }
        }

        // V chunk: transpose from staging smem
#pragma unroll
        for (int i = 0; i < 4; i++) {
            int e = tid + i * 256;
            int r = e >> 4, c4 = e & 15;
            uint2 hv = *(const uint2*)(Svh + r * 64 + c4 * 4);
            uint2 lv = *(const uint2*)(Svl + r * 64 + c4 * 4);
            int d = c4 * 4;
            Vth[(d + 0) * AT_SA + r] = __ushort_as_bfloat16((unsigned short)(hv.x & 0xffff));
            Vth[(d + 1) * AT_SA + r] = __ushort_as_bfloat16((unsigned short)(hv.x >> 16));
            Vth[(d + 2) * AT_SA + r] = __ushort_as_bfloat16((unsigned short)(hv.y & 0xffff));
            Vth[(d + 3) * AT_SA + r] = __ushort_as_bfloat16((unsigned short)(hv.y >> 16));
            Vtl[(d + 0) * AT_SA + r] = __ushort_as_bfloat16((unsigned short)(lv.x & 0xffff));
            Vtl[(d + 1) * AT_SA + r] = __ushort_as_bfloat16((unsigned short)(lv.x >> 16));
            Vtl[(d + 2) * AT_SA + r] = __ushort_as_bfloat16((unsigned short)(lv.y & 0xffff));
            Vtl[(d + 3) * AT_SA + r] = __ushort_as_bfloat16((unsigned short)(lv.y >> 16));
        }
        __syncthreads();

        if (kc + 1 < 8) stage_v(kc + 1);

#pragma unroll
        for (int kk = 0; kk < 64; kk += 16) {
            uint32_t ah[4], al[4];
            int rb0 = (wm * 16 + gID) * AT_SA + kk + t4 * 2;
            int rb1 = rb0 + 8 * AT_SA;
            ah[0] = *(const uint32_t*)&Phi[rb0];
            ah[1] = *(const uint32_t*)&Phi[rb1];
            ah[2] = *(const uint32_t*)&Phi[rb0 + 8];
            ah[3] = *(const uint32_t*)&Phi[rb1 + 8];
            al[0] = *(const uint32_t*)&Plo[rb0];
            al[1] = *(const uint32_t*)&Plo[rb1];
            al[2] = *(const uint32_t*)&Plo[rb0 + 8];
            al[3] = *(const uint32_t*)&Plo[rb1 + 8];
#pragma unroll
            for (int ni = 0; ni < 4; ni++) {
                int nb = (wn * 32 + ni * 8 + gID) * AT_SA + kk + t4 * 2;
                uint32_t bh[2], bl[2];
                bh[0] = *(const uint32_t*)&Vth[nb];
                bh[1] = *(const uint32_t*)&Vth[nb + 8];
                bl[0] = *(const uint32_t*)&Vtl[nb];
                bl[1] = *(const uint32_t*)&Vtl[nb + 8];
                mma16816(pv[ni], ah, bh);
                mma16816(pv[ni], al, bh);
                mma16816(pv[ni], ah, bl);
            }
        }
    }

    // ---- write ctx as bf16 hi/lo ----
#pragma unroll
    for (int ni = 0; ni < 4; ni++) {
        int d = wn * 32 + ni * 8 + t4 * 2;
#pragma unroll
        for (int hf = 0; hf < 2; hf++) {
            int row = wm * 16 + gID + hf * 8;
            unsigned short h0, h1, l0, l1;
            split1(pv[ni][hf * 2 + 0], h0, l0);
            split1(pv[ni][hf * 2 + 1], h1, l1);
            size_t o = hb + (size_t)(q0 + row) * DMODEL + d;
            *(uint32_t*)(Chi_g + o) = pack2(h0, h1);
            *(uint32_t*)(Clo_g + o) = pack2(l0, l1);
        }
    }
}

// ---------------------------------------------------------------------------
// LayerNorm + residual: warp per row (round-10 proven).
// ---------------------------------------------------------------------------
__global__ __launch_bounds__(256)
void ln_residual_kernel(const float* __restrict__ y,
                        const float* __restrict__ res,
                        const float* __restrict__ g,
                        const float* __restrict__ bta,
                        float* __restrict__ out,
                        __nv_bfloat16* __restrict__ ohi,
                        __nv_bfloat16* __restrict__ olo)
{
    const int warp = threadIdx.x >> 5;
    const int lane = threadIdx.x & 31;
    const int row  = blockIdx.x * 8 + warp;
    const size_t base = (size_t)row * DMODEL;

    float4 v[4];
    float sum = 0.f;
#pragma unroll
    for (int it = 0; it < 4; it++) {
        int c = lane * 4 + it * 128;
        float4 a = *(const float4*)(y + base + c);
        float4 bb = *(const float4*)(res + base + c);
        v[it].x = a.x + bb.x; v[it].y = a.y + bb.y;
        v[it].z = a.z + bb.z; v[it].w = a.w + bb.w;
        sum += v[it].x + v[it].y + v[it].z + v[it].w;
    }
#pragma unroll
    for (int off = 16; off; off >>= 1)
        sum += __shfl_xor_sync(0xffffffffu, sum, off);
    float mean = sum * (1.0f / 512.0f);

    float var = 0.f;
#pragma unroll
    for (int it = 0; it < 4; it++) {
        v[it].x -= mean; v[it].y -= mean; v[it].z -= mean; v[it].w -= mean;
        var += v[it].x * v[it].x + v[it].y * v[it].y
             + v[it].z * v[it].z + v[it].w * v[it].w;
    }
#pragma unroll
    for (int off = 16; off; off >>= 1)
        var += __shfl_xor_sync(0xffffffffu, var, off);
    float inv = rsqrtf(var * (1.0f / 512.0f) + LN_EPS);

#pragma unroll
    for (int it = 0; it < 4; it++) {
        int c = lane * 4 + it * 128;
        float4 gg = *(const float4*)(g + c);
        float4 bb = *(const float4*)(bta + c);
        float4 o;
        o.x = v[it].x * inv * gg.x + bb.x;
        o.y = v[it].y * inv * gg.y + bb.y;
        o.z = v[it].z * inv * gg.z + bb.z;
        o.w = v[it].w * inv * gg.w + bb.w;
        *(float4*)(out + base + c) = o;
        if (ohi) {
            unsigned short h0, h1, h2, h3, l0, l1, l2, l3;
            split1(o.x, h0, l0); split1(o.y, h1, l1);
            split1(o.z, h2, l2); split1(o.w, h3, l3);
            uint2 hv, lv;
            hv.x = pack2(h0, h1); hv.y = pack2(h2, h3);
            lv.x = pack2(l0, l1); lv.y = pack2(l2, l3);
            *(uint2*)(ohi + base + c) = hv;
            *(uint2*)(olo + base + c) = lv;
        }
    }
}

// ---------------------------------------------------------------------------
// launch
// ---------------------------------------------------------------------------
extern "C" void kernel_launch(void* const* d_in, const int* in_sizes, int n_in,
                              void* d_out, int out_size)
{
    const float* x     = (const float*)d_in[0];
    const float* mask  = (const float*)d_in[1];
    const float* Wq    = (const float*)d_in[2];
    const float* bq    = (const float*)d_in[3];
    const float* Wk    = (const float*)d_in[4];
    const float* bk    = (const float*)d_in[5];
    const float* Wv    = (const float*)d_in[6];
    const float* bv    = (const float*)d_in[7];
    const float* Wo    = (const float*)d_in[8];
    const float* bo    = (const float*)d_in[9];
    const float* ln1g  = (const float*)d_in[10];
    const float* ln1b  = (const float*)d_in[11];
    const float* W1    = (const float*)d_in[12];
    const float* b1    = (const float*)d_in[13];
    const float* W2    = (const float*)d_in[14];
    const float* b2    = (const float*)d_in[15];
    const float* ln2g  = (const float*)d_in[16];
    const float* ln2b  = (const float*)d_in[17];
    float* out = (float*)d_out;

    float *t0, *aln;
    cudaGetSymbolAddress((void**)&t0,  g_t0);
    cudaGetSymbolAddress((void**)&aln, g_attnln);

    __nv_bfloat16 *xhi, *xlo, *qhi, *qlo, *khi, *klo, *vhi, *vlo;
    __nv_bfloat16 *chi, *clo, *ahi, *alo, *fhi, *flo;
    cudaGetSymbolAddress((void**)&xhi, g_xhi);
    cudaGetSymbolAddress((void**)&xlo, g_xlo);
    cudaGetSymbolAddress((void**)&qhi, g_qhi);
    cudaGetSymbolAddress((void**)&qlo, g_qlo);
    cudaGetSymbolAddress((void**)&khi, g_khi);
    cudaGetSymbolAddress((void**)&klo, g_klo);
    cudaGetSymbolAddress((void**)&vhi, g_vhi);
    cudaGetSymbolAddress((void**)&vlo, g_vlo);
    cudaGetSymbolAddress((void**)&chi, g_chi);
    cudaGetSymbolAddress((void**)&clo, g_clo);
    cudaGetSymbolAddress((void**)&ahi, g_ahi);
    cudaGetSymbolAddress((void**)&alo, g_alo);
    cudaGetSymbolAddress((void**)&fhi, g_fhi);
    cudaGetSymbolAddress((void**)&flo, g_flo);

    __nv_bfloat16 *wqh, *wql, *wkh, *wkl, *wvh, *wvl, *woh, *wol, *w1h, *w1l, *w2h, *w2l;
    cudaGetSymbolAddress((void**)&wqh, g_wqhi);
    cudaGetSymbolAddress((void**)&wql, g_wqlo);
    cudaGetSymbolAddress((void**)&wkh, g_wkhi);
    cudaGetSymbolAddress((void**)&wkl, g_wklo);
    cudaGetSymbolAddress((void**)&wvh, g_wvhi);
    cudaGetSymbolAddress((void**)&wvl, g_wvlo);
    cudaGetSymbolAddress((void**)&woh, g_wohi);
    cudaGetSymbolAddress((void**)&wol, g_wolo);
    cudaGetSymbolAddress((void**)&w1h, g_w1hi);
    cudaGetSymbolAddress((void**)&w1l, g_w1lo);
    cudaGetSymbolAddress((void**)&w2h, g_w2hi);
    cudaGetSymbolAddress((void**)&w2l, g_w2lo);

    cudaFuncSetAttribute(attn_mma,
                         cudaFuncAttributeMaxDynamicSharedMemorySize, AT_SMEM);
    cudaFuncSetAttribute(gemm_mma,
                         cudaFuncAttributeMaxDynamicSharedMemorySize, GM_SMEM_BYTES);

    dim3 tb(32, 8);

    // weight transpose + split
    tsplit_kernel<<<dim3(DMODEL / 32, DMODEL / 32), tb>>>(Wq, wqh, wql, DMODEL, DMODEL);
    tsplit_kernel<<<dim3(DMODEL / 32, DMODEL / 32), tb>>>(Wk, wkh, wkl, DMODEL, DMODEL);
    tsplit_kernel<<<dim3(DMODEL / 32, DMODEL / 32), tb>>>(Wv, wvh, wvl, DMODEL, DMODEL);
    tsplit_kernel<<<dim3(DMODEL / 32, DMODEL / 32), tb>>>(Wo, woh, wol, DMODEL, DMODEL);
    tsplit_kernel<<<dim3(DFF / 32, DMODEL / 32), tb>>>(W1, w1h, w1l, DMODEL, DFF);
    tsplit_kernel<<<dim3(DMODEL / 32, DFF / 32), tb>>>(W2, w2h, w2l, DFF, DMODEL);

    // split input x
    {
        int n4 = MTOK * DMODEL / 4;
        split_kernel<<<(n4 + 255) / 256, 256>>>(x, xhi, xlo, n4);
    }

    // QKV projections -> bf16 hi/lo directly
    {
        dim3 grid(DMODEL / 64, MTOK / 128);
        gemm_mma<<<grid, 256, GM_SMEM_BYTES>>>(xhi, xlo, wqh, wql, bq,
                                               nullptr, qhi, qlo,
                                               MTOK, DMODEL, DMODEL, 0);
        gemm_mma<<<grid, 256, GM_SMEM_BYTES>>>(xhi, xlo, wkh, wkl, bk,
                                               nullptr, khi, klo,
                                               MTOK, DMODEL, DMODEL, 0);
        gemm_mma<<<grid, 256, GM_SMEM_BYTES>>>(xhi, xlo, wvh, wvl, bv,
                                               nullptr, vhi, vlo,
                                               MTOK, DMODEL, DMODEL, 0);
    }

    // attention -> ctx bf16 hi/lo
    {
        dim3 grid(SEQ / 64, NHEADS, BATCH);
        attn_mma<<<grid, 256, AT_SMEM>>>(qhi, qlo, khi, klo, vhi, vlo,
                                         mask, chi, clo);
    }

    // output projection + residual LN
    {
        dim3 grid(DMODEL / 64, MTOK / 128);
        gemm_mma<<<grid, 256, GM_SMEM_BYTES>>>(chi, clo, woh, wol, bo,
                                               t0, nullptr, nullptr,
                                               MTOK, DMODEL, DMODEL, 0);
        ln_residual_kernel<<<MTOK / 8, 256>>>(t0, x, ln1g, ln1b, aln, ahi, alo);
    }

    // FFN
    {
        dim3 grid1(DFF / 64, MTOK / 128);
        gemm_mma<<<grid1, 256, GM_SMEM_BYTES>>>(ahi, alo, w1h, w1l, b1,
                                                nullptr, fhi, flo,
                                                MTOK, DFF, DMODEL, 1);
        dim3 grid2(DMODEL / 64, MTOK / 128);
        gemm_mma<<<grid2, 256, GM_SMEM_BYTES>>>(fhi, flo, w2h, w2l, b2,
                                                t0, nullptr, nullptr,
                                                MTOK, DMODEL, DFF, 0);
        ln_residual_kernel<<<MTOK / 8, 256>>>(t0, aln, ln2g, ln2b, out,
                                              nullptr, nullptr);
    }
}

// round 12
// speedup vs baseline: 1.1166x; 1.0228x over previous
#include <cuda_runtime.h>
#include <cuda_bf16.h>
#include <math.h>
#include <stdint.h>

// ---------------------------------------------------------------------------
// Problem dims (fixed)
// ---------------------------------------------------------------------------
#define BATCH   32
#define SEQ     512
#define DMODEL  512
#define NHEADS  8
#define HDIM    64
#define DFF     2048
#define MTOK    (BATCH * SEQ)
#define LN_EPS  1e-12f

// ---------------------------------------------------------------------------
// Scratch (device globals)
// ---------------------------------------------------------------------------
__device__ float g_t0[MTOK * DMODEL];
__device__ float g_attnln[MTOK * DMODEL];

__device__ __nv_bfloat16 g_xhi[MTOK * DMODEL];
__device__ __nv_bfloat16 g_xlo[MTOK * DMODEL];
__device__ __nv_bfloat16 g_qhi[MTOK * DMODEL];
__device__ __nv_bfloat16 g_qlo[MTOK * DMODEL];
__device__ __nv_bfloat16 g_khi[MTOK * DMODEL];
__device__ __nv_bfloat16 g_klo[MTOK * DMODEL];
__device__ __nv_bfloat16 g_vhi[MTOK * DMODEL];
__device__ __nv_bfloat16 g_vlo[MTOK * DMODEL];
__device__ __nv_bfloat16 g_chi[MTOK * DMODEL];
__device__ __nv_bfloat16 g_clo[MTOK * DMODEL];
__device__ __nv_bfloat16 g_ahi[MTOK * DMODEL];
__device__ __nv_bfloat16 g_alo[MTOK * DMODEL];
__device__ __nv_bfloat16 g_fhi[MTOK * DFF];
__device__ __nv_bfloat16 g_flo[MTOK * DFF];

__device__ __nv_bfloat16 g_wqhi[DMODEL * DMODEL];
__device__ __nv_bfloat16 g_wqlo[DMODEL * DMODEL];
__device__ __nv_bfloat16 g_wkhi[DMODEL * DMODEL];
__device__ __nv_bfloat16 g_wklo[DMODEL * DMODEL];
__device__ __nv_bfloat16 g_wvhi[DMODEL * DMODEL];
__device__ __nv_bfloat16 g_wvlo[DMODEL * DMODEL];
__device__ __nv_bfloat16 g_wohi[DMODEL * DMODEL];
__device__ __nv_bfloat16 g_wolo[DMODEL * DMODEL];
__device__ __nv_bfloat16 g_w1hi[DFF * DMODEL];
__device__ __nv_bfloat16 g_w1lo[DFF * DMODEL];
__device__ __nv_bfloat16 g_w2hi[DMODEL * DFF];
__device__ __nv_bfloat16 g_w2lo[DMODEL * DFF];

// ---------------------------------------------------------------------------
// helpers
// ---------------------------------------------------------------------------
__device__ __forceinline__ void mma16816(float* c, const uint32_t* a, const uint32_t* b)
{
    asm volatile(
        "mma.sync.aligned.m16n8k16.row.col.f32.bf16.bf16.f32 "
        "{%0,%1,%2,%3}, {%4,%5,%6,%7}, {%8,%9}, {%0,%1,%2,%3};"
        : "+f"(c[0]), "+f"(c[1]), "+f"(c[2]), "+f"(c[3])
        : "r"(a[0]), "r"(a[1]), "r"(a[2]), "r"(a[3]), "r"(b[0]), "r"(b[1]));
}

__device__ __forceinline__ void ldsm_x4(uint32_t* r, uint32_t addr)
{
    asm volatile(
        "ldmatrix.sync.aligned.m8n8.x4.shared.b16 {%0,%1,%2,%3}, [%4];"
        : "=r"(r[0]), "=r"(r[1]), "=r"(r[2]), "=r"(r[3]) : "r"(addr));
}

__device__ __forceinline__ uint32_t smem_u32(const void* p) {
    uint32_t a;
    asm("{ .reg .u64 t; cvta.to.shared.u64 t, %1; cvt.u32.u64 %0, t; }"
        : "=r"(a) : "l"(p));
    return a;
}

__device__ __forceinline__ void cp16(uint32_t dst, const void* src) {
    asm volatile("cp.async.cg.shared.global [%0], [%1], 16;"
                 :: "r"(dst), "l"(src));
}
__device__ __forceinline__ void cp_commit() {
    asm volatile("cp.async.commit_group;" ::: "memory");
}
template <int N>
__device__ __forceinline__ void cp_wait() {
    asm volatile("cp.async.wait_group %0;" :: "n"(N) : "memory");
}

__device__ __forceinline__ float fast_exp(float x) {
    float y = fmaxf(x * 1.4426950408889634f, -120.0f);
    float n = rintf(y);
    float f = y - n;
    float p = 1.3333558e-3f;
    p = fmaf(p, f, 9.6181291e-3f);
    p = fmaf(p, f, 5.5504109e-2f);
    p = fmaf(p, f, 2.4022651e-1f);
    p = fmaf(p, f, 6.9314718e-1f);
    p = fmaf(p, f, 1.0f);
    return p * __int_as_float(((int)n + 127) << 23);
}

__device__ __forceinline__ void split1(float v, unsigned short& h, unsigned short& l) {
    __nv_bfloat16 hb = __float2bfloat16_rn(v);
    float r = v - __bfloat162float(hb);
    __nv_bfloat16 lb = __float2bfloat16_rn(r);
    h = __bfloat16_as_ushort(hb);
    l = __bfloat16_as_ushort(lb);
}
__device__ __forceinline__ uint32_t pack2(unsigned short a, unsigned short b) {
    return (uint32_t)a | ((uint32_t)b << 16);
}

// ---------------------------------------------------------------------------
// prep kernels
// ---------------------------------------------------------------------------
__global__ void split_kernel(const float* __restrict__ X,
                             __nv_bfloat16* __restrict__ hi,
                             __nv_bfloat16* __restrict__ lo, int n4)
{
    int i = blockIdx.x * blockDim.x + threadIdx.x;
    if (i >= n4) return;
    float4 x = ((const float4*)X)[i];
    unsigned short h0, h1, h2, h3, l0, l1, l2, l3;
    split1(x.x, h0, l0); split1(x.y, h1, l1);
    split1(x.z, h2, l2); split1(x.w, h3, l3);
    uint2 hv, lv;
    hv.x = pack2(h0, h1); hv.y = pack2(h2, h3);
    lv.x = pack2(l0, l1); lv.y = pack2(l2, l3);
    ((uint2*)hi)[i] = hv;
    ((uint2*)lo)[i] = lv;
}

// Transpose + split: W[K][N] fp32 -> hi/lo [N][K] bf16
__global__ void tsplit_kernel(const float* __restrict__ W,
                              __nv_bfloat16* __restrict__ hi,
                              __nv_bfloat16* __restrict__ lo,
                              int K, int N)
{
    __shared__ float tile[32][33];
    const int n0 = blockIdx.x * 32, k0 = blockIdx.y * 32;
    const int tx = threadIdx.x, ty = threadIdx.y;
#pragma unroll
    for (int i = 0; i < 32; i += 8)
        tile[ty + i][tx] = W[(size_t)(k0 + ty + i) * N + n0 + tx];
    __syncthreads();
#pragma unroll
    for (int i = 0; i < 32; i += 8) {
        float v = tile[tx][ty + i];
        unsigned short h, l;
        split1(v, h, l);
        size_t o = (size_t)(n0 + ty + i) * K + k0 + tx;
        hi[o] = __ushort_as_bfloat16(h);
        lo[o] = __ushort_as_bfloat16(l);
    }
}

// ---------------------------------------------------------------------------
// Pipelined tensor-core split-GEMM, ldmatrix fragments (round-11 proven).
// CTA 128x64, k-tile 32, 2-stage cp.async, 60 KB smem -> 3 CTA/SM.
// ---------------------------------------------------------------------------
#define SA2 40
#define ST2_A (128 * SA2)
#define ST2_B (64 * SA2)
#define STAGE2 (2 * ST2_A + 2 * ST2_B)
#define GM_SMEM_BYTES (2 * STAGE2 * 2)

__global__ __launch_bounds__(256)
void gemm_mma(const __nv_bfloat16* __restrict__ Ahi,
              const __nv_bfloat16* __restrict__ Alo,
              const __nv_bfloat16* __restrict__ Bhi,
              const __nv_bfloat16* __restrict__ Blo,
              const float* __restrict__ bias,
              float* __restrict__ Cf,
              __nv_bfloat16* __restrict__ Chi,
              __nv_bfloat16* __restrict__ Clo,
              int M, int N, int K, int do_gelu)
{
    extern __shared__ __nv_bfloat16 smb[];
    const uint32_t sm_base = smem_u32(smb);

    const int tid = threadIdx.x;
    const int wid = tid >> 5;
    const int lid = tid & 31;
    const int gID = lid >> 2;
    const int t4  = lid & 3;

    const int row0 = blockIdx.y * 128;
    const int col0 = blockIdx.x * 64;
    const int m_off = (wid & 3) * 32;
    const int n_off = (wid >> 2) * 32;

    const int a_ro = ((lid >> 3) & 1) * 8 + (lid & 7);
    const int a_ko = (lid >> 4) * 8;
    const int b_rr = lid & 7;
    const int b_ni = (lid >> 4) & 1;
    const int b_ko = ((lid >> 3) & 1) * 8;

    auto load_stage = [&](int buf, int t) {
        const int kb = t << 5;
        uint32_t base = sm_base + (uint32_t)buf * (STAGE2 * 2);
#pragma unroll
        for (int i = 0; i < 2; i++) {
            int e = tid + i * 256;
            int r = e >> 2, g = e & 3;
            uint32_t ds = (uint32_t)(r * SA2 + g * 8) * 2;
            size_t src = (size_t)(row0 + r) * K + kb + g * 8;
            cp16(base + ds, Ahi + src);
            cp16(base + ST2_A * 2 + ds, Alo + src);
        }
        {
            int r = tid >> 2, g = tid & 3;
            uint32_t ds = (uint32_t)(r * SA2 + g * 8) * 2;
            size_t src = (size_t)(col0 + r) * K + kb + g * 8;
            cp16(base + 2 * ST2_A * 2 + ds, Bhi + src);
            cp16(base + 2 * ST2_A * 2 + ST2_B * 2 + ds, Blo + src);
        }
        cp_commit();
    };

    float acc[2][4][4];
#pragma unroll
    for (int mi = 0; mi < 2; mi++)
#pragma unroll
        for (int ni = 0; ni < 4; ni++)
#pragma unroll
            for (int j = 0; j < 4; j++) acc[mi][ni][j] = 0.f;

    const int nT = K >> 5;
    load_stage(0, 0);

    for (int t = 0; t < nT; t++) {
        const int buf = t & 1;
        if (t + 1 < nT) {
            load_stage(1 - buf, t + 1);
            cp_wait<1>();
        } else {
            cp_wait<0>();
        }
        __syncthreads();

        const uint32_t sA = sm_base + (uint32_t)buf * (STAGE2 * 2);
        const uint32_t sB = sA + 2 * ST2_A * 2;

#pragma unroll
        for (int kk = 0; kk < 32; kk += 16) {
            uint32_t ahi[2][4], alo[2][4], bhi[4][2], blo[4][2];
#pragma unroll
            for (int mi = 0; mi < 2; mi++) {
                uint32_t aaddr = sA +
                    (uint32_t)((m_off + mi * 16 + a_ro) * SA2 + kk + a_ko) * 2;
                ldsm_x4(ahi[mi], aaddr);
                ldsm_x4(alo[mi], aaddr + ST2_A * 2);
            }
#pragma unroll
            for (int p = 0; p < 2; p++) {
                int n = n_off + (p * 2 + b_ni) * 8 + b_rr;
                uint32_t baddr = sB + (uint32_t)(n * SA2 + kk + b_ko) * 2;
                uint32_t r[4];
                ldsm_x4(r, baddr);
                bhi[p * 2][0] = r[0]; bhi[p * 2][1] = r[1];
                bhi[p * 2 + 1][0] = r[2]; bhi[p * 2 + 1][1] = r[3];
                ldsm_x4(r, baddr + ST2_B * 2);
                blo[p * 2][0] = r[0]; blo[p * 2][1] = r[1];
                blo[p * 2 + 1][0] = r[2]; blo[p * 2 + 1][1] = r[3];
            }
#pragma unroll
            for (int mi = 0; mi < 2; mi++)
#pragma unroll
                for (int ni = 0; ni < 4; ni++) {
                    mma16816(acc[mi][ni], ahi[mi], bhi[ni]);
                    mma16816(acc[mi][ni], alo[mi], bhi[ni]);
                    mma16816(acc[mi][ni], ahi[mi], blo[ni]);
                }
        }
        __syncthreads();
    }

    // ---- epilogue ----
#pragma unroll
    for (int mi = 0; mi < 2; mi++) {
#pragma unroll
        for (int ni = 0; ni < 4; ni++) {
            int col = col0 + n_off + ni * 8 + t4 * 2;
            float b0 = bias[col], b1 = bias[col + 1];
#pragma unroll
            for (int half = 0; half < 2; half++) {
                int row = row0 + m_off + mi * 16 + gID + half * 8;
                float v0 = acc[mi][ni][half * 2 + 0] + b0;
                float v1 = acc[mi][ni][half * 2 + 1] + b1;
                if (do_gelu) {
                    v0 = 0.5f * v0 * (1.0f + erff(v0 * 0.70710678118654752f));
                    v1 = 0.5f * v1 * (1.0f + erff(v1 * 0.70710678118654752f));
                }
                size_t o = (size_t)row * N + col;
                if (Cf) {
                    float2 fo; fo.x = v0; fo.y = v1;
                    *(float2*)(Cf + o) = fo;
                }
                if (Chi) {
                    unsigned short h0, h1, l0, l1;
                    split1(v0, h0, l0);
                    split1(v1, h1, l1);
                    *(uint32_t*)(Chi + o) = pack2(h0, h1);
                    *(uint32_t*)(Clo + o) = pack2(l0, l1);
                }
            }
        }
    }
}

// ---------------------------------------------------------------------------
// Tensor-core attention: K pipelined, V staged, ldmatrix fragments.
// ---------------------------------------------------------------------------
#define AT_SA   72
#define AT_QHI  0
#define AT_QLO  9216
#define AT_K0   18432
#define AT_SV   36864
#define AT_PHI  55296
#define AT_PLO  64512
#define AT_SS   73728
#define AT_INV  (AT_SS + 64 * 512 * 4)
#define AT_SMEM (AT_INV + 256)

__global__ __launch_bounds__(256)
void attn_mma(const __nv_bfloat16* __restrict__ Qhi_g,
              const __nv_bfloat16* __restrict__ Qlo_g,
              const __nv_bfloat16* __restrict__ Khi_g,
              const __nv_bfloat16* __restrict__ Klo_g,
              const __nv_bfloat16* __restrict__ Vhi_g,
              const __nv_bfloat16* __restrict__ Vlo_g,
              const float* __restrict__ mask,
              __nv_bfloat16* __restrict__ Chi_g,
              __nv_bfloat16* __restrict__ Clo_g)
{
    extern __shared__ char smc[];
    const uint32_t sm_base = smem_u32(smc);
    __nv_bfloat16* Qhi = (__nv_bfloat16*)(smc + AT_QHI);
    __nv_bfloat16* Qlo = (__nv_bfloat16*)(smc + AT_QLO);
    __nv_bfloat16* Phi = (__nv_bfloat16*)(smc + AT_PHI);
    __nv_bfloat16* Plo = (__nv_bfloat16*)(smc + AT_PLO);
    float* Ss   = (float*)(smc + AT_SS);
    float* invs = (float*)(smc + AT_INV);

    const int tid = threadIdx.x;
    const int wid = tid >> 5, lid = tid & 31;
    const int gID = lid >> 2, t4 = lid & 3;
    const int wm = wid & 3, wn = wid >> 2;
    const int q0 = blockIdx.x * 64;
    const int h = blockIdx.y, b = blockIdx.z;
    const size_t hb = ((size_t)b * SEQ) * DMODEL + (size_t)h * HDIM;
    const float* mbase = mask + (size_t)b * SEQ * SEQ;

    // ldmatrix lane-constant components (same mapping as gemm)
    const int a_ro = ((lid >> 3) & 1) * 8 + (lid & 7);
    const int a_ko = (lid >> 4) * 8;
    const int b_rr = lid & 7;
    const int b_ni = (lid >> 4) & 1;
    const int b_ko = ((lid >> 3) & 1) * 8;

    auto load_k = [&](int bb, int kc) {
        const int k0 = kc * 64;
        uint32_t kh = sm_base + AT_K0 + (uint32_t)bb * 18432;
        uint32_t kl = kh + 9216;
#pragma unroll
        for (int i = 0; i < 2; i++) {
            int e = tid + i * 256;
            int r = e >> 3, g = e & 7;
            size_t src = hb + (size_t)(k0 + r) * DMODEL + g * 8;
            uint32_t ds = (uint32_t)(r * AT_SA + g * 8) * 2;
            cp16(kh + ds, Khi_g + src);
            cp16(kl + ds, Klo_g + src);
        }
        cp_commit();
    };

    auto stage_v = [&](int kc) {
        const int k0 = kc * 64;
        uint32_t sv = sm_base + AT_SV;
#pragma unroll
        for (int i = 0; i < 2; i++) {
            int e = tid + i * 256;
            int r = e >> 3, g = e & 7;
            size_t src = hb + (size_t)(k0 + r) * DMODEL + g * 8;
            uint32_t ds = (uint32_t)(r * 64 + g * 8) * 2;
            cp16(sv + ds, Vhi_g + src);
            cp16(sv + 8192 + ds, Vlo_g + src);
        }
        cp_commit();
    };

    load_k(0, 0);

#pragma unroll
    for (int i = 0; i < 2; i++) {
        int e = tid + i * 256;
        int r = e >> 3, g = e & 7;
        size_t src = hb + (size_t)(q0 + r) * DMODEL + g * 8;
        int ds = r * AT_SA + g * 8;
        *(uint4*)(Qhi + ds) = *(const uint4*)(Qhi_g + src);
        *(uint4*)(Qlo + ds) = *(const uint4*)(Qlo_g + src);
    }

    float pv[4][4];
#pragma unroll
    for (int ni = 0; ni < 4; ni++)
#pragma unroll
        for (int j = 0; j < 4; j++) pv[ni][j] = 0.f;

    const uint32_t uQhi = sm_base + AT_QHI;
    const uint32_t uQlo = sm_base + AT_QLO;
    const uint32_t uPhi = sm_base + AT_PHI;
    const uint32_t uPlo = sm_base + AT_PLO;

    // ---- phase 1: scores ----
    for (int kc = 0; kc < 8; kc++) {
        const int k0 = kc * 64;
        if (kc + 1 < 8) {
            load_k((kc + 1) & 1, kc + 1);
            cp_wait<1>();
        } else {
            cp_wait<0>();
        }
        __syncthreads();

        const uint32_t uKhi = sm_base + AT_K0 + (uint32_t)(kc & 1) * 18432;
        const uint32_t uKlo = uKhi + 9216;

        float s[4][4];
#pragma unroll
        for (int ni = 0; ni < 4; ni++)
#pragma unroll
            for (int j = 0; j < 4; j++) s[ni][j] = 0.f;

#pragma unroll
        for (int kk = 0; kk < 64; kk += 16) {
            uint32_t ah[4], al[4], bh[4][2], bl[4][2];
            {
                uint32_t aaddr = (uint32_t)((wm * 16 + a_ro) * AT_SA + kk + a_ko) * 2;
                ldsm_x4(ah, uQhi + aaddr);
                ldsm_x4(al, uQlo + aaddr);
            }
#pragma unroll
            for (int p = 0; p < 2; p++) {
                int n = wn * 32 + (p * 2 + b_ni) * 8 + b_rr;
                uint32_t baddr = (uint32_t)(n * AT_SA + kk + b_ko) * 2;
                uint32_t r[4];
                ldsm_x4(r, uKhi + baddr);
                bh[p * 2][0] = r[0]; bh[p * 2][1] = r[1];
                bh[p * 2 + 1][0] = r[2]; bh[p * 2 + 1][1] = r[3];
                ldsm_x4(r, uKlo + baddr);
                bl[p * 2][0] = r[0]; bl[p * 2][1] = r[1];
                bl[p * 2 + 1][0] = r[2]; bl[p * 2 + 1][1] = r[3];
            }
#pragma unroll
            for (int ni = 0; ni < 4; ni++) {
                mma16816(s[ni], ah, bh[ni]);
                mma16816(s[ni], al, bh[ni]);
                mma16816(s[ni], ah, bl[ni]);
            }
        }
#pragma unroll
        for (int ni = 0; ni < 4; ni++) {
            int col = k0 + wn * 32 + ni * 8 + t4 * 2;
#pragma unroll
            for (int hf = 0; hf < 2; hf++) {
                int row = wm * 16 + gID + hf * 8;
                float2 m2 = *(const float2*)(mbase + (size_t)(q0 + row) * SEQ + col);
                float2 o;
                o.x = s[ni][hf * 2 + 0] * 0.125f + m2.x;
                o.y = s[ni][hf * 2 + 1] * 0.125f + m2.y;
                *(float2*)(Ss + row * 512 + col) = o;
            }
        }
        __syncthreads();
    }

    stage_v(0);

    // ---- phase 2: softmax ----
    {
#pragma unroll
        for (int rr = 0; rr < 8; rr++) {
            int r = wid * 8 + rr;
            float* row = Ss + r * 512;
            float4 v[4];
#pragma unroll
            for (int it = 0; it < 4; it++)
                v[it] = *(float4*)(row + it * 128 + lid * 4);
            float m = -1e30f;
#pragma unroll
            for (int it = 0; it < 4; it++)
                m = fmaxf(m, fmaxf(fmaxf(v[it].x, v[it].y), fmaxf(v[it].z, v[it].w)));
#pragma unroll
            for (int off = 16; off; off >>= 1)
                m = fmaxf(m, __shfl_xor_sync(0xffffffffu, m, off));
            float sum = 0.f;
#pragma unroll
            for (int it = 0; it < 4; it++) {
                v[it].x = fast_exp(v[it].x - m);
                v[it].y = fast_exp(v[it].y - m);
                v[it].z = fast_exp(v[it].z - m);
                v[it].w = fast_exp(v[it].w - m);
                sum += v[it].x + v[it].y + v[it].z + v[it].w;
                *(float4*)(row + it * 128 + lid * 4) = v[it];
            }
#pragma unroll
            for (int off = 16; off; off >>= 1)
                sum += __shfl_xor_sync(0xffffffffu, sum, off);
            if (lid == 0) invs[r] = 1.0f / sum;
        }
    }

    // ---- phase 3: P @ V ----
    __nv_bfloat16* Vth = (__nv_bfloat16*)(smc + AT_K0);
    __nv_bfloat16* Vtl = Vth + 4608;
    const uint32_t uVth = sm_base + AT_K0;
    const uint32_t uVtl = uVth + 9216;
    const __nv_bfloat16* Svh = (const __nv_bfloat16*)(smc + AT_SV);
    const __nv_bfloat16* Svl = Svh + 4096;
    for (int kc = 0; kc < 8; kc++) {
        const int k0 = kc * 64;
        cp_wait<0>();
        __syncthreads();

        // P chunk: normalize + split
        {
            int r = tid >> 2, c0 = (tid & 3) * 16;
            float is = invs[r];
#pragma unroll
            for (int j2 = 0; j2 < 2; j2++) {
                const float* src = Ss + r * 512 + k0 + c0 + j2 * 8;
                float4 a = *(const float4*)(src);
                float4 bq = *(const float4*)(src + 4);
                float vals[8] = {a.x * is, a.y * is, a.z * is, a.w * is,
                                 bq.x * is, bq.y * is, bq.z * is, bq.w * is};
                unsigned short hh[8], ll[8];
#pragma unroll
                for (int j = 0; j < 8; j++) split1(vals[j], hh[j], ll[j]);
                uint4 hv, lv;
                hv.x = pack2(hh[0], hh[1]); hv.y = pack2(hh[2], hh[3]);
                hv.z = pack2(hh[4], hh[5]); hv.w = pack2(hh[6], hh[7]);
                lv.x = pack2(ll[0], ll[1]); lv.y = pack2(ll[2], ll[3]);
                lv.z = pack2(ll[4], ll[5]); lv.w = pack2(ll[6], ll[7]);
                *(uint4*)(Phi + r * AT_SA + c0 + j2 * 8) = hv;
                *(uint4*)(Plo + r * AT_SA + c0 + j2 * 8) = lv;
            }
        }

        // V chunk: transpose from staging smem
#pragma unroll
        for (int i = 0; i < 4; i++) {
            int e = tid + i * 256;
            int r = e >> 4, c4 = e & 15;
            uint2 hv = *(const uint2*)(Svh + r * 64 + c4 * 4);
            uint2 lv = *(const uint2*)(Svl + r * 64 + c4 * 4);
            int d = c4 * 4;
            Vth[(d + 0) * AT_SA + r] = __ushort_as_bfloat16((unsigned short)(hv.x & 0xffff));
            Vth[(d + 1) * AT_SA + r] = __ushort_as_bfloat16((unsigned short)(hv.x >> 16));
            Vth[(d + 2) * AT_SA + r] = __ushort_as_bfloat16((unsigned short)(hv.y & 0xffff));
            Vth[(d + 3) * AT_SA + r] = __ushort_as_bfloat16((unsigned short)(hv.y >> 16));
            Vtl[(d + 0) * AT_SA + r] = __ushort_as_bfloat16((unsigned short)(lv.x & 0xffff));
            Vtl[(d + 1) * AT_SA + r] = __ushort_as_bfloat16((unsigned short)(lv.x >> 16));
            Vtl[(d + 2) * AT_SA + r] = __ushort_as_bfloat16((unsigned short)(lv.y & 0xffff));
            Vtl[(d + 3) * AT_SA + r] = __ushort_as_bfloat16((unsigned short)(lv.y >> 16));
        }
        __syncthreads();

        if (kc + 1 < 8) stage_v(kc + 1);

#pragma unroll
        for (int kk = 0; kk < 64; kk += 16) {
            uint32_t ah[4], al[4], bh[4][2], bl[4][2];
            {
                uint32_t aaddr = (uint32_t)((wm * 16 + a_ro) * AT_SA + kk + a_ko) * 2;
                ldsm_x4(ah, uPhi + aaddr);
                ldsm_x4(al, uPlo + aaddr);
            }
#pragma unroll
            for (int p = 0; p < 2; p++) {
                int n = wn * 32 + (p * 2 + b_ni) * 8 + b_rr;
                uint32_t baddr = (uint32_t)(n * AT_SA + kk + b_ko) * 2;
                uint32_t r[4];
                ldsm_x4(r, uVth + baddr);
                bh[p * 2][0] = r[0]; bh[p * 2][1] = r[1];
                bh[p * 2 + 1][0] = r[2]; bh[p * 2 + 1][1] = r[3];
                ldsm_x4(r, uVtl + baddr);
                bl[p * 2][0] = r[0]; bl[p * 2][1] = r[1];
                bl[p * 2 + 1][0] = r[2]; bl[p * 2 + 1][1] = r[3];
            }
#pragma unroll
            for (int ni = 0; ni < 4; ni++) {
                mma16816(pv[ni], ah, bh[ni]);
                mma16816(pv[ni], al, bh[ni]);
                mma16816(pv[ni], ah, bl[ni]);
            }
        }
    }

    // ---- write ctx as bf16 hi/lo ----
#pragma unroll
    for (int ni = 0; ni < 4; ni++) {
        int d = wn * 32 + ni * 8 + t4 * 2;
#pragma unroll
        for (int hf = 0; hf < 2; hf++) {
            int row = wm * 16 + gID + hf * 8;
            unsigned short h0, h1, l0, l1;
            split1(pv[ni][hf * 2 + 0], h0, l0);
            split1(pv[ni][hf * 2 + 1], h1, l1);
            size_t o = hb + (size_t)(q0 + row) * DMODEL + d;
            *(uint32_t*)(Chi_g + o) = pack2(h0, h1);
            *(uint32_t*)(Clo_g + o) = pack2(l0, l1);
        }
    }
}

// ---------------------------------------------------------------------------
// LayerNorm + residual: warp per row (round-10 proven).
// ---------------------------------------------------------------------------
__global__ __launch_bounds__(256)
void ln_residual_kernel(const float* __restrict__ y,
                        const float* __restrict__ res,
                        const float* __restrict__ g,
                        const float* __restrict__ bta,
                        float* __restrict__ out,
                        __nv_bfloat16* __restrict__ ohi,
                        __nv_bfloat16* __restrict__ olo)
{
    const int warp = threadIdx.x >> 5;
    const int lane = threadIdx.x & 31;
    const int row  = blockIdx.x * 8 + warp;
    const size_t base = (size_t)row * DMODEL;

    float4 v[4];
    float sum = 0.f;
#pragma unroll
    for (int it = 0; it < 4; it++) {
        int c = lane * 4 + it * 128;
        float4 a = *(const float4*)(y + base + c);
        float4 bb = *(const float4*)(res + base + c);
        v[it].x = a.x + bb.x; v[it].y = a.y + bb.y;
        v[it].z = a.z + bb.z; v[it].w = a.w + bb.w;
        sum += v[it].x + v[it].y + v[it].z + v[it].w;
    }
#pragma unroll
    for (int off = 16; off; off >>= 1)
        sum += __shfl_xor_sync(0xffffffffu, sum, off);
    float mean = sum * (1.0f / 512.0f);

    float var = 0.f;
#pragma unroll
    for (int it = 0; it < 4; it++) {
        v[it].x -= mean; v[it].y -= mean; v[it].z -= mean; v[it].w -= mean;
        var += v[it].x * v[it].x + v[it].y * v[it].y
             + v[it].z * v[it].z + v[it].w * v[it].w;
    }
#pragma unroll
    for (int off = 16; off; off >>= 1)
        var += __shfl_xor_sync(0xffffffffu, var, off);
    float inv = rsqrtf(var * (1.0f / 512.0f) + LN_EPS);

#pragma unroll
    for (int it = 0; it < 4; it++) {
        int c = lane * 4 + it * 128;
        float4 gg = *(const float4*)(g + c);
        float4 bb = *(const float4*)(bta + c);
        float4 o;
        o.x = v[it].x * inv * gg.x + bb.x;
        o.y = v[it].y * inv * gg.y + bb.y;
        o.z = v[it].z * inv * gg.z + bb.z;
        o.w = v[it].w * inv * gg.w + bb.w;
        *(float4*)(out + base + c) = o;
        if (ohi) {
            unsigned short h0, h1, h2, h3, l0, l1, l2, l3;
            split1(o.x, h0, l0); split1(o.y, h1, l1);
            split1(o.z, h2, l2); split1(o.w, h3, l3);
            uint2 hv, lv;
            hv.x = pack2(h0, h1); hv.y = pack2(h2, h3);
            lv.x = pack2(l0, l1); lv.y = pack2(l2, l3);
            *(uint2*)(ohi + base + c) = hv;
            *(uint2*)(olo + base + c) = lv;
        }
    }
}

// ---------------------------------------------------------------------------
// launch
// ---------------------------------------------------------------------------
extern "C" void kernel_launch(void* const* d_in, const int* in_sizes, int n_in,
                              void* d_out, int out_size)
{
    const float* x     = (const float*)d_in[0];
    const float* mask  = (const float*)d_in[1];
    const float* Wq    = (const float*)d_in[2];
    const float* bq    = (const float*)d_in[3];
    const float* Wk    = (const float*)d_in[4];
    const float* bk    = (const float*)d_in[5];
    const float* Wv    = (const float*)d_in[6];
    const float* bv    = (const float*)d_in[7];
    const float* Wo    = (const float*)d_in[8];
    const float* bo    = (const float*)d_in[9];
    const float* ln1g  = (const float*)d_in[10];
    const float* ln1b  = (const float*)d_in[11];
    const float* W1    = (const float*)d_in[12];
    const float* b1    = (const float*)d_in[13];
    const float* W2    = (const float*)d_in[14];
    const float* b2    = (const float*)d_in[15];
    const float* ln2g  = (const float*)d_in[16];
    const float* ln2b  = (const float*)d_in[17];
    float* out = (float*)d_out;

    float *t0, *aln;
    cudaGetSymbolAddress((void**)&t0,  g_t0);
    cudaGetSymbolAddress((void**)&aln, g_attnln);

    __nv_bfloat16 *xhi, *xlo, *qhi, *qlo, *khi, *klo, *vhi, *vlo;
    __nv_bfloat16 *chi, *clo, *ahi, *alo, *fhi, *flo;
    cudaGetSymbolAddress((void**)&xhi, g_xhi);
    cudaGetSymbolAddress((void**)&xlo, g_xlo);
    cudaGetSymbolAddress((void**)&qhi, g_qhi);
    cudaGetSymbolAddress((void**)&qlo, g_qlo);
    cudaGetSymbolAddress((void**)&khi, g_khi);
    cudaGetSymbolAddress((void**)&klo, g_klo);
    cudaGetSymbolAddress((void**)&vhi, g_vhi);
    cudaGetSymbolAddress((void**)&vlo, g_vlo);
    cudaGetSymbolAddress((void**)&chi, g_chi);
    cudaGetSymbolAddress((void**)&clo, g_clo);
    cudaGetSymbolAddress((void**)&ahi, g_ahi);
    cudaGetSymbolAddress((void**)&alo, g_alo);
    cudaGetSymbolAddress((void**)&fhi, g_fhi);
    cudaGetSymbolAddress((void**)&flo, g_flo);

    __nv_bfloat16 *wqh, *wql, *wkh, *wkl, *wvh, *wvl, *woh, *wol, *w1h, *w1l, *w2h, *w2l;
    cudaGetSymbolAddress((void**)&wqh, g_wqhi);
    cudaGetSymbolAddress((void**)&wql, g_wqlo);
    cudaGetSymbolAddress((void**)&wkh, g_wkhi);
    cudaGetSymbolAddress((void**)&wkl, g_wklo);
    cudaGetSymbolAddress((void**)&wvh, g_wvhi);
    cudaGetSymbolAddress((void**)&wvl, g_wvlo);
    cudaGetSymbolAddress((void**)&woh, g_wohi);
    cudaGetSymbolAddress((void**)&wol, g_wolo);
    cudaGetSymbolAddress((void**)&w1h, g_w1hi);
    cudaGetSymbolAddress((void**)&w1l, g_w1lo);
    cudaGetSymbolAddress((void**)&w2h, g_w2hi);
    cudaGetSymbolAddress((void**)&w2l, g_w2lo);

    cudaFuncSetAttribute(attn_mma,
                         cudaFuncAttributeMaxDynamicSharedMemorySize, AT_SMEM);
    cudaFuncSetAttribute(gemm_mma,
                         cudaFuncAttributeMaxDynamicSharedMemorySize, GM_SMEM_BYTES);

    dim3 tb(32, 8);

    // weight transpose + split
    tsplit_kernel<<<dim3(DMODEL / 32, DMODEL / 32), tb>>>(Wq, wqh, wql, DMODEL, DMODEL);
    tsplit_kernel<<<dim3(DMODEL / 32, DMODEL / 32), tb>>>(Wk, wkh, wkl, DMODEL, DMODEL);
    tsplit_kernel<<<dim3(DMODEL / 32, DMODEL / 32), tb>>>(Wv, wvh, wvl, DMODEL, DMODEL);
    tsplit_kernel<<<dim3(DMODEL / 32, DMODEL / 32), tb>>>(Wo, woh, wol, DMODEL, DMODEL);
    tsplit_kernel<<<dim3(DFF / 32, DMODEL / 32), tb>>>(W1, w1h, w1l, DMODEL, DFF);
    tsplit_kernel<<<dim3(DMODEL / 32, DFF / 32), tb>>>(W2, w2h, w2l, DFF, DMODEL);

    // split input x
    {
        int n4 = MTOK * DMODEL / 4;
        split_kernel<<<(n4 + 255) / 256, 256>>>(x, xhi, xlo, n4);
    }

    // QKV projections -> bf16 hi/lo directly
    {
        dim3 grid(DMODEL / 64, MTOK / 128);
        gemm_mma<<<grid, 256, GM_SMEM_BYTES>>>(xhi, xlo, wqh, wql, bq,
                                               nullptr, qhi, qlo,
                                               MTOK, DMODEL, DMODEL, 0);
        gemm_mma<<<grid, 256, GM_SMEM_BYTES>>>(xhi, xlo, wkh, wkl, bk,
                                               nullptr, khi, klo,
                                               MTOK, DMODEL, DMODEL, 0);
        gemm_mma<<<grid, 256, GM_SMEM_BYTES>>>(xhi, xlo, wvh, wvl, bv,
                                               nullptr, vhi, vlo,
                                               MTOK, DMODEL, DMODEL, 0);
    }

    // attention -> ctx bf16 hi/lo
    {
        dim3 grid(SEQ / 64, NHEADS, BATCH);
        attn_mma<<<grid, 256, AT_SMEM>>>(qhi, qlo, khi, klo, vhi, vlo,
                                         mask, chi, clo);
    }

    // output projection + residual LN
    {
        dim3 grid(DMODEL / 64, MTOK / 128);
        gemm_mma<<<grid, 256, GM_SMEM_BYTES>>>(chi, clo, woh, wol, bo,
                                               t0, nullptr, nullptr,
                                               MTOK, DMODEL, DMODEL, 0);
        ln_residual_kernel<<<MTOK / 8, 256>>>(t0, x, ln1g, ln1b, aln, ahi, alo);
    }

    // FFN
    {
        dim3 grid1(DFF / 64, MTOK / 128);
        gemm_mma<<<grid1, 256, GM_SMEM_BYTES>>>(ahi, alo, w1h, w1l, b1,
                                                nullptr, fhi, flo,
                                                MTOK, DFF, DMODEL, 1);
        dim3 grid2(DMODEL / 64, MTOK / 128);
        gemm_mma<<<grid2, 256, GM_SMEM_BYTES>>>(fhi, flo, w2h, w2l, b2,
                                                t0, nullptr, nullptr,
                                                MTOK, DMODEL, DFF, 0);
        ln_residual_kernel<<<MTOK / 8, 256>>>(t0, aln, ln2g, ln2b, out,
                                              nullptr, nullptr);
    }
}

// round 14
// speedup vs baseline: 1.1284x; 1.0106x over previous
#include <cuda_runtime.h>
#include <cuda_bf16.h>
#include <math.h>
#include <stdint.h>

// ---------------------------------------------------------------------------
// Problem dims (fixed)
// ---------------------------------------------------------------------------
#define BATCH   32
#define SEQ     512
#define DMODEL  512
#define NHEADS  8
#define HDIM    64
#define DFF     2048
#define MTOK    (BATCH * SEQ)
#define LN_EPS  1e-12f

// ---------------------------------------------------------------------------
// Scratch (device globals)
// ---------------------------------------------------------------------------
__device__ float g_t0[MTOK * DMODEL];
__device__ float g_attnln[MTOK * DMODEL];

__device__ __nv_bfloat16 g_xhi[MTOK * DMODEL];
__device__ __nv_bfloat16 g_xlo[MTOK * DMODEL];
__device__ __nv_bfloat16 g_qhi[MTOK * DMODEL];
__device__ __nv_bfloat16 g_qlo[MTOK * DMODEL];
__device__ __nv_bfloat16 g_khi[MTOK * DMODEL];
__device__ __nv_bfloat16 g_klo[MTOK * DMODEL];
__device__ __nv_bfloat16 g_vhi[MTOK * DMODEL];
__device__ __nv_bfloat16 g_vlo[MTOK * DMODEL];
__device__ __nv_bfloat16 g_chi[MTOK * DMODEL];
__device__ __nv_bfloat16 g_clo[MTOK * DMODEL];
__device__ __nv_bfloat16 g_ahi[MTOK * DMODEL];
__device__ __nv_bfloat16 g_alo[MTOK * DMODEL];
__device__ __nv_bfloat16 g_fhi[MTOK * DFF];
__device__ __nv_bfloat16 g_flo[MTOK * DFF];

__device__ __nv_bfloat16 g_wqhi[DMODEL * DMODEL];
__device__ __nv_bfloat16 g_wqlo[DMODEL * DMODEL];
__device__ __nv_bfloat16 g_wkhi[DMODEL * DMODEL];
__device__ __nv_bfloat16 g_wklo[DMODEL * DMODEL];
__device__ __nv_bfloat16 g_wvhi[DMODEL * DMODEL];
__device__ __nv_bfloat16 g_wvlo[DMODEL * DMODEL];
__device__ __nv_bfloat16 g_wohi[DMODEL * DMODEL];
__device__ __nv_bfloat16 g_wolo[DMODEL * DMODEL];
__device__ __nv_bfloat16 g_w1hi[DFF * DMODEL];
__device__ __nv_bfloat16 g_w1lo[DFF * DMODEL];
__device__ __nv_bfloat16 g_w2hi[DMODEL * DFF];
__device__ __nv_bfloat16 g_w2lo[DMODEL * DFF];

// ---------------------------------------------------------------------------
// helpers
// ---------------------------------------------------------------------------
__device__ __forceinline__ void mma16816(float* c, const uint32_t* a, const uint32_t* b)
{
    asm volatile(
        "mma.sync.aligned.m16n8k16.row.col.f32.bf16.bf16.f32 "
        "{%0,%1,%2,%3}, {%4,%5,%6,%7}, {%8,%9}, {%0,%1,%2,%3};"
        : "+f"(c[0]), "+f"(c[1]), "+f"(c[2]), "+f"(c[3])
        : "r"(a[0]), "r"(a[1]), "r"(a[2]), "r"(a[3]), "r"(b[0]), "r"(b[1]));
}

__device__ __forceinline__ void ldsm_x4(uint32_t* r, uint32_t addr)
{
    asm volatile(
        "ldmatrix.sync.aligned.m8n8.x4.shared.b16 {%0,%1,%2,%3}, [%4];"
        : "=r"(r[0]), "=r"(r[1]), "=r"(r[2]), "=r"(r[3]) : "r"(addr));
}

__device__ __forceinline__ uint32_t smem_u32(const void* p) {
    uint32_t a;
    asm("{ .reg .u64 t; cvta.to.shared.u64 t, %1; cvt.u32.u64 %0, t; }"
        : "=r"(a) : "l"(p));
    return a;
}

__device__ __forceinline__ void cp16(uint32_t dst, const void* src) {
    asm volatile("cp.async.cg.shared.global [%0], [%1], 16;"
                 :: "r"(dst), "l"(src));
}
__device__ __forceinline__ void cp_commit() {
    asm volatile("cp.async.commit_group;" ::: "memory");
}
template <int N>
__device__ __forceinline__ void cp_wait() {
    asm volatile("cp.async.wait_group %0;" :: "n"(N) : "memory");
}

__device__ __forceinline__ float fast_exp(float x) {
    float y = fmaxf(x * 1.4426950408889634f, -120.0f);
    float n = rintf(y);
    float f = y - n;
    float p = 1.3333558e-3f;
    p = fmaf(p, f, 9.6181291e-3f);
    p = fmaf(p, f, 5.5504109e-2f);
    p = fmaf(p, f, 2.4022651e-1f);
    p = fmaf(p, f, 6.9314718e-1f);
    p = fmaf(p, f, 1.0f);
    return p * __int_as_float(((int)n + 127) << 23);
}

__device__ __forceinline__ void split1(float v, unsigned short& h, unsigned short& l) {
    __nv_bfloat16 hb = __float2bfloat16_rn(v);
    float r = v - __bfloat162float(hb);
    __nv_bfloat16 lb = __float2bfloat16_rn(r);
    h = __bfloat16_as_ushort(hb);
    l = __bfloat16_as_ushort(lb);
}
__device__ __forceinline__ uint32_t pack2(unsigned short a, unsigned short b) {
    return (uint32_t)a | ((uint32_t)b << 16);
}

// ---------------------------------------------------------------------------
// prep kernels
// ---------------------------------------------------------------------------
__global__ void split_kernel(const float* __restrict__ X,
                             __nv_bfloat16* __restrict__ hi,
                             __nv_bfloat16* __restrict__ lo, int n4)
{
    int i = blockIdx.x * blockDim.x + threadIdx.x;
    if (i >= n4) return;
    float4 x = ((const float4*)X)[i];
    unsigned short h0, h1, h2, h3, l0, l1, l2, l3;
    split1(x.x, h0, l0); split1(x.y, h1, l1);
    split1(x.z, h2, l2); split1(x.w, h3, l3);
    uint2 hv, lv;
    hv.x = pack2(h0, h1); hv.y = pack2(h2, h3);
    lv.x = pack2(l0, l1); lv.y = pack2(l2, l3);
    ((uint2*)hi)[i] = hv;
    ((uint2*)lo)[i] = lv;
}

// Transpose + split: W[K][N] fp32 -> hi/lo [N][K] bf16
__global__ void tsplit_kernel(const float* __restrict__ W,
                              __nv_bfloat16* __restrict__ hi,
                              __nv_bfloat16* __restrict__ lo,
                              int K, int N)
{
    __shared__ float tile[32][33];
    const int n0 = blockIdx.x * 32, k0 = blockIdx.y * 32;
    const int tx = threadIdx.x, ty = threadIdx.y;
#pragma unroll
    for (int i = 0; i < 32; i += 8)
        tile[ty + i][tx] = W[(size_t)(k0 + ty + i) * N + n0 + tx];
    __syncthreads();
#pragma unroll
    for (int i = 0; i < 32; i += 8) {
        float v = tile[tx][ty + i];
        unsigned short h, l;
        split1(v, h, l);
        size_t o = (size_t)(n0 + ty + i) * K + k0 + tx;
        hi[o] = __ushort_as_bfloat16(h);
        lo[o] = __ushort_as_bfloat16(l);
    }
}

// ---------------------------------------------------------------------------
// Pipelined tensor-core split-GEMM, ldmatrix fragments (round-11 proven).
// CTA 128x64, k-tile 32, 2-stage cp.async, 60 KB smem -> 3 CTA/SM.
// ---------------------------------------------------------------------------
#define SA2 40
#define ST2_A (128 * SA2)
#define ST2_B (64 * SA2)
#define STAGE2 (2 * ST2_A + 2 * ST2_B)
#define GM_SMEM_BYTES (2 * STAGE2 * 2)

__global__ __launch_bounds__(256)
void gemm_mma(const __nv_bfloat16* __restrict__ Ahi,
              const __nv_bfloat16* __restrict__ Alo,
              const __nv_bfloat16* __restrict__ Bhi,
              const __nv_bfloat16* __restrict__ Blo,
              const float* __restrict__ bias,
              float* __restrict__ Cf,
              __nv_bfloat16* __restrict__ Chi,
              __nv_bfloat16* __restrict__ Clo,
              int M, int N, int K, int do_gelu)
{
    extern __shared__ __nv_bfloat16 smb[];
    const uint32_t sm_base = smem_u32(smb);

    const int tid = threadIdx.x;
    const int wid = tid >> 5;
    const int lid = tid & 31;
    const int gID = lid >> 2;
    const int t4  = lid & 3;

    const int row0 = blockIdx.y * 128;
    const int col0 = blockIdx.x * 64;
    const int m_off = (wid & 3) * 32;
    const int n_off = (wid >> 2) * 32;

    const int a_ro = ((lid >> 3) & 1) * 8 + (lid & 7);
    const int a_ko = (lid >> 4) * 8;
    const int b_rr = lid & 7;
    const int b_ni = (lid >> 4) & 1;
    const int b_ko = ((lid >> 3) & 1) * 8;

    auto load_stage = [&](int buf, int t) {
        const int kb = t << 5;
        uint32_t base = sm_base + (uint32_t)buf * (STAGE2 * 2);
#pragma unroll
        for (int i = 0; i < 2; i++) {
            int e = tid + i * 256;
            int r = e >> 2, g = e & 3;
            uint32_t ds = (uint32_t)(r * SA2 + g * 8) * 2;
            size_t src = (size_t)(row0 + r) * K + kb + g * 8;
            cp16(base + ds, Ahi + src);
            cp16(base + ST2_A * 2 + ds, Alo + src);
        }
        {
            int r = tid >> 2, g = tid & 3;
            uint32_t ds = (uint32_t)(r * SA2 + g * 8) * 2;
            size_t src = (size_t)(col0 + r) * K + kb + g * 8;
            cp16(base + 2 * ST2_A * 2 + ds, Bhi + src);
            cp16(base + 2 * ST2_A * 2 + ST2_B * 2 + ds, Blo + src);
        }
        cp_commit();
    };

    float acc[2][4][4];
#pragma unroll
    for (int mi = 0; mi < 2; mi++)
#pragma unroll
        for (int ni = 0; ni < 4; ni++)
#pragma unroll
            for (int j = 0; j < 4; j++) acc[mi][ni][j] = 0.f;

    const int nT = K >> 5;
    load_stage(0, 0);

    for (int t = 0; t < nT; t++) {
        const int buf = t & 1;
        if (t + 1 < nT) {
            load_stage(1 - buf, t + 1);
            cp_wait<1>();
        } else {
            cp_wait<0>();
        }
        __syncthreads();

        const uint32_t sA = sm_base + (uint32_t)buf * (STAGE2 * 2);
        const uint32_t sB = sA + 2 * ST2_A * 2;

#pragma unroll
        for (int kk = 0; kk < 32; kk += 16) {
            uint32_t ahi[2][4], alo[2][4], bhi[4][2], blo[4][2];
#pragma unroll
            for (int mi = 0; mi < 2; mi++) {
                uint32_t aaddr = sA +
                    (uint32_t)((m_off + mi * 16 + a_ro) * SA2 + kk + a_ko) * 2;
                ldsm_x4(ahi[mi], aaddr);
                ldsm_x4(alo[mi], aaddr + ST2_A * 2);
            }
#pragma unroll
            for (int p = 0; p < 2; p++) {
                int n = n_off + (p * 2 + b_ni) * 8 + b_rr;
                uint32_t baddr = sB + (uint32_t)(n * SA2 + kk + b_ko) * 2;
                uint32_t r[4];
                ldsm_x4(r, baddr);
                bhi[p * 2][0] = r[0]; bhi[p * 2][1] = r[1];
                bhi[p * 2 + 1][0] = r[2]; bhi[p * 2 + 1][1] = r[3];
                ldsm_x4(r, baddr + ST2_B * 2);
                blo[p * 2][0] = r[0]; blo[p * 2][1] = r[1];
                blo[p * 2 + 1][0] = r[2]; blo[p * 2 + 1][1] = r[3];
            }
#pragma unroll
            for (int mi = 0; mi < 2; mi++)
#pragma unroll
                for (int ni = 0; ni < 4; ni++) {
                    mma16816(acc[mi][ni], ahi[mi], bhi[ni]);
                    mma16816(acc[mi][ni], alo[mi], bhi[ni]);
                    mma16816(acc[mi][ni], ahi[mi], blo[ni]);
                }
        }
        __syncthreads();
    }

    // ---- epilogue ----
#pragma unroll
    for (int mi = 0; mi < 2; mi++) {
#pragma unroll
        for (int ni = 0; ni < 4; ni++) {
            int col = col0 + n_off + ni * 8 + t4 * 2;
            float b0 = bias[col], b1 = bias[col + 1];
#pragma unroll
            for (int half = 0; half < 2; half++) {
                int row = row0 + m_off + mi * 16 + gID + half * 8;
                float v0 = acc[mi][ni][half * 2 + 0] + b0;
                float v1 = acc[mi][ni][half * 2 + 1] + b1;
                if (do_gelu) {
                    v0 = 0.5f * v0 * (1.0f + erff(v0 * 0.70710678118654752f));
                    v1 = 0.5f * v1 * (1.0f + erff(v1 * 0.70710678118654752f));
                }
                size_t o = (size_t)row * N + col;
                if (Cf) {
                    float2 fo; fo.x = v0; fo.y = v1;
                    *(float2*)(Cf + o) = fo;
                }
                if (Chi) {
                    unsigned short h0, h1, l0, l1;
                    split1(v0, h0, l0);
                    split1(v1, h1, l1);
                    *(uint32_t*)(Chi + o) = pack2(h0, h1);
                    *(uint32_t*)(Clo + o) = pack2(l0, l1);
                }
            }
        }
    }
}

// ---------------------------------------------------------------------------
// Tensor-core attention: K+mask pipelined via cp.async, V staged, ldmatrix.
// K bufs: 18432..55296.  mask buf0: dedicated region AT_MK0 (appended);
// mask buf1: Phi+Plo region (dead during phase 1).
// ---------------------------------------------------------------------------
#define AT_SA   72
#define AT_QHI  0
#define AT_QLO  9216
#define AT_K0   18432                 // K buf0 18432.., K buf1 36864..55296
#define AT_SV   36864                 // phase-3 V staging (== K buf1, dead then)
#define AT_PHI  55296                 // phase1: mask buf1; phase3: P hi
#define AT_PLO  64512                 //                      phase3: P lo
#define AT_SS   73728
#define AT_INV  (AT_SS + 64 * 512 * 4)        // 204800
#define AT_MK0  (AT_INV + 256)                // 205056: mask buf0 (16 KB)
#define AT_SMEM (AT_MK0 + 16384)              // 221440

__global__ __launch_bounds__(256)
void attn_mma(const __nv_bfloat16* __restrict__ Qhi_g,
              const __nv_bfloat16* __restrict__ Qlo_g,
              const __nv_bfloat16* __restrict__ Khi_g,
              const __nv_bfloat16* __restrict__ Klo_g,
              const __nv_bfloat16* __restrict__ Vhi_g,
              const __nv_bfloat16* __restrict__ Vlo_g,
              const float* __restrict__ mask,
              __nv_bfloat16* __restrict__ Chi_g,
              __nv_bfloat16* __restrict__ Clo_g)
{
    extern __shared__ char smc[];
    const uint32_t sm_base = smem_u32(smc);
    __nv_bfloat16* Qhi = (__nv_bfloat16*)(smc + AT_QHI);
    __nv_bfloat16* Qlo = (__nv_bfloat16*)(smc + AT_QLO);
    __nv_bfloat16* Phi = (__nv_bfloat16*)(smc + AT_PHI);
    __nv_bfloat16* Plo = (__nv_bfloat16*)(smc + AT_PLO);
    float* Ss   = (float*)(smc + AT_SS);
    float* invs = (float*)(smc + AT_INV);

    const int tid = threadIdx.x;
    const int wid = tid >> 5, lid = tid & 31;
    const int gID = lid >> 2, t4 = lid & 3;
    const int wm = wid & 3, wn = wid >> 2;
    const int q0 = blockIdx.x * 64;
    const int h = blockIdx.y, b = blockIdx.z;
    const size_t hb = ((size_t)b * SEQ) * DMODEL + (size_t)h * HDIM;
    const float* mbase = mask + (size_t)b * SEQ * SEQ;

    const int a_ro = ((lid >> 3) & 1) * 8 + (lid & 7);
    const int a_ko = (lid >> 4) * 8;
    const int b_rr = lid & 7;
    const int b_ni = (lid >> 4) & 1;
    const int b_ko = ((lid >> 3) & 1) * 8;

    // K chunk + mask chunk in ONE commit group (keeps wait<N> semantics)
    auto load_k = [&](int bb, int kc) {
        const int k0 = kc * 64;
        uint32_t kh = sm_base + AT_K0 + (uint32_t)bb * 18432;
        uint32_t kl = kh + 9216;
#pragma unroll
        for (int i = 0; i < 2; i++) {
            int e = tid + i * 256;
            int r = e >> 3, g = e & 7;
            size_t src = hb + (size_t)(k0 + r) * DMODEL + g * 8;
            uint32_t ds = (uint32_t)(r * AT_SA + g * 8) * 2;
            cp16(kh + ds, Khi_g + src);
            cp16(kl + ds, Klo_g + src);
        }
        // mask chunk 64x64 fp32 = 16 KB -> buf bb (MK0 or PHI region)
        uint32_t mb = sm_base + (bb == 0 ? AT_MK0 : AT_PHI);
#pragma unroll
        for (int i = 0; i < 4; i++) {
            int e = tid + i * 256;
            int r = e >> 4, c4 = e & 15;
            cp16(mb + (uint32_t)(r * 64 + c4 * 4) * 4,
                 mbase + (size_t)(q0 + r) * SEQ + k0 + c4 * 4);
        }
        cp_commit();
    };

    auto stage_v = [&](int kc) {
        const int k0 = kc * 64;
        uint32_t sv = sm_base + AT_SV;
#pragma unroll
        for (int i = 0; i < 2; i++) {
            int e = tid + i * 256;
            int r = e >> 3, g = e & 7;
            size_t src = hb + (size_t)(k0 + r) * DMODEL + g * 8;
            uint32_t ds = (uint32_t)(r * 64 + g * 8) * 2;
            cp16(sv + ds, Vhi_g + src);
            cp16(sv + 8192 + ds, Vlo_g + src);
        }
        cp_commit();
    };

    load_k(0, 0);

#pragma unroll
    for (int i = 0; i < 2; i++) {
        int e = tid + i * 256;
        int r = e >> 3, g = e & 7;
        size_t src = hb + (size_t)(q0 + r) * DMODEL + g * 8;
        int ds = r * AT_SA + g * 8;
        *(uint4*)(Qhi + ds) = *(const uint4*)(Qhi_g + src);
        *(uint4*)(Qlo + ds) = *(const uint4*)(Qlo_g + src);
    }

    float pv[4][4];
#pragma unroll
    for (int ni = 0; ni < 4; ni++)
#pragma unroll
        for (int j = 0; j < 4; j++) pv[ni][j] = 0.f;

    const uint32_t uQhi = sm_base + AT_QHI;
    const uint32_t uQlo = sm_base + AT_QLO;
    const uint32_t uPhi = sm_base + AT_PHI;
    const uint32_t uPlo = sm_base + AT_PLO;

    // ---- phase 1: scores ----
    for (int kc = 0; kc < 8; kc++) {
        const int k0 = kc * 64;
        if (kc + 1 < 8) {
            load_k((kc + 1) & 1, kc + 1);
            cp_wait<1>();
        } else {
            cp_wait<0>();
        }
        __syncthreads();

        const uint32_t uKhi = sm_base + AT_K0 + (uint32_t)(kc & 1) * 18432;
        const uint32_t uKlo = uKhi + 9216;
        const float* msm = (const float*)(smc + ((kc & 1) == 0 ? AT_MK0 : AT_PHI));

        float s[4][4];
#pragma unroll
        for (int ni = 0; ni < 4; ni++)
#pragma unroll
            for (int j = 0; j < 4; j++) s[ni][j] = 0.f;

#pragma unroll
        for (int kk = 0; kk < 64; kk += 16) {
            uint32_t ah[4], al[4], bh[4][2], bl[4][2];
            {
                uint32_t aaddr = (uint32_t)((wm * 16 + a_ro) * AT_SA + kk + a_ko) * 2;
                ldsm_x4(ah, uQhi + aaddr);
                ldsm_x4(al, uQlo + aaddr);
            }
#pragma unroll
            for (int p = 0; p < 2; p++) {
                int n = wn * 32 + (p * 2 + b_ni) * 8 + b_rr;
                uint32_t baddr = (uint32_t)(n * AT_SA + kk + b_ko) * 2;
                uint32_t r[4];
                ldsm_x4(r, uKhi + baddr);
                bh[p * 2][0] = r[0]; bh[p * 2][1] = r[1];
                bh[p * 2 + 1][0] = r[2]; bh[p * 2 + 1][1] = r[3];
                ldsm_x4(r, uKlo + baddr);
                bl[p * 2][0] = r[0]; bl[p * 2][1] = r[1];
                bl[p * 2 + 1][0] = r[2]; bl[p * 2 + 1][1] = r[3];
            }
#pragma unroll
            for (int ni = 0; ni < 4; ni++) {
                mma16816(s[ni], ah, bh[ni]);
                mma16816(s[ni], al, bh[ni]);
                mma16816(s[ni], ah, bl[ni]);
            }
        }
#pragma unroll
        for (int ni = 0; ni < 4; ni++) {
            int cl = wn * 32 + ni * 8 + t4 * 2;     // column within chunk
#pragma unroll
            for (int hf = 0; hf < 2; hf++) {
                int row = wm * 16 + gID + hf * 8;
                float2 m2 = *(const float2*)(msm + row * 64 + cl);
                float2 o;
                o.x = s[ni][hf * 2 + 0] * 0.125f + m2.x;
                o.y = s[ni][hf * 2 + 1] * 0.125f + m2.y;
                *(float2*)(Ss + row * 512 + k0 + cl) = o;
            }
        }
        __syncthreads();
    }

    stage_v(0);

    // ---- phase 2: softmax (stores unnormalized exp; invs saved per row) ----
    {
#pragma unroll
        for (int rr = 0; rr < 8; rr++) {
            int r = wid * 8 + rr;
            float* row = Ss + r * 512;
            float4 v[4];
#pragma unroll
            for (int it = 0; it < 4; it++)
                v[it] = *(float4*)(row + it * 128 + lid * 4);
            float m = -1e30f;
#pragma unroll
            for (int it = 0; it < 4; it++)
                m = fmaxf(m, fmaxf(fmaxf(v[it].x, v[it].y), fmaxf(v[it].z, v[it].w)));
#pragma unroll
            for (int off = 16; off; off >>= 1)
                m = fmaxf(m, __shfl_xor_sync(0xffffffffu, m, off));
            float sum = 0.f;
#pragma unroll
            for (int it = 0; it < 4; it++) {
                v[it].x = fast_exp(v[it].x - m);
                v[it].y = fast_exp(v[it].y - m);
                v[it].z = fast_exp(v[it].z - m);
                v[it].w = fast_exp(v[it].w - m);
                sum += v[it].x + v[it].y + v[it].z + v[it].w;
                *(float4*)(row + it * 128 + lid * 4) = v[it];
            }
#pragma unroll
            for (int off = 16; off; off >>= 1)
                sum += __shfl_xor_sync(0xffffffffu, sum, off);
            if (lid == 0) invs[r] = 1.0f / sum;
        }
    }

    // ---- phase 3: P @ V (P unnormalized; normalize at ctx write) ----
    __nv_bfloat16* Vth = (__nv_bfloat16*)(smc + AT_K0);
    __nv_bfloat16* Vtl = Vth + 4608;
    const uint32_t uVth = sm_base + AT_K0;
    const uint32_t uVtl = uVth + 9216;
    const __nv_bfloat16* Svh = (const __nv_bfloat16*)(smc + AT_SV);
    const __nv_bfloat16* Svl = Svh + 4096;
    for (int kc = 0; kc < 8; kc++) {
        const int k0 = kc * 64;
        cp_wait<0>();
        __syncthreads();

        // P chunk: split only (no normalization)
        {
            int r = tid >> 2, c0 = (tid & 3) * 16;
#pragma unroll
            for (int j2 = 0; j2 < 2; j2++) {
                const float* src = Ss + r * 512 + k0 + c0 + j2 * 8;
                float4 a = *(const float4*)(src);
                float4 bq = *(const float4*)(src + 4);
                float vals[8] = {a.x, a.y, a.z, a.w, bq.x, bq.y, bq.z, bq.w};
                unsigned short hh[8], ll[8];
#pragma unroll
                for (int j = 0; j < 8; j++) split1(vals[j], hh[j], ll[j]);
                uint4 hv, lv;
                hv.x = pack2(hh[0], hh[1]); hv.y = pack2(hh[2], hh[3]);
                hv.z = pack2(hh[4], hh[5]); hv.w = pack2(hh[6], hh[7]);
                lv.x = pack2(ll[0], ll[1]); lv.y = pack2(ll[2], ll[3]);
                lv.z = pack2(ll[4], ll[5]); lv.w = pack2(ll[6], ll[7]);
                *(uint4*)(Phi + r * AT_SA + c0 + j2 * 8) = hv;
                *(uint4*)(Plo + r * AT_SA + c0 + j2 * 8) = lv;
            }
        }

        // V chunk: transpose from staging smem
#pragma unroll
        for (int i = 0; i < 4; i++) {
            int e = tid + i * 256;
            int r = e >> 4, c4 = e & 15;
            uint2 hv = *(const uint2*)(Svh + r * 64 + c4 * 4);
            uint2 lv = *(const uint2*)(Svl + r * 64 + c4 * 4);
            int d = c4 * 4;
            Vth[(d + 0) * AT_SA + r] = __ushort_as_bfloat16((unsigned short)(hv.x & 0xffff));
            Vth[(d + 1) * AT_SA + r] = __ushort_as_bfloat16((unsigned short)(hv.x >> 16));
            Vth[(d + 2) * AT_SA + r] = __ushort_as_bfloat16((unsigned short)(hv.y & 0xffff));
            Vth[(d + 3) * AT_SA + r] = __ushort_as_bfloat16((unsigned short)(hv.y >> 16));
            Vtl[(d + 0) * AT_SA + r] = __ushort_as_bfloat16((unsigned short)(lv.x & 0xffff));
            Vtl[(d + 1) * AT_SA + r] = __ushort_as_bfloat16((unsigned short)(lv.x >> 16));
            Vtl[(d + 2) * AT_SA + r] = __ushort_as_bfloat16((unsigned short)(lv.y & 0xffff));
            Vtl[(d + 3) * AT_SA + r] = __ushort_as_bfloat16((unsigned short)(lv.y >> 16));
        }
        __syncthreads();

        if (kc + 1 < 8) stage_v(kc + 1);

#pragma unroll
        for (int kk = 0; kk < 64; kk += 16) {
            uint32_t ah[4], al[4], bh[4][2], bl[4][2];
            {
                uint32_t aaddr = (uint32_t)((wm * 16 + a_ro) * AT_SA + kk + a_ko) * 2;
                ldsm_x4(ah, uPhi + aaddr);
                ldsm_x4(al, uPlo + aaddr);
            }
#pragma unroll
            for (int p = 0; p < 2; p++) {
                int n = wn * 32 + (p * 2 + b_ni) * 8 + b_rr;
                uint32_t baddr = (uint32_t)(n * AT_SA + kk + b_ko) * 2;
                uint32_t r[4];
                ldsm_x4(r, uVth + baddr);
                bh[p * 2][0] = r[0]; bh[p * 2][1] = r[1];
                bh[p * 2 + 1][0] = r[2]; bh[p * 2 + 1][1] = r[3];
                ldsm_x4(r, uVtl + baddr);
                bl[p * 2][0] = r[0]; bl[p * 2][1] = r[1];
                bl[p * 2 + 1][0] = r[2]; bl[p * 2 + 1][1] = r[3];
            }
#pragma unroll
            for (int ni = 0; ni < 4; ni++) {
                mma16816(pv[ni], ah, bh[ni]);
                mma16816(pv[ni], al, bh[ni]);
                mma16816(pv[ni], ah, bl[ni]);
            }
        }
    }

    // ---- write ctx (normalize by invs here) ----
#pragma unroll
    for (int ni = 0; ni < 4; ni++) {
        int d = wn * 32 + ni * 8 + t4 * 2;
#pragma unroll
        for (int hf = 0; hf < 2; hf++) {
            int row = wm * 16 + gID + hf * 8;
            float is = invs[row];
            unsigned short h0, h1, l0, l1;
            split1(pv[ni][hf * 2 + 0] * is, h0, l0);
            split1(pv[ni][hf * 2 + 1] * is, h1, l1);
            size_t o = hb + (size_t)(q0 + row) * DMODEL + d;
            *(uint32_t*)(Chi_g + o) = pack2(h0, h1);
            *(uint32_t*)(Clo_g + o) = pack2(l0, l1);
        }
    }
}

// ---------------------------------------------------------------------------
// LayerNorm + residual: warp per row (round-10 proven).
// ---------------------------------------------------------------------------
__global__ __launch_bounds__(256)
void ln_residual_kernel(const float* __restrict__ y,
                        const float* __restrict__ res,
                        const float* __restrict__ g,
                        const float* __restrict__ bta,
                        float* __restrict__ out,
                        __nv_bfloat16* __restrict__ ohi,
                        __nv_bfloat16* __restrict__ olo)
{
    const int warp = threadIdx.x >> 5;
    const int lane = threadIdx.x & 31;
    const int row  = blockIdx.x * 8 + warp;
    const size_t base = (size_t)row * DMODEL;

    float4 v[4];
    float sum = 0.f;
#pragma unroll
    for (int it = 0; it < 4; it++) {
        int c = lane * 4 + it * 128;
        float4 a = *(const float4*)(y + base + c);
        float4 bb = *(const float4*)(res + base + c);
        v[it].x = a.x + bb.x; v[it].y = a.y + bb.y;
        v[it].z = a.z + bb.z; v[it].w = a.w + bb.w;
        sum += v[it].x + v[it].y + v[it].z + v[it].w;
    }
#pragma unroll
    for (int off = 16; off; off >>= 1)
        sum += __shfl_xor_sync(0xffffffffu, sum, off);
    float mean = sum * (1.0f / 512.0f);

    float var = 0.f;
#pragma unroll
    for (int it = 0; it < 4; it++) {
        v[it].x -= mean; v[it].y -= mean; v[it].z -= mean; v[it].w -= mean;
        var += v[it].x * v[it].x + v[it].y * v[it].y
             + v[it].z * v[it].z + v[it].w * v[it].w;
    }
#pragma unroll
    for (int off = 16; off; off >>= 1)
        var += __shfl_xor_sync(0xffffffffu, var, off);
    float inv = rsqrtf(var * (1.0f / 512.0f) + LN_EPS);

#pragma unroll
    for (int it = 0; it < 4; it++) {
        int c = lane * 4 + it * 128;
        float4 gg = *(const float4*)(g + c);
        float4 bb = *(const float4*)(bta + c);
        float4 o;
        o.x = v[it].x * inv * gg.x + bb.x;
        o.y = v[it].y * inv * gg.y + bb.y;
        o.z = v[it].z * inv * gg.z + bb.z;
        o.w = v[it].w * inv * gg.w + bb.w;
        *(float4*)(out + base + c) = o;
        if (ohi) {
            unsigned short h0, h1, h2, h3, l0, l1, l2, l3;
            split1(o.x, h0, l0); split1(o.y, h1, l1);
            split1(o.z, h2, l2); split1(o.w, h3, l3);
            uint2 hv, lv;
            hv.x = pack2(h0, h1); hv.y = pack2(h2, h3);
            lv.x = pack2(l0, l1); lv.y = pack2(l2, l3);
            *(uint2*)(ohi + base + c) = hv;
            *(uint2*)(olo + base + c) = lv;
        }
    }
}

// ---------------------------------------------------------------------------
// launch
// ---------------------------------------------------------------------------
extern "C" void kernel_launch(void* const* d_in, const int* in_sizes, int n_in,
                              void* d_out, int out_size)
{
    const float* x     = (const float*)d_in[0];
    const float* mask  = (const float*)d_in[1];
    const float* Wq    = (const float*)d_in[2];
    const float* bq    = (const float*)d_in[3];
    const float* Wk    = (const float*)d_in[4];
    const float* bk    = (const float*)d_in[5];
    const float* Wv    = (const float*)d_in[6];
    const float* bv    = (const float*)d_in[7];
    const float* Wo    = (const float*)d_in[8];
    const float* bo    = (const float*)d_in[9];
    const float* ln1g  = (const float*)d_in[10];
    const float* ln1b  = (const float*)d_in[11];
    const float* W1    = (const float*)d_in[12];
    const float* b1    = (const float*)d_in[13];
    const float* W2    = (const float*)d_in[14];
    const float* b2    = (const float*)d_in[15];
    const float* ln2g  = (const float*)d_in[16];
    const float* ln2b  = (const float*)d_in[17];
    float* out = (float*)d_out;

    float *t0, *aln;
    cudaGetSymbolAddress((void**)&t0,  g_t0);
    cudaGetSymbolAddress((void**)&aln, g_attnln);

    __nv_bfloat16 *xhi, *xlo, *qhi, *qlo, *khi, *klo, *vhi, *vlo;
    __nv_bfloat16 *chi, *clo, *ahi, *alo, *fhi, *flo;
    cudaGetSymbolAddress((void**)&xhi, g_xhi);
    cudaGetSymbolAddress((void**)&xlo, g_xlo);
    cudaGetSymbolAddress((void**)&qhi, g_qhi);
    cudaGetSymbolAddress((void**)&qlo, g_qlo);
    cudaGetSymbolAddress((void**)&khi, g_khi);
    cudaGetSymbolAddress((void**)&klo, g_klo);
    cudaGetSymbolAddress((void**)&vhi, g_vhi);
    cudaGetSymbolAddress((void**)&vlo, g_vlo);
    cudaGetSymbolAddress((void**)&chi, g_chi);
    cudaGetSymbolAddress((void**)&clo, g_clo);
    cudaGetSymbolAddress((void**)&ahi, g_ahi);
    cudaGetSymbolAddress((void**)&alo, g_alo);
    cudaGetSymbolAddress((void**)&fhi, g_fhi);
    cudaGetSymbolAddress((void**)&flo, g_flo);

    __nv_bfloat16 *wqh, *wql, *wkh, *wkl, *wvh, *wvl, *woh, *wol, *w1h, *w1l, *w2h, *w2l;
    cudaGetSymbolAddress((void**)&wqh, g_wqhi);
    cudaGetSymbolAddress((void**)&wql, g_wqlo);
    cudaGetSymbolAddress((void**)&wkh, g_wkhi);
    cudaGetSymbolAddress((void**)&wkl, g_wklo);
    cudaGetSymbolAddress((void**)&wvh, g_wvhi);
    cudaGetSymbolAddress((void**)&wvl, g_wvlo);
    cudaGetSymbolAddress((void**)&woh, g_wohi);
    cudaGetSymbolAddress((void**)&wol, g_wolo);
    cudaGetSymbolAddress((void**)&w1h, g_w1hi);
    cudaGetSymbolAddress((void**)&w1l, g_w1lo);
    cudaGetSymbolAddress((void**)&w2h, g_w2hi);
    cudaGetSymbolAddress((void**)&w2l, g_w2lo);

    cudaFuncSetAttribute(attn_mma,
                         cudaFuncAttributeMaxDynamicSharedMemorySize, AT_SMEM);
    cudaFuncSetAttribute(gemm_mma,
                         cudaFuncAttributeMaxDynamicSharedMemorySize, GM_SMEM_BYTES);

    dim3 tb(32, 8);

    // weight transpose + split
    tsplit_kernel<<<dim3(DMODEL / 32, DMODEL / 32), tb>>>(Wq, wqh, wql, DMODEL, DMODEL);
    tsplit_kernel<<<dim3(DMODEL / 32, DMODEL / 32), tb>>>(Wk, wkh, wkl, DMODEL, DMODEL);
    tsplit_kernel<<<dim3(DMODEL / 32, DMODEL / 32), tb>>>(Wv, wvh, wvl, DMODEL, DMODEL);
    tsplit_kernel<<<dim3(DMODEL / 32, DMODEL / 32), tb>>>(Wo, woh, wol, DMODEL, DMODEL);
    tsplit_kernel<<<dim3(DFF / 32, DMODEL / 32), tb>>>(W1, w1h, w1l, DMODEL, DFF);
    tsplit_kernel<<<dim3(DMODEL / 32, DFF / 32), tb>>>(W2, w2h, w2l, DFF, DMODEL);

    // split input x
    {
        int n4 = MTOK * DMODEL / 4;
        split_kernel<<<(n4 + 255) / 256, 256>>>(x, xhi, xlo, n4);
    }

    // QKV projections -> bf16 hi/lo directly
    {
        dim3 grid(DMODEL / 64, MTOK / 128);
        gemm_mma<<<grid, 256, GM_SMEM_BYTES>>>(xhi, xlo, wqh, wql, bq,
                                               nullptr, qhi, qlo,
                                               MTOK, DMODEL, DMODEL, 0);
        gemm_mma<<<grid, 256, GM_SMEM_BYTES>>>(xhi, xlo, wkh, wkl, bk,
                                               nullptr, khi, klo,
                                               MTOK, DMODEL, DMODEL, 0);
        gemm_mma<<<grid, 256, GM_SMEM_BYTES>>>(xhi, xlo, wvh, wvl, bv,
                                               nullptr, vhi, vlo,
                                               MTOK, DMODEL, DMODEL, 0);
    }

    // attention -> ctx bf16 hi/lo
    {
        dim3 grid(SEQ / 64, NHEADS, BATCH);
        attn_mma<<<grid, 256, AT_SMEM>>>(qhi, qlo, khi, klo, vhi, vlo,
                                         mask, chi, clo);
    }

    // output projection + residual LN
    {
        dim3 grid(DMODEL / 64, MTOK / 128);
        gemm_mma<<<grid, 256, GM_SMEM_BYTES>>>(chi, clo, woh, wol, bo,
                                               t0, nullptr, nullptr,
                                               MTOK, DMODEL, DMODEL, 0);
        ln_residual_kernel<<<MTOK / 8, 256>>>(t0, x, ln1g, ln1b, aln, ahi, alo);
    }

    // FFN
    {
        dim3 grid1(DFF / 64, MTOK / 128);
        gemm_mma<<<grid1, 256, GM_SMEM_BYTES>>>(ahi, alo, w1h, w1l, b1,
                                                nullptr, fhi, flo,
                                                MTOK, DFF, DMODEL, 1);
        dim3 grid2(DMODEL / 64, MTOK / 128);
        gemm_mma<<<grid2, 256, GM_SMEM_BYTES>>>(fhi, flo, w2h, w2l, b2,
                                                t0, nullptr, nullptr,
                                                MTOK, DMODEL, DFF, 0);
        ln_residual_kernel<<<MTOK / 8, 256>>>(t0, aln, ln2g, ln2b, out,
                                              nullptr, nullptr);
    }
}

// round 15
// speedup vs baseline: 1.2283x; 1.0885x over previous
#include <cuda_runtime.h>
#include <cuda_bf16.h>
#include <math.h>
#include <stdint.h>

// ---------------------------------------------------------------------------
// Problem dims (fixed)
// ---------------------------------------------------------------------------
#define BATCH   32
#define SEQ     512
#define DMODEL  512
#define NHEADS  8
#define HDIM    64
#define DFF     2048
#define MTOK    (BATCH * SEQ)
#define LN_EPS  1e-12f

// ---------------------------------------------------------------------------
// Scratch (device globals)
// ---------------------------------------------------------------------------
__device__ float g_t0[MTOK * DMODEL];
__device__ float g_attnln[MTOK * DMODEL];

__device__ __nv_bfloat16 g_xhi[MTOK * DMODEL];
__device__ __nv_bfloat16 g_xlo[MTOK * DMODEL];
__device__ __nv_bfloat16 g_qhi[MTOK * DMODEL];
__device__ __nv_bfloat16 g_qlo[MTOK * DMODEL];
__device__ __nv_bfloat16 g_khi[MTOK * DMODEL];
__device__ __nv_bfloat16 g_klo[MTOK * DMODEL];
__device__ __nv_bfloat16 g_vhi[MTOK * DMODEL];
__device__ __nv_bfloat16 g_vlo[MTOK * DMODEL];
__device__ __nv_bfloat16 g_chi[MTOK * DMODEL];
__device__ __nv_bfloat16 g_clo[MTOK * DMODEL];
__device__ __nv_bfloat16 g_ahi[MTOK * DMODEL];
__device__ __nv_bfloat16 g_alo[MTOK * DMODEL];
__device__ __nv_bfloat16 g_fhi[MTOK * DFF];
__device__ __nv_bfloat16 g_flo[MTOK * DFF];

__device__ __nv_bfloat16 g_wqhi[DMODEL * DMODEL];
__device__ __nv_bfloat16 g_wqlo[DMODEL * DMODEL];
__device__ __nv_bfloat16 g_wkhi[DMODEL * DMODEL];
__device__ __nv_bfloat16 g_wklo[DMODEL * DMODEL];
__device__ __nv_bfloat16 g_wvhi[DMODEL * DMODEL];
__device__ __nv_bfloat16 g_wvlo[DMODEL * DMODEL];
__device__ __nv_bfloat16 g_wohi[DMODEL * DMODEL];
__device__ __nv_bfloat16 g_wolo[DMODEL * DMODEL];
__device__ __nv_bfloat16 g_w1hi[DFF * DMODEL];
__device__ __nv_bfloat16 g_w1lo[DFF * DMODEL];
__device__ __nv_bfloat16 g_w2hi[DMODEL * DFF];
__device__ __nv_bfloat16 g_w2lo[DMODEL * DFF];

// ---------------------------------------------------------------------------
// helpers
// ---------------------------------------------------------------------------
__device__ __forceinline__ void mma16816(float* c, const uint32_t* a, const uint32_t* b)
{
    asm volatile(
        "mma.sync.aligned.m16n8k16.row.col.f32.bf16.bf16.f32 "
        "{%0,%1,%2,%3}, {%4,%5,%6,%7}, {%8,%9}, {%0,%1,%2,%3};"
        : "+f"(c[0]), "+f"(c[1]), "+f"(c[2]), "+f"(c[3])
        : "r"(a[0]), "r"(a[1]), "r"(a[2]), "r"(a[3]), "r"(b[0]), "r"(b[1]));
}

__device__ __forceinline__ void ldsm_x4(uint32_t* r, uint32_t addr)
{
    asm volatile(
        "ldmatrix.sync.aligned.m8n8.x4.shared.b16 {%0,%1,%2,%3}, [%4];"
        : "=r"(r[0]), "=r"(r[1]), "=r"(r[2]), "=r"(r[3]) : "r"(addr));
}

__device__ __forceinline__ uint32_t smem_u32(const void* p) {
    uint32_t a;
    asm("{ .reg .u64 t; cvta.to.shared.u64 t, %1; cvt.u32.u64 %0, t; }"
        : "=r"(a) : "l"(p));
    return a;
}

__device__ __forceinline__ void cp16(uint32_t dst, const void* src) {
    asm volatile("cp.async.cg.shared.global [%0], [%1], 16;"
                 :: "r"(dst), "l"(src));
}
__device__ __forceinline__ void cp_commit() {
    asm volatile("cp.async.commit_group;" ::: "memory");
}
template <int N>
__device__ __forceinline__ void cp_wait() {
    asm volatile("cp.async.wait_group %0;" :: "n"(N) : "memory");
}

__device__ __forceinline__ float fast_exp(float x) {
    float y = fmaxf(x * 1.4426950408889634f, -120.0f);
    float n = rintf(y);
    float f = y - n;
    float p = 1.3333558e-3f;
    p = fmaf(p, f, 9.6181291e-3f);
    p = fmaf(p, f, 5.5504109e-2f);
    p = fmaf(p, f, 2.4022651e-1f);
    p = fmaf(p, f, 6.9314718e-1f);
    p = fmaf(p, f, 1.0f);
    return p * __int_as_float(((int)n + 127) << 23);
}

__device__ __forceinline__ void split1(float v, unsigned short& h, unsigned short& l) {
    __nv_bfloat16 hb = __float2bfloat16_rn(v);
    float r = v - __bfloat162float(hb);
    __nv_bfloat16 lb = __float2bfloat16_rn(r);
    h = __bfloat16_as_ushort(hb);
    l = __bfloat16_as_ushort(lb);
}
__device__ __forceinline__ uint32_t pack2(unsigned short a, unsigned short b) {
    return (uint32_t)a | ((uint32_t)b << 16);
}

// per-z pointer set for batched GEMM launches
struct GPtrs {
    const __nv_bfloat16* bhi;
    const __nv_bfloat16* blo;
    const float* bias;
    float* cf;
    __nv_bfloat16* chi;
    __nv_bfloat16* clo;
};

// ---------------------------------------------------------------------------
// prep kernels
// ---------------------------------------------------------------------------
__global__ void split_kernel(const float* __restrict__ X,
                             __nv_bfloat16* __restrict__ hi,
                             __nv_bfloat16* __restrict__ lo, int n4)
{
    int i = blockIdx.x * blockDim.x + threadIdx.x;
    if (i >= n4) return;
    float4 x = ((const float4*)X)[i];
    unsigned short h0, h1, h2, h3, l0, l1, l2, l3;
    split1(x.x, h0, l0); split1(x.y, h1, l1);
    split1(x.z, h2, l2); split1(x.w, h3, l3);
    uint2 hv, lv;
    hv.x = pack2(h0, h1); hv.y = pack2(h2, h3);
    lv.x = pack2(l0, l1); lv.y = pack2(l2, l3);
    ((uint2*)hi)[i] = hv;
    ((uint2*)lo)[i] = lv;
}

// Transpose + split: W[K][N] fp32 -> hi/lo [N][K] bf16
__global__ void tsplit_kernel(const float* __restrict__ W,
                              __nv_bfloat16* __restrict__ hi,
                              __nv_bfloat16* __restrict__ lo,
                              int K, int N)
{
    __shared__ float tile[32][33];
    const int n0 = blockIdx.x * 32, k0 = blockIdx.y * 32;
    const int tx = threadIdx.x, ty = threadIdx.y;
#pragma unroll
    for (int i = 0; i < 32; i += 8)
        tile[ty + i][tx] = W[(size_t)(k0 + ty + i) * N + n0 + tx];
    __syncthreads();
#pragma unroll
    for (int i = 0; i < 32; i += 8) {
        float v = tile[tx][ty + i];
        unsigned short h, l;
        split1(v, h, l);
        size_t o = (size_t)(n0 + ty + i) * K + k0 + tx;
        hi[o] = __ushort_as_bfloat16(h);
        lo[o] = __ushort_as_bfloat16(l);
    }
}

// ---------------------------------------------------------------------------
// Pipelined tensor-core split-GEMM, ldmatrix fragments (round-11 proven).
// CTA 128x64, k-tile 32, 2-stage cp.async, 60 KB smem -> 3 CTA/SM.
// blockIdx.z selects pointer set (z-batched QKV; z=1 otherwise).
// ---------------------------------------------------------------------------
#define SA2 40
#define ST2_A (128 * SA2)
#define ST2_B (64 * SA2)
#define STAGE2 (2 * ST2_A + 2 * ST2_B)
#define GM_SMEM_BYTES (2 * STAGE2 * 2)

__global__ __launch_bounds__(256)
void gemm_mma(const __nv_bfloat16* __restrict__ Ahi,
              const __nv_bfloat16* __restrict__ Alo,
              GPtrs p0, GPtrs p1, GPtrs p2,
              int M, int N, int K, int do_gelu)
{
    const GPtrs& P = (blockIdx.z == 0) ? p0 : (blockIdx.z == 1) ? p1 : p2;
    const __nv_bfloat16* __restrict__ Bhi = P.bhi;
    const __nv_bfloat16* __restrict__ Blo = P.blo;
    const float* __restrict__ bias = P.bias;
    float* __restrict__ Cf = P.cf;
    __nv_bfloat16* __restrict__ Chi = P.chi;
    __nv_bfloat16* __restrict__ Clo = P.clo;

    extern __shared__ __nv_bfloat16 smb[];
    const uint32_t sm_base = smem_u32(smb);

    const int tid = threadIdx.x;
    const int wid = tid >> 5;
    const int lid = tid & 31;
    const int gID = lid >> 2;
    const int t4  = lid & 3;

    const int row0 = blockIdx.y * 128;
    const int col0 = blockIdx.x * 64;
    const int m_off = (wid & 3) * 32;
    const int n_off = (wid >> 2) * 32;

    const int a_ro = ((lid >> 3) & 1) * 8 + (lid & 7);
    const int a_ko = (lid >> 4) * 8;
    const int b_rr = lid & 7;
    const int b_ni = (lid >> 4) & 1;
    const int b_ko = ((lid >> 3) & 1) * 8;

    auto load_stage = [&](int buf, int t) {
        const int kb = t << 5;
        uint32_t base = sm_base + (uint32_t)buf * (STAGE2 * 2);
#pragma unroll
        for (int i = 0; i < 2; i++) {
            int e = tid + i * 256;
            int r = e >> 2, g = e & 3;
            uint32_t ds = (uint32_t)(r * SA2 + g * 8) * 2;
            size_t src = (size_t)(row0 + r) * K + kb + g * 8;
            cp16(base + ds, Ahi + src);
            cp16(base + ST2_A * 2 + ds, Alo + src);
        }
        {
            int r = tid >> 2, g = tid & 3;
            uint32_t ds = (uint32_t)(r * SA2 + g * 8) * 2;
            size_t src = (size_t)(col0 + r) * K + kb + g * 8;
            cp16(base + 2 * ST2_A * 2 + ds, Bhi + src);
            cp16(base + 2 * ST2_A * 2 + ST2_B * 2 + ds, Blo + src);
        }
        cp_commit();
    };

    float acc[2][4][4];
#pragma unroll
    for (int mi = 0; mi < 2; mi++)
#pragma unroll
        for (int ni = 0; ni < 4; ni++)
#pragma unroll
            for (int j = 0; j < 4; j++) acc[mi][ni][j] = 0.f;

    const int nT = K >> 5;
    load_stage(0, 0);

    for (int t = 0; t < nT; t++) {
        const int buf = t & 1;
        if (t + 1 < nT) {
            load_stage(1 - buf, t + 1);
            cp_wait<1>();
        } else {
            cp_wait<0>();
        }
        __syncthreads();

        const uint32_t sA = sm_base + (uint32_t)buf * (STAGE2 * 2);
        const uint32_t sB = sA + 2 * ST2_A * 2;

#pragma unroll
        for (int kk = 0; kk < 32; kk += 16) {
            uint32_t ahi[2][4], alo[2][4], bhi[4][2], blo[4][2];
#pragma unroll
            for (int mi = 0; mi < 2; mi++) {
                uint32_t aaddr = sA +
                    (uint32_t)((m_off + mi * 16 + a_ro) * SA2 + kk + a_ko) * 2;
                ldsm_x4(ahi[mi], aaddr);
                ldsm_x4(alo[mi], aaddr + ST2_A * 2);
            }
#pragma unroll
            for (int p = 0; p < 2; p++) {
                int n = n_off + (p * 2 + b_ni) * 8 + b_rr;
                uint32_t baddr = sB + (uint32_t)(n * SA2 + kk + b_ko) * 2;
                uint32_t r[4];
                ldsm_x4(r, baddr);
                bhi[p * 2][0] = r[0]; bhi[p * 2][1] = r[1];
                bhi[p * 2 + 1][0] = r[2]; bhi[p * 2 + 1][1] = r[3];
                ldsm_x4(r, baddr + ST2_B * 2);
                blo[p * 2][0] = r[0]; blo[p * 2][1] = r[1];
                blo[p * 2 + 1][0] = r[2]; blo[p * 2 + 1][1] = r[3];
            }
#pragma unroll
            for (int mi = 0; mi < 2; mi++)
#pragma unroll
                for (int ni = 0; ni < 4; ni++) {
                    mma16816(acc[mi][ni], ahi[mi], bhi[ni]);
                    mma16816(acc[mi][ni], alo[mi], bhi[ni]);
                    mma16816(acc[mi][ni], ahi[mi], blo[ni]);
                }
        }
        __syncthreads();
    }

    // ---- epilogue ----
#pragma unroll
    for (int mi = 0; mi < 2; mi++) {
#pragma unroll
        for (int ni = 0; ni < 4; ni++) {
            int col = col0 + n_off + ni * 8 + t4 * 2;
            float b0 = bias[col], b1 = bias[col + 1];
#pragma unroll
            for (int half = 0; half < 2; half++) {
                int row = row0 + m_off + mi * 16 + gID + half * 8;
                float v0 = acc[mi][ni][half * 2 + 0] + b0;
                float v1 = acc[mi][ni][half * 2 + 1] + b1;
                if (do_gelu) {
                    v0 = 0.5f * v0 * (1.0f + erff(v0 * 0.70710678118654752f));
                    v1 = 0.5f * v1 * (1.0f + erff(v1 * 0.70710678118654752f));
                }
                size_t o = (size_t)row * N + col;
                if (Cf) {
                    float2 fo; fo.x = v0; fo.y = v1;
                    *(float2*)(Cf + o) = fo;
                }
                if (Chi) {
                    unsigned short h0, h1, l0, l1;
                    split1(v0, h0, l0);
                    split1(v1, h1, l1);
                    *(uint32_t*)(Chi + o) = pack2(h0, h1);
                    *(uint32_t*)(Clo + o) = pack2(l0, l1);
                }
            }
        }
    }
}

// ---------------------------------------------------------------------------
// Tensor-core attention (round-14 proven): K+mask pipelined, V staged,
// ldmatrix fragments, deferred normalization.
// ---------------------------------------------------------------------------
#define AT_SA   72
#define AT_QHI  0
#define AT_QLO  9216
#define AT_K0   18432
#define AT_SV   36864
#define AT_PHI  55296
#define AT_PLO  64512
#define AT_SS   73728
#define AT_INV  (AT_SS + 64 * 512 * 4)
#define AT_MK0  (AT_INV + 256)
#define AT_SMEM (AT_MK0 + 16384)

__global__ __launch_bounds__(256)
void attn_mma(const __nv_bfloat16* __restrict__ Qhi_g,
              const __nv_bfloat16* __restrict__ Qlo_g,
              const __nv_bfloat16* __restrict__ Khi_g,
              const __nv_bfloat16* __restrict__ Klo_g,
              const __nv_bfloat16* __restrict__ Vhi_g,
              const __nv_bfloat16* __restrict__ Vlo_g,
              const float* __restrict__ mask,
              __nv_bfloat16* __restrict__ Chi_g,
              __nv_bfloat16* __restrict__ Clo_g)
{
    extern __shared__ char smc[];
    const uint32_t sm_base = smem_u32(smc);
    __nv_bfloat16* Qhi = (__nv_bfloat16*)(smc + AT_QHI);
    __nv_bfloat16* Qlo = (__nv_bfloat16*)(smc + AT_QLO);
    __nv_bfloat16* Phi = (__nv_bfloat16*)(smc + AT_PHI);
    __nv_bfloat16* Plo = (__nv_bfloat16*)(smc + AT_PLO);
    float* Ss   = (float*)(smc + AT_SS);
    float* invs = (float*)(smc + AT_INV);

    const int tid = threadIdx.x;
    const int wid = tid >> 5, lid = tid & 31;
    const int gID = lid >> 2, t4 = lid & 3;
    const int wm = wid & 3, wn = wid >> 2;
    const int q0 = blockIdx.x * 64;
    const int h = blockIdx.y, b = blockIdx.z;
    const size_t hb = ((size_t)b * SEQ) * DMODEL + (size_t)h * HDIM;
    const float* mbase = mask + (size_t)b * SEQ * SEQ;

    const int a_ro = ((lid >> 3) & 1) * 8 + (lid & 7);
    const int a_ko = (lid >> 4) * 8;
    const int b_rr = lid & 7;
    const int b_ni = (lid >> 4) & 1;
    const int b_ko = ((lid >> 3) & 1) * 8;

    auto load_k = [&](int bb, int kc) {
        const int k0 = kc * 64;
        uint32_t kh = sm_base + AT_K0 + (uint32_t)bb * 18432;
        uint32_t kl = kh + 9216;
#pragma unroll
        for (int i = 0; i < 2; i++) {
            int e = tid + i * 256;
            int r = e >> 3, g = e & 7;
            size_t src = hb + (size_t)(k0 + r) * DMODEL + g * 8;
            uint32_t ds = (uint32_t)(r * AT_SA + g * 8) * 2;
            cp16(kh + ds, Khi_g + src);
            cp16(kl + ds, Klo_g + src);
        }
        uint32_t mb = sm_base + (bb == 0 ? AT_MK0 : AT_PHI);
#pragma unroll
        for (int i = 0; i < 4; i++) {
            int e = tid + i * 256;
            int r = e >> 4, c4 = e & 15;
            cp16(mb + (uint32_t)(r * 64 + c4 * 4) * 4,
                 mbase + (size_t)(q0 + r) * SEQ + k0 + c4 * 4);
        }
        cp_commit();
    };

    auto stage_v = [&](int kc) {
        const int k0 = kc * 64;
        uint32_t sv = sm_base + AT_SV;
#pragma unroll
        for (int i = 0; i < 2; i++) {
            int e = tid + i * 256;
            int r = e >> 3, g = e & 7;
            size_t src = hb + (size_t)(k0 + r) * DMODEL + g * 8;
            uint32_t ds = (uint32_t)(r * 64 + g * 8) * 2;
            cp16(sv + ds, Vhi_g + src);
            cp16(sv + 8192 + ds, Vlo_g + src);
        }
        cp_commit();
    };

    load_k(0, 0);

#pragma unroll
    for (int i = 0; i < 2; i++) {
        int e = tid + i * 256;
        int r = e >> 3, g = e & 7;
        size_t src = hb + (size_t)(q0 + r) * DMODEL + g * 8;
        int ds = r * AT_SA + g * 8;
        *(uint4*)(Qhi + ds) = *(const uint4*)(Qhi_g + src);
        *(uint4*)(Qlo + ds) = *(const uint4*)(Qlo_g + src);
    }

    float pv[4][4];
#pragma unroll
    for (int ni = 0; ni < 4; ni++)
#pragma unroll
        for (int j = 0; j < 4; j++) pv[ni][j] = 0.f;

    const uint32_t uQhi = sm_base + AT_QHI;
    const uint32_t uQlo = sm_base + AT_QLO;
    const uint32_t uPhi = sm_base + AT_PHI;
    const uint32_t uPlo = sm_base + AT_PLO;

    // ---- phase 1: scores ----
    for (int kc = 0; kc < 8; kc++) {
        const int k0 = kc * 64;
        if (kc + 1 < 8) {
            load_k((kc + 1) & 1, kc + 1);
            cp_wait<1>();
        } else {
            cp_wait<0>();
        }
        __syncthreads();

        const uint32_t uKhi = sm_base + AT_K0 + (uint32_t)(kc & 1) * 18432;
        const uint32_t uKlo = uKhi + 9216;
        const float* msm = (const float*)(smc + ((kc & 1) == 0 ? AT_MK0 : AT_PHI));

        float s[4][4];
#pragma unroll
        for (int ni = 0; ni < 4; ni++)
#pragma unroll
            for (int j = 0; j < 4; j++) s[ni][j] = 0.f;

#pragma unroll
        for (int kk = 0; kk < 64; kk += 16) {
            uint32_t ah[4], al[4], bh[4][2], bl[4][2];
            {
                uint32_t aaddr = (uint32_t)((wm * 16 + a_ro) * AT_SA + kk + a_ko) * 2;
                ldsm_x4(ah, uQhi + aaddr);
                ldsm_x4(al, uQlo + aaddr);
            }
#pragma unroll
            for (int p = 0; p < 2; p++) {
                int n = wn * 32 + (p * 2 + b_ni) * 8 + b_rr;
                uint32_t baddr = (uint32_t)(n * AT_SA + kk + b_ko) * 2;
                uint32_t r[4];
                ldsm_x4(r, uKhi + baddr);
                bh[p * 2][0] = r[0]; bh[p * 2][1] = r[1];
                bh[p * 2 + 1][0] = r[2]; bh[p * 2 + 1][1] = r[3];
                ldsm_x4(r, uKlo + baddr);
                bl[p * 2][0] = r[0]; bl[p * 2][1] = r[1];
                bl[p * 2 + 1][0] = r[2]; bl[p * 2 + 1][1] = r[3];
            }
#pragma unroll
            for (int ni = 0; ni < 4; ni++) {
                mma16816(s[ni], ah, bh[ni]);
                mma16816(s[ni], al, bh[ni]);
                mma16816(s[ni], ah, bl[ni]);
            }
        }
#pragma unroll
        for (int ni = 0; ni < 4; ni++) {
            int cl = wn * 32 + ni * 8 + t4 * 2;
#pragma unroll
            for (int hf = 0; hf < 2; hf++) {
                int row = wm * 16 + gID + hf * 8;
                float2 m2 = *(const float2*)(msm + row * 64 + cl);
                float2 o;
                o.x = s[ni][hf * 2 + 0] * 0.125f + m2.x;
                o.y = s[ni][hf * 2 + 1] * 0.125f + m2.y;
                *(float2*)(Ss + row * 512 + k0 + cl) = o;
            }
        }
        __syncthreads();
    }

    stage_v(0);

    // ---- phase 2: softmax (unnormalized exp; invs per row) ----
    {
#pragma unroll
        for (int rr = 0; rr < 8; rr++) {
            int r = wid * 8 + rr;
            float* row = Ss + r * 512;
            float4 v[4];
#pragma unroll
            for (int it = 0; it < 4; it++)
                v[it] = *(float4*)(row + it * 128 + lid * 4);
            float m = -1e30f;
#pragma unroll
            for (int it = 0; it < 4; it++)
                m = fmaxf(m, fmaxf(fmaxf(v[it].x, v[it].y), fmaxf(v[it].z, v[it].w)));
#pragma unroll
            for (int off = 16; off; off >>= 1)
                m = fmaxf(m, __shfl_xor_sync(0xffffffffu, m, off));
            float sum = 0.f;
#pragma unroll
            for (int it = 0; it < 4; it++) {
                v[it].x = fast_exp(v[it].x - m);
                v[it].y = fast_exp(v[it].y - m);
                v[it].z = fast_exp(v[it].z - m);
                v[it].w = fast_exp(v[it].w - m);
                sum += v[it].x + v[it].y + v[it].z + v[it].w;
                *(float4*)(row + it * 128 + lid * 4) = v[it];
            }
#pragma unroll
            for (int off = 16; off; off >>= 1)
                sum += __shfl_xor_sync(0xffffffffu, sum, off);
            if (lid == 0) invs[r] = 1.0f / sum;
        }
    }

    // ---- phase 3: P @ V ----
    __nv_bfloat16* Vth = (__nv_bfloat16*)(smc + AT_K0);
    __nv_bfloat16* Vtl = Vth + 4608;
    const uint32_t uVth = sm_base + AT_K0;
    const uint32_t uVtl = uVth + 9216;
    const __nv_bfloat16* Svh = (const __nv_bfloat16*)(smc + AT_SV);
    const __nv_bfloat16* Svl = Svh + 4096;
    for (int kc = 0; kc < 8; kc++) {
        const int k0 = kc * 64;
        cp_wait<0>();
        __syncthreads();

        // P chunk: split only
        {
            int r = tid >> 2, c0 = (tid & 3) * 16;
#pragma unroll
            for (int j2 = 0; j2 < 2; j2++) {
                const float* src = Ss + r * 512 + k0 + c0 + j2 * 8;
                float4 a = *(const float4*)(src);
                float4 bq = *(const float4*)(src + 4);
                float vals[8] = {a.x, a.y, a.z, a.w, bq.x, bq.y, bq.z, bq.w};
                unsigned short hh[8], ll[8];
#pragma unroll
                for (int j = 0; j < 8; j++) split1(vals[j], hh[j], ll[j]);
                uint4 hv, lv;
                hv.x = pack2(hh[0], hh[1]); hv.y = pack2(hh[2], hh[3]);
                hv.z = pack2(hh[4], hh[5]); hv.w = pack2(hh[6], hh[7]);
                lv.x = pack2(ll[0], ll[1]); lv.y = pack2(ll[2], ll[3]);
                lv.z = pack2(ll[4], ll[5]); lv.w = pack2(ll[6], ll[7]);
                *(uint4*)(Phi + r * AT_SA + c0 + j2 * 8) = hv;
                *(uint4*)(Plo + r * AT_SA + c0 + j2 * 8) = lv;
            }
        }

        // V chunk: transpose from staging smem
#pragma unroll
        for (int i = 0; i < 4; i++) {
            int e = tid + i * 256;
            int r = e >> 4, c4 = e & 15;
            uint2 hv = *(const uint2*)(Svh + r * 64 + c4 * 4);
            uint2 lv = *(const uint2*)(Svl + r * 64 + c4 * 4);
            int d = c4 * 4;
            Vth[(d + 0) * AT_SA + r] = __ushort_as_bfloat16((unsigned short)(hv.x & 0xffff));
            Vth[(d + 1) * AT_SA + r] = __ushort_as_bfloat16((unsigned short)(hv.x >> 16));
            Vth[(d + 2) * AT_SA + r] = __ushort_as_bfloat16((unsigned short)(hv.y & 0xffff));
            Vth[(d + 3) * AT_SA + r] = __ushort_as_bfloat16((unsigned short)(hv.y >> 16));
            Vtl[(d + 0) * AT_SA + r] = __ushort_as_bfloat16((unsigned short)(lv.x & 0xffff));
            Vtl[(d + 1) * AT_SA + r] = __ushort_as_bfloat16((unsigned short)(lv.x >> 16));
            Vtl[(d + 2) * AT_SA + r] = __ushort_as_bfloat16((unsigned short)(lv.y & 0xffff));
            Vtl[(d + 3) * AT_SA + r] = __ushort_as_bfloat16((unsigned short)(lv.y >> 16));
        }
        __syncthreads();

        if (kc + 1 < 8) stage_v(kc + 1);

#pragma unroll
        for (int kk = 0; kk < 64; kk += 16) {
            uint32_t ah[4], al[4], bh[4][2], bl[4][2];
            {
                uint32_t aaddr = (uint32_t)((wm * 16 + a_ro) * AT_SA + kk + a_ko) * 2;
                ldsm_x4(ah, uPhi + aaddr);
                ldsm_x4(al, uPlo + aaddr);
            }
#pragma unroll
            for (int p = 0; p < 2; p++) {
                int n = wn * 32 + (p * 2 + b_ni) * 8 + b_rr;
                uint32_t baddr = (uint32_t)(n * AT_SA + kk + b_ko) * 2;
                uint32_t r[4];
                ldsm_x4(r, uVth + baddr);
                bh[p * 2][0] = r[0]; bh[p * 2][1] = r[1];
                bh[p * 2 + 1][0] = r[2]; bh[p * 2 + 1][1] = r[3];
                ldsm_x4(r, uVtl + baddr);
                bl[p * 2][0] = r[0]; bl[p * 2][1] = r[1];
                bl[p * 2 + 1][0] = r[2]; bl[p * 2 + 1][1] = r[3];
            }
#pragma unroll
            for (int ni = 0; ni < 4; ni++) {
                mma16816(pv[ni], ah, bh[ni]);
                mma16816(pv[ni], al, bh[ni]);
                mma16816(pv[ni], ah, bl[ni]);
            }
        }
    }

    // ---- write ctx (normalize by invs here) ----
#pragma unroll
    for (int ni = 0; ni < 4; ni++) {
        int d = wn * 32 + ni * 8 + t4 * 2;
#pragma unroll
        for (int hf = 0; hf < 2; hf++) {
            int row = wm * 16 + gID + hf * 8;
            float is = invs[row];
            unsigned short h0, h1, l0, l1;
            split1(pv[ni][hf * 2 + 0] * is, h0, l0);
            split1(pv[ni][hf * 2 + 1] * is, h1, l1);
            size_t o = hb + (size_t)(q0 + row) * DMODEL + d;
            *(uint32_t*)(Chi_g + o) = pack2(h0, h1);
            *(uint32_t*)(Clo_g + o) = pack2(l0, l1);
        }
    }
}

// ---------------------------------------------------------------------------
// LayerNorm + residual: warp per row (round-10 proven).
// ---------------------------------------------------------------------------
__global__ __launch_bounds__(256)
void ln_residual_kernel(const float* __restrict__ y,
                        const float* __restrict__ res,
                        const float* __restrict__ g,
                        const float* __restrict__ bta,
                        float* __restrict__ out,
                        __nv_bfloat16* __restrict__ ohi,
                        __nv_bfloat16* __restrict__ olo)
{
    const int warp = threadIdx.x >> 5;
    const int lane = threadIdx.x & 31;
    const int row  = blockIdx.x * 8 + warp;
    const size_t base = (size_t)row * DMODEL;

    float4 v[4];
    float sum = 0.f;
#pragma unroll
    for (int it = 0; it < 4; it++) {
        int c = lane * 4 + it * 128;
        float4 a = *(const float4*)(y + base + c);
        float4 bb = *(const float4*)(res + base + c);
        v[it].x = a.x + bb.x; v[it].y = a.y + bb.y;
        v[it].z = a.z + bb.z; v[it].w = a.w + bb.w;
        sum += v[it].x + v[it].y + v[it].z + v[it].w;
    }
#pragma unroll
    for (int off = 16; off; off >>= 1)
        sum += __shfl_xor_sync(0xffffffffu, sum, off);
    float mean = sum * (1.0f / 512.0f);

    float var = 0.f;
#pragma unroll
    for (int it = 0; it < 4; it++) {
        v[it].x -= mean; v[it].y -= mean; v[it].z -= mean; v[it].w -= mean;
        var += v[it].x * v[it].x + v[it].y * v[it].y
             + v[it].z * v[it].z + v[it].w * v[it].w;
    }
#pragma unroll
    for (int off = 16; off; off >>= 1)
        var += __shfl_xor_sync(0xffffffffu, var, off);
    float inv = rsqrtf(var * (1.0f / 512.0f) + LN_EPS);

#pragma unroll
    for (int it = 0; it < 4; it++) {
        int c = lane * 4 + it * 128;
        float4 gg = *(const float4*)(g + c);
        float4 bb = *(const float4*)(bta + c);
        float4 o;
        o.x = v[it].x * inv * gg.x + bb.x;
        o.y = v[it].y * inv * gg.y + bb.y;
        o.z = v[it].z * inv * gg.z + bb.z;
        o.w = v[it].w * inv * gg.w + bb.w;
        *(float4*)(out + base + c) = o;
        if (ohi) {
            unsigned short h0, h1, h2, h3, l0, l1, l2, l3;
            split1(o.x, h0, l0); split1(o.y, h1, l1);
            split1(o.z, h2, l2); split1(o.w, h3, l3);
            uint2 hv, lv;
            hv.x = pack2(h0, h1); hv.y = pack2(h2, h3);
            lv.x = pack2(l0, l1); lv.y = pack2(l2, l3);
            *(uint2*)(ohi + base + c) = hv;
            *(uint2*)(olo + base + c) = lv;
        }
    }
}

// ---------------------------------------------------------------------------
// launch
// ---------------------------------------------------------------------------
extern "C" void kernel_launch(void* const* d_in, const int* in_sizes, int n_in,
                              void* d_out, int out_size)
{
    const float* x     = (const float*)d_in[0];
    const float* mask  = (const float*)d_in[1];
    const float* Wq    = (const float*)d_in[2];
    const float* bq    = (const float*)d_in[3];
    const float* Wk    = (const float*)d_in[4];
    const float* bk    = (const float*)d_in[5];
    const float* Wv    = (const float*)d_in[6];
    const float* bv    = (const float*)d_in[7];
    const float* Wo    = (const float*)d_in[8];
    const float* bo    = (const float*)d_in[9];
    const float* ln1g  = (const float*)d_in[10];
    const float* ln1b  = (const float*)d_in[11];
    const float* W1    = (const float*)d_in[12];
    const float* b1    = (const float*)d_in[13];
    const float* W2    = (const float*)d_in[14];
    const float* b2    = (const float*)d_in[15];
    const float* ln2g  = (const float*)d_in[16];
    const float* ln2b  = (const float*)d_in[17];
    float* out = (float*)d_out;

    float *t0, *aln;
    cudaGetSymbolAddress((void**)&t0,  g_t0);
    cudaGetSymbolAddress((void**)&aln, g_attnln);

    __nv_bfloat16 *xhi, *xlo, *qhi, *qlo, *khi, *klo, *vhi, *vlo;
    __nv_bfloat16 *chi, *clo, *ahi, *alo, *fhi, *flo;
    cudaGetSymbolAddress((void**)&xhi, g_xhi);
    cudaGetSymbolAddress((void**)&xlo, g_xlo);
    cudaGetSymbolAddress((void**)&qhi, g_qhi);
    cudaGetSymbolAddress((void**)&qlo, g_qlo);
    cudaGetSymbolAddress((void**)&khi, g_khi);
    cudaGetSymbolAddress((void**)&klo, g_klo);
    cudaGetSymbolAddress((void**)&vhi, g_vhi);
    cudaGetSymbolAddress((void**)&vlo, g_vlo);
    cudaGetSymbolAddress((void**)&chi, g_chi);
    cudaGetSymbolAddress((void**)&clo, g_clo);
    cudaGetSymbolAddress((void**)&ahi, g_ahi);
    cudaGetSymbolAddress((void**)&alo, g_alo);
    cudaGetSymbolAddress((void**)&fhi, g_fhi);
    cudaGetSymbolAddress((void**)&flo, g_flo);

    __nv_bfloat16 *wqh, *wql, *wkh, *wkl, *wvh, *wvl, *woh, *wol, *w1h, *w1l, *w2h, *w2l;
    cudaGetSymbolAddress((void**)&wqh, g_wqhi);
    cudaGetSymbolAddress((void**)&wql, g_wqlo);
    cudaGetSymbolAddress((void**)&wkh, g_wkhi);
    cudaGetSymbolAddress((void**)&wkl, g_wklo);
    cudaGetSymbolAddress((void**)&wvh, g_wvhi);
    cudaGetSymbolAddress((void**)&wvl, g_wvlo);
    cudaGetSymbolAddress((void**)&woh, g_wohi);
    cudaGetSymbolAddress((void**)&wol, g_wolo);
    cudaGetSymbolAddress((void**)&w1h, g_w1hi);
    cudaGetSymbolAddress((void**)&w1l, g_w1lo);
    cudaGetSymbolAddress((void**)&w2h, g_w2hi);
    cudaGetSymbolAddress((void**)&w2l, g_w2lo);

    cudaFuncSetAttribute(attn_mma,
                         cudaFuncAttributeMaxDynamicSharedMemorySize, AT_SMEM);
    cudaFuncSetAttribute(gemm_mma,
                         cudaFuncAttributeMaxDynamicSharedMemorySize, GM_SMEM_BYTES);

    dim3 tb(32, 8);

    // weight transpose + split
    tsplit_kernel<<<dim3(DMODEL / 32, DMODEL / 32), tb>>>(Wq, wqh, wql, DMODEL, DMODEL);
    tsplit_kernel<<<dim3(DMODEL / 32, DMODEL / 32), tb>>>(Wk, wkh, wkl, DMODEL, DMODEL);
    tsplit_kernel<<<dim3(DMODEL / 32, DMODEL / 32), tb>>>(Wv, wvh, wvl, DMODEL, DMODEL);
    tsplit_kernel<<<dim3(DMODEL / 32, DMODEL / 32), tb>>>(Wo, woh, wol, DMODEL, DMODEL);
    tsplit_kernel<<<dim3(DFF / 32, DMODEL / 32), tb>>>(W1, w1h, w1l, DMODEL, DFF);
    tsplit_kernel<<<dim3(DMODEL / 32, DFF / 32), tb>>>(W2, w2h, w2l, DFF, DMODEL);

    // split input x
    {
        int n4 = MTOK * DMODEL / 4;
        split_kernel<<<(n4 + 255) / 256, 256>>>(x, xhi, xlo, n4);
    }

    // QKV projections: one z=3 batched launch
    {
        GPtrs pq = {wqh, wql, bq, nullptr, qhi, qlo};
        GPtrs pk = {wkh, wkl, bk, nullptr, khi, klo};
        GPtrs pv = {wvh, wvl, bv, nullptr, vhi, vlo};
        dim3 grid(DMODEL / 64, MTOK / 128, 3);
        gemm_mma<<<grid, 256, GM_SMEM_BYTES>>>(xhi, xlo, pq, pk, pv,
                                               MTOK, DMODEL, DMODEL, 0);
    }

    // attention -> ctx bf16 hi/lo
    {
        dim3 grid(SEQ / 64, NHEADS, BATCH);
        attn_mma<<<grid, 256, AT_SMEM>>>(qhi, qlo, khi, klo, vhi, vlo,
                                         mask, chi, clo);
    }

    // output projection + residual LN
    {
        GPtrs po = {woh, wol, bo, t0, nullptr, nullptr};
        dim3 grid(DMODEL / 64, MTOK / 128, 1);
        gemm_mma<<<grid, 256, GM_SMEM_BYTES>>>(chi, clo, po, po, po,
                                               MTOK, DMODEL, DMODEL, 0);
        ln_residual_kernel<<<MTOK / 8, 256>>>(t0, x, ln1g, ln1b, aln, ahi, alo);
    }

    // FFN
    {
        GPtrs p1 = {w1h, w1l, b1, nullptr, fhi, flo};
        dim3 grid1(DFF / 64, MTOK / 128, 1);
        gemm_mma<<<grid1, 256, GM_SMEM_BYTES>>>(ahi, alo, p1, p1, p1,
                                                MTOK, DFF, DMODEL, 1);
        GPtrs p2 = {w2h, w2l, b2, t0, nullptr, nullptr};
        dim3 grid2(DMODEL / 64, MTOK / 128, 1);
        gemm_mma<<<grid2, 256, GM_SMEM_BYTES>>>(fhi, flo, p2, p2, p2,
                                                MTOK, DMODEL, DFF, 0);
        ln_residual_kernel<<<MTOK / 8, 256>>>(t0, aln, ln2g, ln2b, out,
                                              nullptr, nullptr);
    }
}

// round 16
// speedup vs baseline: 1.4461x; 1.1773x over previous
#include <cuda_runtime.h>
#include <cuda_bf16.h>
#include <math.h>
#include <stdint.h>

// ---------------------------------------------------------------------------
// Problem dims (fixed)
// ---------------------------------------------------------------------------
#define BATCH   32
#define SEQ     512
#define DMODEL  512
#define NHEADS  8
#define HDIM    64
#define DFF     2048
#define MTOK    (BATCH * SEQ)
#define LN_EPS  1e-12f

// ---------------------------------------------------------------------------
// Scratch (device globals)
// ---------------------------------------------------------------------------
__device__ float g_t0[MTOK * DMODEL];
__device__ float g_attnln[MTOK * DMODEL];

__device__ __nv_bfloat16 g_xhi[MTOK * DMODEL];
__device__ __nv_bfloat16 g_xlo[MTOK * DMODEL];
__device__ __nv_bfloat16 g_qhi[MTOK * DMODEL];
__device__ __nv_bfloat16 g_qlo[MTOK * DMODEL];
__device__ __nv_bfloat16 g_khi[MTOK * DMODEL];
__device__ __nv_bfloat16 g_klo[MTOK * DMODEL];
__device__ __nv_bfloat16 g_vhi[MTOK * DMODEL];
__device__ __nv_bfloat16 g_vlo[MTOK * DMODEL];
__device__ __nv_bfloat16 g_chi[MTOK * DMODEL];
__device__ __nv_bfloat16 g_clo[MTOK * DMODEL];
__device__ __nv_bfloat16 g_ahi[MTOK * DMODEL];
__device__ __nv_bfloat16 g_alo[MTOK * DMODEL];
__device__ __nv_bfloat16 g_fhi[MTOK * DFF];
__device__ __nv_bfloat16 g_flo[MTOK * DFF];

__device__ __nv_bfloat16 g_wqhi[DMODEL * DMODEL];
__device__ __nv_bfloat16 g_wqlo[DMODEL * DMODEL];
__device__ __nv_bfloat16 g_wkhi[DMODEL * DMODEL];
__device__ __nv_bfloat16 g_wklo[DMODEL * DMODEL];
__device__ __nv_bfloat16 g_wvhi[DMODEL * DMODEL];
__device__ __nv_bfloat16 g_wvlo[DMODEL * DMODEL];
__device__ __nv_bfloat16 g_wohi[DMODEL * DMODEL];
__device__ __nv_bfloat16 g_wolo[DMODEL * DMODEL];
__device__ __nv_bfloat16 g_w1hi[DFF * DMODEL];
__device__ __nv_bfloat16 g_w1lo[DFF * DMODEL];
__device__ __nv_bfloat16 g_w2hi[DMODEL * DFF];
__device__ __nv_bfloat16 g_w2lo[DMODEL * DFF];

// ---------------------------------------------------------------------------
// helpers
// ---------------------------------------------------------------------------
__device__ __forceinline__ void mma16816(float* c, const uint32_t* a, const uint32_t* b)
{
    asm volatile(
        "mma.sync.aligned.m16n8k16.row.col.f32.bf16.bf16.f32 "
        "{%0,%1,%2,%3}, {%4,%5,%6,%7}, {%8,%9}, {%0,%1,%2,%3};"
        : "+f"(c[0]), "+f"(c[1]), "+f"(c[2]), "+f"(c[3])
        : "r"(a[0]), "r"(a[1]), "r"(a[2]), "r"(a[3]), "r"(b[0]), "r"(b[1]));
}

__device__ __forceinline__ void ldsm_x4(uint32_t* r, uint32_t addr)
{
    asm volatile(
        "ldmatrix.sync.aligned.m8n8.x4.shared.b16 {%0,%1,%2,%3}, [%4];"
        : "=r"(r[0]), "=r"(r[1]), "=r"(r[2]), "=r"(r[3]) : "r"(addr));
}

__device__ __forceinline__ uint32_t smem_u32(const void* p) {
    uint32_t a;
    asm("{ .reg .u64 t; cvta.to.shared.u64 t, %1; cvt.u32.u64 %0, t; }"
        : "=r"(a) : "l"(p));
    return a;
}

__device__ __forceinline__ void cp16(uint32_t dst, const void* src) {
    asm volatile("cp.async.cg.shared.global [%0], [%1], 16;"
                 :: "r"(dst), "l"(src));
}
__device__ __forceinline__ void cp_commit() {
    asm volatile("cp.async.commit_group;" ::: "memory");
}
template <int N>
__device__ __forceinline__ void cp_wait() {
    asm volatile("cp.async.wait_group %0;" :: "n"(N) : "memory");
}

__device__ __forceinline__ float fast_exp(float x) {
    float y = fmaxf(x * 1.4426950408889634f, -120.0f);
    float n = rintf(y);
    float f = y - n;
    float p = 1.3333558e-3f;
    p = fmaf(p, f, 9.6181291e-3f);
    p = fmaf(p, f, 5.5504109e-2f);
    p = fmaf(p, f, 2.4022651e-1f);
    p = fmaf(p, f, 6.9314718e-1f);
    p = fmaf(p, f, 1.0f);
    return p * __int_as_float(((int)n + 127) << 23);
}

__device__ __forceinline__ void split1(float v, unsigned short& h, unsigned short& l) {
    __nv_bfloat16 hb = __float2bfloat16_rn(v);
    float r = v - __bfloat162float(hb);
    __nv_bfloat16 lb = __float2bfloat16_rn(r);
    h = __bfloat16_as_ushort(hb);
    l = __bfloat16_as_ushort(lb);
}
__device__ __forceinline__ uint32_t pack2(unsigned short a, unsigned short b) {
    return (uint32_t)a | ((uint32_t)b << 16);
}

// per-z pointer set for batched GEMM launches
struct GPtrs {
    const __nv_bfloat16* bhi;
    const __nv_bfloat16* blo;
    const float* bias;
    float* cf;
    __nv_bfloat16* chi;
    __nv_bfloat16* clo;
};

// ---------------------------------------------------------------------------
// prep kernels
// ---------------------------------------------------------------------------
__global__ void split_kernel(const float* __restrict__ X,
                             __nv_bfloat16* __restrict__ hi,
                             __nv_bfloat16* __restrict__ lo, int n4)
{
    int i = blockIdx.x * blockDim.x + threadIdx.x;
    if (i >= n4) return;
    float4 x = ((const float4*)X)[i];
    unsigned short h0, h1, h2, h3, l0, l1, l2, l3;
    split1(x.x, h0, l0); split1(x.y, h1, l1);
    split1(x.z, h2, l2); split1(x.w, h3, l3);
    uint2 hv, lv;
    hv.x = pack2(h0, h1); hv.y = pack2(h2, h3);
    lv.x = pack2(l0, l1); lv.y = pack2(l2, l3);
    ((uint2*)hi)[i] = hv;
    ((uint2*)lo)[i] = lv;
}

// Transpose + split: W[K][N] fp32 -> hi/lo [N][K] bf16
__global__ void tsplit_kernel(const float* __restrict__ W,
                              __nv_bfloat16* __restrict__ hi,
                              __nv_bfloat16* __restrict__ lo,
                              int K, int N)
{
    __shared__ float tile[32][33];
    const int n0 = blockIdx.x * 32, k0 = blockIdx.y * 32;
    const int tx = threadIdx.x, ty = threadIdx.y;
#pragma unroll
    for (int i = 0; i < 32; i += 8)
        tile[ty + i][tx] = W[(size_t)(k0 + ty + i) * N + n0 + tx];
    __syncthreads();
#pragma unroll
    for (int i = 0; i < 32; i += 8) {
        float v = tile[tx][ty + i];
        unsigned short h, l;
        split1(v, h, l);
        size_t o = (size_t)(n0 + ty + i) * K + k0 + tx;
        hi[o] = __ushort_as_bfloat16(h);
        lo[o] = __ushort_as_bfloat16(l);
    }
}

// ---------------------------------------------------------------------------
// Pipelined tensor-core split-GEMM (round-15 winner, unchanged).
// ---------------------------------------------------------------------------
#define SA2 40
#define ST2_A (128 * SA2)
#define ST2_B (64 * SA2)
#define STAGE2 (2 * ST2_A + 2 * ST2_B)
#define GM_SMEM_BYTES (2 * STAGE2 * 2)

__global__ __launch_bounds__(256)
void gemm_mma(const __nv_bfloat16* __restrict__ Ahi,
              const __nv_bfloat16* __restrict__ Alo,
              GPtrs p0, GPtrs p1, GPtrs p2,
              int M, int N, int K, int do_gelu)
{
    const GPtrs& P = (blockIdx.z == 0) ? p0 : (blockIdx.z == 1) ? p1 : p2;
    const __nv_bfloat16* __restrict__ Bhi = P.bhi;
    const __nv_bfloat16* __restrict__ Blo = P.blo;
    const float* __restrict__ bias = P.bias;
    float* __restrict__ Cf = P.cf;
    __nv_bfloat16* __restrict__ Chi = P.chi;
    __nv_bfloat16* __restrict__ Clo = P.clo;

    extern __shared__ __nv_bfloat16 smb[];
    const uint32_t sm_base = smem_u32(smb);

    const int tid = threadIdx.x;
    const int wid = tid >> 5;
    const int lid = tid & 31;
    const int gID = lid >> 2;
    const int t4  = lid & 3;

    const int row0 = blockIdx.y * 128;
    const int col0 = blockIdx.x * 64;
    const int m_off = (wid & 3) * 32;
    const int n_off = (wid >> 2) * 32;

    const int a_ro = ((lid >> 3) & 1) * 8 + (lid & 7);
    const int a_ko = (lid >> 4) * 8;
    const int b_rr = lid & 7;
    const int b_ni = (lid >> 4) & 1;
    const int b_ko = ((lid >> 3) & 1) * 8;

    auto load_stage = [&](int buf, int t) {
        const int kb = t << 5;
        uint32_t base = sm_base + (uint32_t)buf * (STAGE2 * 2);
#pragma unroll
        for (int i = 0; i < 2; i++) {
            int e = tid + i * 256;
            int r = e >> 2, g = e & 3;
            uint32_t ds = (uint32_t)(r * SA2 + g * 8) * 2;
            size_t src = (size_t)(row0 + r) * K + kb + g * 8;
            cp16(base + ds, Ahi + src);
            cp16(base + ST2_A * 2 + ds, Alo + src);
        }
        {
            int r = tid >> 2, g = tid & 3;
            uint32_t ds = (uint32_t)(r * SA2 + g * 8) * 2;
            size_t src = (size_t)(col0 + r) * K + kb + g * 8;
            cp16(base + 2 * ST2_A * 2 + ds, Bhi + src);
            cp16(base + 2 * ST2_A * 2 + ST2_B * 2 + ds, Blo + src);
        }
        cp_commit();
    };

    float acc[2][4][4];
#pragma unroll
    for (int mi = 0; mi < 2; mi++)
#pragma unroll
        for (int ni = 0; ni < 4; ni++)
#pragma unroll
            for (int j = 0; j < 4; j++) acc[mi][ni][j] = 0.f;

    const int nT = K >> 5;
    load_stage(0, 0);

    for (int t = 0; t < nT; t++) {
        const int buf = t & 1;
        if (t + 1 < nT) {
            load_stage(1 - buf, t + 1);
            cp_wait<1>();
        } else {
            cp_wait<0>();
        }
        __syncthreads();

        const uint32_t sA = sm_base + (uint32_t)buf * (STAGE2 * 2);
        const uint32_t sB = sA + 2 * ST2_A * 2;

#pragma unroll
        for (int kk = 0; kk < 32; kk += 16) {
            uint32_t ahi[2][4], alo[2][4], bhi[4][2], blo[4][2];
#pragma unroll
            for (int mi = 0; mi < 2; mi++) {
                uint32_t aaddr = sA +
                    (uint32_t)((m_off + mi * 16 + a_ro) * SA2 + kk + a_ko) * 2;
                ldsm_x4(ahi[mi], aaddr);
                ldsm_x4(alo[mi], aaddr + ST2_A * 2);
            }
#pragma unroll
            for (int p = 0; p < 2; p++) {
                int n = n_off + (p * 2 + b_ni) * 8 + b_rr;
                uint32_t baddr = sB + (uint32_t)(n * SA2 + kk + b_ko) * 2;
                uint32_t r[4];
                ldsm_x4(r, baddr);
                bhi[p * 2][0] = r[0]; bhi[p * 2][1] = r[1];
                bhi[p * 2 + 1][0] = r[2]; bhi[p * 2 + 1][1] = r[3];
                ldsm_x4(r, baddr + ST2_B * 2);
                blo[p * 2][0] = r[0]; blo[p * 2][1] = r[1];
                blo[p * 2 + 1][0] = r[2]; blo[p * 2 + 1][1] = r[3];
            }
#pragma unroll
            for (int mi = 0; mi < 2; mi++)
#pragma unroll
                for (int ni = 0; ni < 4; ni++) {
                    mma16816(acc[mi][ni], ahi[mi], bhi[ni]);
                    mma16816(acc[mi][ni], alo[mi], bhi[ni]);
                    mma16816(acc[mi][ni], ahi[mi], blo[ni]);
                }
        }
        __syncthreads();
    }

#pragma unroll
    for (int mi = 0; mi < 2; mi++) {
#pragma unroll
        for (int ni = 0; ni < 4; ni++) {
            int col = col0 + n_off + ni * 8 + t4 * 2;
            float b0 = bias[col], b1 = bias[col + 1];
#pragma unroll
            for (int half = 0; half < 2; half++) {
                int row = row0 + m_off + mi * 16 + gID + half * 8;
                float v0 = acc[mi][ni][half * 2 + 0] + b0;
                float v1 = acc[mi][ni][half * 2 + 1] + b1;
                if (do_gelu) {
                    v0 = 0.5f * v0 * (1.0f + erff(v0 * 0.70710678118654752f));
                    v1 = 0.5f * v1 * (1.0f + erff(v1 * 0.70710678118654752f));
                }
                size_t o = (size_t)row * N + col;
                if (Cf) {
                    float2 fo; fo.x = v0; fo.y = v1;
                    *(float2*)(Cf + o) = fo;
                }
                if (Chi) {
                    unsigned short h0, h1, l0, l1;
                    split1(v0, h0, l0);
                    split1(v1, h1, l1);
                    *(uint32_t*)(Chi + o) = pack2(h0, h1);
                    *(uint32_t*)(Clo + o) = pack2(l0, l1);
                }
            }
        }
    }
}

// ---------------------------------------------------------------------------
// Flash attention: CTA = 128 q-rows x (head, batch). 8 warps x 16 full rows.
// Online softmax; P fragments reused in-register; K+mask and V cp.async
// double-buffered (alternating commit groups, wait<2>).
// ---------------------------------------------------------------------------
#define AT_SA   72
#define FQ_HI   0                        // 128*72*2 = 18432
#define FQ_LO   18432
#define FK0     36864                    // K buf b at +b*18432 (hi 9216, lo 9216)
#define FMK     73728                    // mask buf b at +b*32768 (128x64 fp32)
#define FSV     139264                   // V staging buf b at +b*16384
#define FVT     172032                   // Vt hi 9216, lo 9216
#define AT_SMEM 190464

__global__ __launch_bounds__(256)
void attn_mma(const __nv_bfloat16* __restrict__ Qhi_g,
              const __nv_bfloat16* __restrict__ Qlo_g,
              const __nv_bfloat16* __restrict__ Khi_g,
              const __nv_bfloat16* __restrict__ Klo_g,
              const __nv_bfloat16* __restrict__ Vhi_g,
              const __nv_bfloat16* __restrict__ Vlo_g,
              const float* __restrict__ mask,
              __nv_bfloat16* __restrict__ Chi_g,
              __nv_bfloat16* __restrict__ Clo_g)
{
    extern __shared__ char smc[];
    const uint32_t sm_base = smem_u32(smc);

    const int tid = threadIdx.x;
    const int wid = tid >> 5, lid = tid & 31;
    const int gID = lid >> 2, t4 = lid & 3;
    const int q0 = blockIdx.x * 128;
    const int h = blockIdx.y, b = blockIdx.z;
    const size_t hb = ((size_t)b * SEQ) * DMODEL + (size_t)h * HDIM;
    const float* mbase = mask + (size_t)b * SEQ * SEQ;

    const int a_ro = ((lid >> 3) & 1) * 8 + (lid & 7);
    const int a_ko = (lid >> 4) * 8;
    const int b_rr = lid & 7;
    const int b_ni = (lid >> 4) & 1;
    const int b_ko = ((lid >> 3) & 1) * 8;

    // K chunk (64xHDIM hi/lo) + mask chunk (128x64 fp32) in one commit group
    auto load_k = [&](int bb, int kc) {
        const int k0 = kc * 64;
        uint32_t kh = sm_base + FK0 + (uint32_t)bb * 18432;
        uint32_t kl = kh + 9216;
#pragma unroll
        for (int i = 0; i < 2; i++) {
            int e = tid + i * 256;
            int r = e >> 3, g = e & 7;
            size_t src = hb + (size_t)(k0 + r) * DMODEL + g * 8;
            uint32_t ds = (uint32_t)(r * AT_SA + g * 8) * 2;
            cp16(kh + ds, Khi_g + src);
            cp16(kl + ds, Klo_g + src);
        }
        uint32_t mb = sm_base + FMK + (uint32_t)bb * 32768;
#pragma unroll
        for (int i = 0; i < 8; i++) {
            int e = tid + i * 256;
            int r = e >> 4, c4 = e & 15;
            cp16(mb + (uint32_t)(r * 64 + c4 * 4) * 4,
                 mbase + (size_t)(q0 + r) * SEQ + k0 + c4 * 4);
        }
        cp_commit();
    };

    // V chunk staging (row-major, hi/lo) in its own commit group
    auto stage_v = [&](int bb, int kc) {
        const int k0 = kc * 64;
        uint32_t sv = sm_base + FSV + (uint32_t)bb * 16384;
#pragma unroll
        for (int i = 0; i < 2; i++) {
            int e = tid + i * 256;
            int r = e >> 3, g = e & 7;
            size_t src = hb + (size_t)(k0 + r) * DMODEL + g * 8;
            uint32_t ds = (uint32_t)(r * 64 + g * 8) * 2;
            cp16(sv + ds, Vhi_g + src);
            cp16(sv + 8192 + ds, Vlo_g + src);
        }
        cp_commit();
    };

    load_k(0, 0);
    stage_v(0, 0);

    // load Q tile 128x64 hi/lo (direct copy)
    {
        __nv_bfloat16* Qh = (__nv_bfloat16*)(smc + FQ_HI);
        __nv_bfloat16* Ql = (__nv_bfloat16*)(smc + FQ_LO);
#pragma unroll
        for (int i = 0; i < 4; i++) {
            int e = tid + i * 256;
            int r = e >> 3, g = e & 7;
            size_t src = hb + (size_t)(q0 + r) * DMODEL + g * 8;
            int ds = r * AT_SA + g * 8;
            *(uint4*)(Qh + ds) = *(const uint4*)(Qhi_g + src);
            *(uint4*)(Ql + ds) = *(const uint4*)(Qlo_g + src);
        }
    }

    float pv[8][4];
#pragma unroll
    for (int ni = 0; ni < 8; ni++)
#pragma unroll
        for (int j = 0; j < 4; j++) pv[ni][j] = 0.f;
    float m_run[2] = {-1e30f, -1e30f};
    float l_run[2] = {0.f, 0.f};

    const uint32_t uQhi = sm_base + FQ_HI;
    const uint32_t uQlo = sm_base + FQ_LO;
    const uint32_t uVth = sm_base + FVT;
    const uint32_t uVtl = uVth + 9216;
    __nv_bfloat16* Vth = (__nv_bfloat16*)(smc + FVT);
    __nv_bfloat16* Vtl = Vth + 4608;

    for (int kc = 0; kc < 8; kc++) {
        const int bb = kc & 1;
        if (kc + 1 < 8) {
            load_k(1 - bb, kc + 1);
            stage_v(1 - bb, kc + 1);
            cp_wait<2>();
        } else {
            cp_wait<0>();
        }
        __syncthreads();   // K/mask/V(kc) visible; prior Vt reads complete

        const uint32_t uKhi = sm_base + FK0 + (uint32_t)bb * 18432;
        const uint32_t uKlo = uKhi + 9216;
        const float* msm = (const float*)(smc + FMK + (size_t)bb * 32768);

        // ---- QK^T for this chunk: s[8][4] over 16 rows x 64 cols ----
        float s[8][4];
#pragma unroll
        for (int ni = 0; ni < 8; ni++)
#pragma unroll
            for (int j = 0; j < 4; j++) s[ni][j] = 0.f;

#pragma unroll
        for (int kk = 0; kk < 64; kk += 16) {
            uint32_t ah[4], al[4];
            {
                uint32_t aaddr = (uint32_t)((wid * 16 + a_ro) * AT_SA + kk + a_ko) * 2;
                ldsm_x4(ah, uQhi + aaddr);
                ldsm_x4(al, uQlo + aaddr);
            }
#pragma unroll
            for (int p = 0; p < 4; p++) {
                int n = (p * 2 + b_ni) * 8 + b_rr;
                uint32_t baddr = (uint32_t)(n * AT_SA + kk + b_ko) * 2;
                uint32_t r[4], r2[4];
                ldsm_x4(r, uKhi + baddr);
                ldsm_x4(r2, uKlo + baddr);
                uint32_t bh0[2] = {r[0], r[1]}, bh1[2] = {r[2], r[3]};
                uint32_t bl0[2] = {r2[0], r2[1]}, bl1[2] = {r2[2], r2[3]};
                mma16816(s[p * 2], ah, bh0);
                mma16816(s[p * 2], al, bh0);
                mma16816(s[p * 2], ah, bl0);
                mma16816(s[p * 2 + 1], ah, bh1);
                mma16816(s[p * 2 + 1], al, bh1);
                mma16816(s[p * 2 + 1], ah, bl1);
            }
        }

        // scale + mask (mask smem rows are CTA-local 0..127)
#pragma unroll
        for (int ni = 0; ni < 8; ni++) {
            int cl = ni * 8 + t4 * 2;
#pragma unroll
            for (int hf = 0; hf < 2; hf++) {
                int row = wid * 16 + gID + hf * 8;
                float2 m2 = *(const float2*)(msm + row * 64 + cl);
                s[ni][hf * 2 + 0] = s[ni][hf * 2 + 0] * 0.125f + m2.x;
                s[ni][hf * 2 + 1] = s[ni][hf * 2 + 1] * 0.125f + m2.y;
            }
        }

        // ---- online softmax update (rows owned entirely by this warp) ----
        float scale0, scale1;
        {
#pragma unroll
            for (int hf = 0; hf < 2; hf++) {
                float mc = -1e30f;
#pragma unroll
                for (int ni = 0; ni < 8; ni++) {
                    mc = fmaxf(mc, fmaxf(s[ni][hf * 2], s[ni][hf * 2 + 1]));
                }
                mc = fmaxf(mc, __shfl_xor_sync(0xffffffffu, mc, 1));
                mc = fmaxf(mc, __shfl_xor_sync(0xffffffffu, mc, 2));
                float m_new = fmaxf(m_run[hf], mc);
                float sc = fast_exp(m_run[hf] - m_new);
                float sum = 0.f;
#pragma unroll
                for (int ni = 0; ni < 8; ni++) {
                    float e0 = fast_exp(s[ni][hf * 2] - m_new);
                    float e1 = fast_exp(s[ni][hf * 2 + 1] - m_new);
                    s[ni][hf * 2] = e0;
                    s[ni][hf * 2 + 1] = e1;
                    sum += e0 + e1;
                }
                sum += __shfl_xor_sync(0xffffffffu, sum, 1);
                sum += __shfl_xor_sync(0xffffffffu, sum, 2);
                l_run[hf] = l_run[hf] * sc + sum;
                m_run[hf] = m_new;
                if (hf == 0) scale0 = sc; else scale1 = sc;
            }
#pragma unroll
            for (int ni = 0; ni < 8; ni++) {
                pv[ni][0] *= scale0; pv[ni][1] *= scale0;
                pv[ni][2] *= scale1; pv[ni][3] *= scale1;
            }
        }

        // ---- convert P accumulator regs -> A fragments in-register ----
        uint32_t ph[4][4], pl[4][4];
#pragma unroll
        for (int c = 0; c < 4; c++) {
            unsigned short h0, h1, l0, l1;
#pragma unroll
            for (int half = 0; half < 2; half++) {
                int ni = 2 * c + half;   // half=0 -> klow (a0,a1), half=1 -> khigh (a2,a3)
                split1(s[ni][0], h0, l0);
                split1(s[ni][1], h1, l1);
                ph[c][half * 2 + 0] = pack2(h0, h1);
                pl[c][half * 2 + 0] = pack2(l0, l1);
                split1(s[ni][2], h0, l0);
                split1(s[ni][3], h1, l1);
                ph[c][half * 2 + 1] = pack2(h0, h1);
                pl[c][half * 2 + 1] = pack2(l0, l1);
            }
        }

        // ---- transpose V(kc) from staging to Vt ----
        {
            const __nv_bfloat16* Svh = (const __nv_bfloat16*)(smc + FSV + (size_t)bb * 16384);
            const __nv_bfloat16* Svl = Svh + 4096;
#pragma unroll
            for (int i = 0; i < 4; i++) {
                int e = tid + i * 256;
                int r = e >> 4, c4 = e & 15;
                uint2 hv = *(const uint2*)(Svh + r * 64 + c4 * 4);
                uint2 lv = *(const uint2*)(Svl + r * 64 + c4 * 4);
                int d = c4 * 4;
                Vth[(d + 0) * AT_SA + r] = __ushort_as_bfloat16((unsigned short)(hv.x & 0xffff));
                Vth[(d + 1) * AT_SA + r] = __ushort_as_bfloat16((unsigned short)(hv.x >> 16));
                Vth[(d + 2) * AT_SA + r] = __ushort_as_bfloat16((unsigned short)(hv.y & 0xffff));
                Vth[(d + 3) * AT_SA + r] = __ushort_as_bfloat16((unsigned short)(hv.y >> 16));
                Vtl[(d + 0) * AT_SA + r] = __ushort_as_bfloat16((unsigned short)(lv.x & 0xffff));
                Vtl[(d + 1) * AT_SA + r] = __ushort_as_bfloat16((unsigned short)(lv.x >> 16));
                Vtl[(d + 2) * AT_SA + r] = __ushort_as_bfloat16((unsigned short)(lv.y & 0xffff));
                Vtl[(d + 3) * AT_SA + r] = __ushort_as_bfloat16((unsigned short)(lv.y >> 16));
            }
        }
        __syncthreads();   // Vt complete before P@V reads

        // ---- pv += P @ V(kc) ----
#pragma unroll
        for (int c = 0; c < 4; c++) {     // contraction chunk (score cols 16c..)
            int kk = c * 16;
#pragma unroll
            for (int p = 0; p < 4; p++) {
                int n = (p * 2 + b_ni) * 8 + b_rr;
                uint32_t baddr = (uint32_t)(n * AT_SA + kk + b_ko) * 2;
                uint32_t r[4], r2[4];
                ldsm_x4(r, uVth + baddr);
                ldsm_x4(r2, uVtl + baddr);
                uint32_t bh0[2] = {r[0], r[1]}, bh1[2] = {r[2], r[3]};
                uint32_t bl0[2] = {r2[0], r2[1]}, bl1[2] = {r2[2], r2[3]};
                mma16816(pv[p * 2], ph[c], bh0);
                mma16816(pv[p * 2], pl[c], bh0);
                mma16816(pv[p * 2], ph[c], bl0);
                mma16816(pv[p * 2 + 1], ph[c], bh1);
                mma16816(pv[p * 2 + 1], pl[c], bh1);
                mma16816(pv[p * 2 + 1], ph[c], bl1);
            }
        }
    }

    // ---- write ctx (normalize by running sums) ----
    float is0 = 1.0f / l_run[0];
    float is1 = 1.0f / l_run[1];
#pragma unroll
    for (int ni = 0; ni < 8; ni++) {
        int d = ni * 8 + t4 * 2;
#pragma unroll
        for (int hf = 0; hf < 2; hf++) {
            int row = wid * 16 + gID + hf * 8;
            float is = (hf == 0) ? is0 : is1;
            unsigned short h0, h1, l0, l1;
            split1(pv[ni][hf * 2 + 0] * is, h0, l0);
            split1(pv[ni][hf * 2 + 1] * is, h1, l1);
            size_t o = hb + (size_t)(q0 + row) * DMODEL + d;
            *(uint32_t*)(Chi_g + o) = pack2(h0, h1);
            *(uint32_t*)(Clo_g + o) = pack2(l0, l1);
        }
    }
}

// ---------------------------------------------------------------------------
// LayerNorm + residual: warp per row (round-10 proven).
// ---------------------------------------------------------------------------
__global__ __launch_bounds__(256)
void ln_residual_kernel(const float* __restrict__ y,
                        const float* __restrict__ res,
                        const float* __restrict__ g,
                        const float* __restrict__ bta,
                        float* __restrict__ out,
                        __nv_bfloat16* __restrict__ ohi,
                        __nv_bfloat16* __restrict__ olo)
{
    const int warp = threadIdx.x >> 5;
    const int lane = threadIdx.x & 31;
    const int row  = blockIdx.x * 8 + warp;
    const size_t base = (size_t)row * DMODEL;

    float4 v[4];
    float sum = 0.f;
#pragma unroll
    for (int it = 0; it < 4; it++) {
        int c = lane * 4 + it * 128;
        float4 a = *(const float4*)(y + base + c);
        float4 bb = *(const float4*)(res + base + c);
        v[it].x = a.x + bb.x; v[it].y = a.y + bb.y;
        v[it].z = a.z + bb.z; v[it].w = a.w + bb.w;
        sum += v[it].x + v[it].y + v[it].z + v[it].w;
    }
#pragma unroll
    for (int off = 16; off; off >>= 1)
        sum += __shfl_xor_sync(0xffffffffu, sum, off);
    float mean = sum * (1.0f / 512.0f);

    float var = 0.f;
#pragma unroll
    for (int it = 0; it < 4; it++) {
        v[it].x -= mean; v[it].y -= mean; v[it].z -= mean; v[it].w -= mean;
        var += v[it].x * v[it].x + v[it].y * v[it].y
             + v[it].z * v[it].z + v[it].w * v[it].w;
    }
#pragma unroll
    for (int off = 16; off; off >>= 1)
        var += __shfl_xor_sync(0xffffffffu, var, off);
    float inv = rsqrtf(var * (1.0f / 512.0f) + LN_EPS);

#pragma unroll
    for (int it = 0; it < 4; it++) {
        int c = lane * 4 + it * 128;
        float4 gg = *(const float4*)(g + c);
        float4 bb = *(const float4*)(bta + c);
        float4 o;
        o.x = v[it].x * inv * gg.x + bb.x;
        o.y = v[it].y * inv * gg.y + bb.y;
        o.z = v[it].z * inv * gg.z + bb.z;
        o.w = v[it].w * inv * gg.w + bb.w;
        *(float4*)(out + base + c) = o;
        if (ohi) {
            unsigned short h0, h1, h2, h3, l0, l1, l2, l3;
            split1(o.x, h0, l0); split1(o.y, h1, l1);
            split1(o.z, h2, l2); split1(o.w, h3, l3);
            uint2 hv, lv;
            hv.x = pack2(h0, h1); hv.y = pack2(h2, h3);
            lv.x = pack2(l0, l1); lv.y = pack2(l2, l3);
            *(uint2*)(ohi + base + c) = hv;
            *(uint2*)(olo + base + c) = lv;
        }
    }
}

// ---------------------------------------------------------------------------
// launch
// ---------------------------------------------------------------------------
extern "C" void kernel_launch(void* const* d_in, const int* in_sizes, int n_in,
                              void* d_out, int out_size)
{
    const float* x     = (const float*)d_in[0];
    const float* mask  = (const float*)d_in[1];
    const float* Wq    = (const float*)d_in[2];
    const float* bq    = (const float*)d_in[3];
    const float* Wk    = (const float*)d_in[4];
    const float* bk    = (const float*)d_in[5];
    const float* Wv    = (const float*)d_in[6];
    const float* bv    = (const float*)d_in[7];
    const float* Wo    = (const float*)d_in[8];
    const float* bo    = (const float*)d_in[9];
    const float* ln1g  = (const float*)d_in[10];
    const float* ln1b  = (const float*)d_in[11];
    const float* W1    = (const float*)d_in[12];
    const float* b1    = (const float*)d_in[13];
    const float* W2    = (const float*)d_in[14];
    const float* b2    = (const float*)d_in[15];
    const float* ln2g  = (const float*)d_in[16];
    const float* ln2b  = (const float*)d_in[17];
    float* out = (float*)d_out;

    float *t0, *aln;
    cudaGetSymbolAddress((void**)&t0,  g_t0);
    cudaGetSymbolAddress((void**)&aln, g_attnln);

    __nv_bfloat16 *xhi, *xlo, *qhi, *qlo, *khi, *klo, *vhi, *vlo;
    __nv_bfloat16 *chi, *clo, *ahi, *alo, *fhi, *flo;
    cudaGetSymbolAddress((void**)&xhi, g_xhi);
    cudaGetSymbolAddress((void**)&xlo, g_xlo);
    cudaGetSymbolAddress((void**)&qhi, g_qhi);
    cudaGetSymbolAddress((void**)&qlo, g_qlo);
    cudaGetSymbolAddress((void**)&khi, g_khi);
    cudaGetSymbolAddress((void**)&klo, g_klo);
    cudaGetSymbolAddress((void**)&vhi, g_vhi);
    cudaGetSymbolAddress((void**)&vlo, g_vlo);
    cudaGetSymbolAddress((void**)&chi, g_chi);
    cudaGetSymbolAddress((void**)&clo, g_clo);
    cudaGetSymbolAddress((void**)&ahi, g_ahi);
    cudaGetSymbolAddress((void**)&alo, g_alo);
    cudaGetSymbolAddress((void**)&fhi, g_fhi);
    cudaGetSymbolAddress((void**)&flo, g_flo);

    __nv_bfloat16 *wqh, *wql, *wkh, *wkl, *wvh, *wvl, *woh, *wol, *w1h, *w1l, *w2h, *w2l;
    cudaGetSymbolAddress((void**)&wqh, g_wqhi);
    cudaGetSymbolAddress((void**)&wql, g_wqlo);
    cudaGetSymbolAddress((void**)&wkh, g_wkhi);
    cudaGetSymbolAddress((void**)&wkl, g_wklo);
    cudaGetSymbolAddress((void**)&wvh, g_wvhi);
    cudaGetSymbolAddress((void**)&wvl, g_wvlo);
    cudaGetSymbolAddress((void**)&woh, g_wohi);
    cudaGetSymbolAddress((void**)&wol, g_wolo);
    cudaGetSymbolAddress((void**)&w1h, g_w1hi);
    cudaGetSymbolAddress((void**)&w1l, g_w1lo);
    cudaGetSymbolAddress((void**)&w2h, g_w2hi);
    cudaGetSymbolAddress((void**)&w2l, g_w2lo);

    cudaFuncSetAttribute(attn_mma,
                         cudaFuncAttributeMaxDynamicSharedMemorySize, AT_SMEM);
    cudaFuncSetAttribute(gemm_mma,
                         cudaFuncAttributeMaxDynamicSharedMemorySize, GM_SMEM_BYTES);

    dim3 tb(32, 8);

    // weight transpose + split
    tsplit_kernel<<<dim3(DMODEL / 32, DMODEL / 32), tb>>>(Wq, wqh, wql, DMODEL, DMODEL);
    tsplit_kernel<<<dim3(DMODEL / 32, DMODEL / 32), tb>>>(Wk, wkh, wkl, DMODEL, DMODEL);
    tsplit_kernel<<<dim3(DMODEL / 32, DMODEL / 32), tb>>>(Wv, wvh, wvl, DMODEL, DMODEL);
    tsplit_kernel<<<dim3(DMODEL / 32, DMODEL / 32), tb>>>(Wo, woh, wol, DMODEL, DMODEL);
    tsplit_kernel<<<dim3(DFF / 32, DMODEL / 32), tb>>>(W1, w1h, w1l, DMODEL, DFF);
    tsplit_kernel<<<dim3(DMODEL / 32, DFF / 32), tb>>>(W2, w2h, w2l, DFF, DMODEL);

    // split input x
    {
        int n4 = MTOK * DMODEL / 4;
        split_kernel<<<(n4 + 255) / 256, 256>>>(x, xhi, xlo, n4);
    }

    // QKV projections: one z=3 batched launch
    {
        GPtrs pq = {wqh, wql, bq, nullptr, qhi, qlo};
        GPtrs pk = {wkh, wkl, bk, nullptr, khi, klo};
        GPtrs pv = {wvh, wvl, bv, nullptr, vhi, vlo};
        dim3 grid(DMODEL / 64, MTOK / 128, 3);
        gemm_mma<<<grid, 256, GM_SMEM_BYTES>>>(xhi, xlo, pq, pk, pv,
                                               MTOK, DMODEL, DMODEL, 0);
    }

    // flash attention -> ctx bf16 hi/lo
    {
        dim3 grid(SEQ / 128, NHEADS, BATCH);
        attn_mma<<<grid, 256, AT_SMEM>>>(qhi, qlo, khi, klo, vhi, vlo,
                                         mask, chi, clo);
    }

    // output projection + residual LN
    {
        GPtrs po = {woh, wol, bo, t0, nullptr, nullptr};
        dim3 grid(DMODEL / 64, MTOK / 128, 1);
        gemm_mma<<<grid, 256, GM_SMEM_BYTES>>>(chi, clo, po, po, po,
                                               MTOK, DMODEL, DMODEL, 0);
        ln_residual_kernel<<<MTOK / 8, 256>>>(t0, x, ln1g, ln1b, aln, ahi, alo);
    }

    // FFN
    {
        GPtrs p1 = {w1h, w1l, b1, nullptr, fhi, flo};
        dim3 grid1(DFF / 64, MTOK / 128, 1);
        gemm_mma<<<grid1, 256, GM_SMEM_BYTES>>>(ahi, alo, p1, p1, p1,
                                                MTOK, DFF, DMODEL, 1);
        GPtrs p2 = {w2h, w2l, b2, t0, nullptr, nullptr};
        dim3 grid2(DMODEL / 64, MTOK / 128, 1);
        gemm_mma<<<grid2, 256, GM_SMEM_BYTES>>>(fhi, flo, p2, p2, p2,
                                                MTOK, DMODEL, DFF, 0);
        ln_residual_kernel<<<MTOK / 8, 256>>>(t0, aln, ln2g, ln2b, out,
                                              nullptr, nullptr);
    }
}